// round 1
// baseline (speedup 1.0000x reference)
#include <cuda_runtime.h>
#include <math.h>

// Problem constants
#define Bb_  2
#define Ss_  2048
#define MEM_ 64
#define Dd_  1024
#define Hh_  16
#define FF_  4096
#define HD_  64
#define NT_  (Bb_ * Ss_)   // 4096 tokens

// -------------------- scratch (device globals; no runtime alloc) --------------------
__device__ float g_x   [(size_t)NT_ * Dd_];     // LN output / generic activation
__device__ float g_qkv [(size_t)NT_ * 3 * Dd_]; // qkv (also reused for qc)
__device__ float g_sa  [(size_t)NT_ * Dd_];     // self-attn out (reused for cross out)
__device__ float g_tgt [(size_t)NT_ * Dd_];     // running residual stream
__device__ float g_kc  [(size_t)Bb_ * MEM_ * Dd_];
__device__ float g_vc  [(size_t)Bb_ * MEM_ * Dd_];
__device__ float g_ffn [(size_t)NT_ * FF_];     // FFN hidden

// -------------------- LayerNorm: one block (256 thr) per 1024-wide row --------------------
__global__ void layernorm_kernel(const float* __restrict__ x,
                                 const float* __restrict__ g,
                                 const float* __restrict__ be,
                                 float* __restrict__ y)
{
    int row = blockIdx.x;
    int tid = threadIdx.x;                 // 256 threads, 4 elems each
    const float* xr = x + (size_t)row * Dd_;
    float4 v = *(const float4*)(xr + tid * 4);

    __shared__ float red[8];
    __shared__ float s_mu, s_inv;

    float s = v.x + v.y + v.z + v.w;
    #pragma unroll
    for (int o = 16; o > 0; o >>= 1) s += __shfl_xor_sync(0xffffffffu, s, o);
    if ((tid & 31) == 0) red[tid >> 5] = s;
    __syncthreads();
    if (tid == 0) {
        float t = 0.f;
        #pragma unroll
        for (int i = 0; i < 8; i++) t += red[i];
        s_mu = t * (1.0f / Dd_);
    }
    __syncthreads();
    float mu = s_mu;
    float dx = v.x - mu, dy = v.y - mu, dz = v.z - mu, dw = v.w - mu;
    float q = dx*dx + dy*dy + dz*dz + dw*dw;
    #pragma unroll
    for (int o = 16; o > 0; o >>= 1) q += __shfl_xor_sync(0xffffffffu, q, o);
    if ((tid & 31) == 0) red[tid >> 5] = q;
    __syncthreads();
    if (tid == 0) {
        float t = 0.f;
        #pragma unroll
        for (int i = 0; i < 8; i++) t += red[i];
        s_inv = rsqrtf(t * (1.0f / Dd_) + 1e-5f);
    }
    __syncthreads();
    float inv = s_inv;
    int c = tid * 4;
    float* yr = y + (size_t)row * Dd_;
    yr[c + 0] = dx * inv * g[c + 0] + be[c + 0];
    yr[c + 1] = dy * inv * g[c + 1] + be[c + 1];
    yr[c + 2] = dz * inv * g[c + 2] + be[c + 2];
    yr[c + 3] = dw * inv * g[c + 3] + be[c + 3];
}

// -------------------- Tiled SGEMM: C = A(MxK) @ B(KxN) + bias [+res] [gelu] --------------------
// BM=BN=128, BK=16, 256 threads, 8x8 per thread. All dims multiples of tile sizes here.
__global__ __launch_bounds__(256)
void gemm_kernel(const float* __restrict__ A, const float* __restrict__ Bm,
                 const float* __restrict__ bias, const float* __restrict__ res,
                 float* __restrict__ C, int Mr, int Nc, int Kd, int dogelu)
{
    __shared__ float As[16][128];
    __shared__ float Bs[16][128];

    int bx = blockIdx.x;           // N tile
    int by = blockIdx.y;           // M tile
    int tid = threadIdx.x;
    int tx = tid & 15;             // 0..15
    int ty = tid >> 4;             // 0..15

    float acc[8][8];
    #pragma unroll
    for (int i = 0; i < 8; i++)
        #pragma unroll
        for (int j = 0; j < 8; j++) acc[i][j] = 0.f;

    int arow = tid >> 2;           // 0..63
    int acol = (tid & 3) * 4;      // 0,4,8,12
    int brow = tid >> 5;           // 0..7
    int bcol = (tid & 31) * 4;     // 0..124

    const float* Ab = A + (size_t)(by * 128) * Kd;
    const float* Bbp = Bm + bx * 128;

    for (int k0 = 0; k0 < Kd; k0 += 16) {
        #pragma unroll
        for (int r = 0; r < 2; r++) {
            float4 a4 = *(const float4*)(Ab + (size_t)(arow + r * 64) * Kd + k0 + acol);
            As[acol + 0][arow + r * 64] = a4.x;
            As[acol + 1][arow + r * 64] = a4.y;
            As[acol + 2][arow + r * 64] = a4.z;
            As[acol + 3][arow + r * 64] = a4.w;
        }
        #pragma unroll
        for (int r = 0; r < 2; r++) {
            float4 b4 = *(const float4*)(Bbp + (size_t)(k0 + brow + r * 8) * Nc + bcol);
            *(float4*)&Bs[brow + r * 8][bcol] = b4;
        }
        __syncthreads();
        #pragma unroll
        for (int kk = 0; kk < 16; kk++) {
            float ra[8], rb[8];
            #pragma unroll
            for (int i = 0; i < 8; i++) ra[i] = As[kk][ty * 8 + i];
            #pragma unroll
            for (int j = 0; j < 8; j++) rb[j] = Bs[kk][tx * 8 + j];
            #pragma unroll
            for (int i = 0; i < 8; i++)
                #pragma unroll
                for (int j = 0; j < 8; j++)
                    acc[i][j] = fmaf(ra[i], rb[j], acc[i][j]);
        }
        __syncthreads();
    }

    #pragma unroll
    for (int i = 0; i < 8; i++) {
        int row = by * 128 + ty * 8 + i;
        #pragma unroll
        for (int j = 0; j < 8; j++) {
            int col = bx * 128 + tx * 8 + j;
            float c = acc[i][j] + bias[col];
            if (res) c += res[(size_t)row * Nc + col];
            if (dogelu) c = 0.5f * c * (1.0f + erff(c * 0.7071067811865475f));
            C[(size_t)row * Nc + col] = c;
        }
    }
}

// -------------------- RoPE on q,k halves of qkv (interleaved even/odd pairs) --------------------
__global__ void rope_kernel(float* __restrict__ qkv,
                            const float* __restrict__ rc,
                            const float* __restrict__ rs)
{
    int idx = blockIdx.x * blockDim.x + threadIdx.x;
    int total = 2 * NT_ * Hh_ * (HD_ / 2);
    if (idx >= total) return;
    int t = idx & 1;          // 0 = q, 1 = k
    int r = idx >> 1;
    int pair = r & 31;  r >>= 5;
    int h = r & 15;     r >>= 4;
    int s = r % Ss_;
    int b = r / Ss_;
    float* base = qkv + ((size_t)(b * Ss_ + s)) * (3 * Dd_) + t * Dd_ + h * HD_ + pair * 2;
    float c  = rc[s * 32 + pair];
    float sn = rs[s * 32 + pair];
    float e = base[0], o = base[1];
    base[0] = e * c - o * sn;
    base[1] = e * sn + o * c;
}

// -------------------- Causal self-attention: one block (128 thr) per (q, b*h) --------------------
__global__ __launch_bounds__(128)
void self_attn_kernel(const float* __restrict__ qkv, float* __restrict__ out)
{
    int qidx = blockIdx.x;
    int bh   = blockIdx.y;
    int b = bh / Hh_, h = bh % Hh_;
    int tid = threadIdx.x;

    __shared__ float sq[HD_];
    __shared__ float p[128];
    __shared__ float acc[HD_];
    __shared__ float red[4];
    __shared__ float s_m, s_l, s_factor;

    const float* qrow = qkv + ((size_t)(b * Ss_ + qidx)) * (3 * Dd_) + h * HD_;
    if (tid < HD_) { sq[tid] = qrow[tid]; acc[tid] = 0.f; }
    if (tid == 0) { s_m = -1e30f; s_l = 0.f; }
    __syncthreads();

    int nkeys = qidx + 1;
    const float scale = 0.125f;  // 1/sqrt(64)

    for (int k0 = 0; k0 < nkeys; k0 += 128) {
        int j = k0 + tid;
        float score = -1e30f;
        if (j < nkeys) {
            const float* krow = qkv + ((size_t)(b * Ss_ + j)) * (3 * Dd_) + Dd_ + h * HD_;
            float s = 0.f;
            #pragma unroll
            for (int d = 0; d < HD_; d += 4) {
                float4 k4 = *(const float4*)(krow + d);
                s = fmaf(sq[d + 0], k4.x, s);
                s = fmaf(sq[d + 1], k4.y, s);
                s = fmaf(sq[d + 2], k4.z, s);
                s = fmaf(sq[d + 3], k4.w, s);
            }
            score = s * scale;
        }
        // chunk max
        float m = score;
        #pragma unroll
        for (int o = 16; o > 0; o >>= 1) m = fmaxf(m, __shfl_xor_sync(0xffffffffu, m, o));
        if ((tid & 31) == 0) red[tid >> 5] = m;
        __syncthreads();
        if (tid == 0) {
            float cm = fmaxf(fmaxf(red[0], red[1]), fmaxf(red[2], red[3]));
            float nm = fmaxf(s_m, cm);
            s_factor = expf(s_m - nm);
            s_m = nm;
        }
        __syncthreads();
        float pv = (j < nkeys) ? expf(score - s_m) : 0.f;
        p[tid] = pv;
        float su = pv;
        #pragma unroll
        for (int o = 16; o > 0; o >>= 1) su += __shfl_xor_sync(0xffffffffu, su, o);
        if ((tid & 31) == 0) red[tid >> 5] = su;
        __syncthreads();
        if (tid == 0) s_l = s_l * s_factor + (red[0] + red[1] + red[2] + red[3]);

        int cl = nkeys - k0; if (cl > 128) cl = 128;
        if (tid < HD_) {
            float a = acc[tid] * s_factor;
            const float* vbase = qkv + ((size_t)(b * Ss_ + k0)) * (3 * Dd_) + 2 * Dd_ + h * HD_ + tid;
            int jj = 0;
            for (; jj + 4 <= cl; jj += 4) {
                a = fmaf(p[jj + 0], vbase[(size_t)(jj + 0) * (3 * Dd_)], a);
                a = fmaf(p[jj + 1], vbase[(size_t)(jj + 1) * (3 * Dd_)], a);
                a = fmaf(p[jj + 2], vbase[(size_t)(jj + 2) * (3 * Dd_)], a);
                a = fmaf(p[jj + 3], vbase[(size_t)(jj + 3) * (3 * Dd_)], a);
            }
            for (; jj < cl; jj++) a = fmaf(p[jj], vbase[(size_t)jj * (3 * Dd_)], a);
            acc[tid] = a;
        }
        __syncthreads();
    }

    if (tid < HD_)
        out[((size_t)(b * Ss_ + qidx)) * Dd_ + h * HD_ + tid] = acc[tid] / s_l;
}

// -------------------- Cross-attention: 64 keys, one block (64 thr) per (q, b*h) --------------------
__global__ __launch_bounds__(64)
void cross_attn_kernel(const float* __restrict__ qc, const float* __restrict__ kc,
                       const float* __restrict__ vc, float* __restrict__ out)
{
    int qidx = blockIdx.x;
    int bh   = blockIdx.y;
    int b = bh / Hh_, h = bh % Hh_;
    int tid = threadIdx.x;

    __shared__ float sq[HD_];
    __shared__ float p[MEM_];
    __shared__ float red[2];

    const float* qrow = qc + ((size_t)(b * Ss_ + qidx)) * Dd_ + h * HD_;
    sq[tid] = qrow[tid];
    __syncthreads();

    const float* krow = kc + ((size_t)(b * MEM_ + tid)) * Dd_ + h * HD_;
    float s = 0.f;
    #pragma unroll
    for (int d = 0; d < HD_; d += 4) {
        float4 k4 = *(const float4*)(krow + d);
        s = fmaf(sq[d + 0], k4.x, s);
        s = fmaf(sq[d + 1], k4.y, s);
        s = fmaf(sq[d + 2], k4.z, s);
        s = fmaf(sq[d + 3], k4.w, s);
    }
    s *= 0.125f;

    float m = s;
    #pragma unroll
    for (int o = 16; o > 0; o >>= 1) m = fmaxf(m, __shfl_xor_sync(0xffffffffu, m, o));
    if ((tid & 31) == 0) red[tid >> 5] = m;
    __syncthreads();
    float gm = fmaxf(red[0], red[1]);
    float pv = expf(s - gm);
    p[tid] = pv;
    float su = pv;
    #pragma unroll
    for (int o = 16; o > 0; o >>= 1) su += __shfl_xor_sync(0xffffffffu, su, o);
    __syncthreads();                 // done reading red (max) before overwrite
    if ((tid & 31) == 0) red[tid >> 5] = su;
    __syncthreads();
    float gl = red[0] + red[1];

    const float* vbase = vc + ((size_t)(b * MEM_)) * Dd_ + h * HD_ + tid;
    float a = 0.f;
    #pragma unroll 4
    for (int j = 0; j < MEM_; j++)
        a = fmaf(p[j], vbase[(size_t)j * Dd_], a);

    out[((size_t)(b * Ss_ + qidx)) * Dd_ + h * HD_ + tid] = a / gl;
}

// -------------------- launch --------------------
extern "C" void kernel_launch(void* const* d_in, const int* in_sizes, int n_in,
                              void* d_out, int out_size)
{
    const float* tgt      = (const float*)d_in[0];
    const float* memory   = (const float*)d_in[1];
    const float* rope_cos = (const float*)d_in[2];
    const float* rope_sin = (const float*)d_in[3];
    const float* W_qkv    = (const float*)d_in[4];
    const float* b_qkv    = (const float*)d_in[5];
    const float* W_o      = (const float*)d_in[6];
    const float* b_o      = (const float*)d_in[7];
    const float* Wq_c     = (const float*)d_in[8];
    const float* bq_c     = (const float*)d_in[9];
    const float* Wk_c     = (const float*)d_in[10];
    const float* bk_c     = (const float*)d_in[11];
    const float* Wv_c     = (const float*)d_in[12];
    const float* bv_c     = (const float*)d_in[13];
    const float* W_co     = (const float*)d_in[14];
    const float* b_co     = (const float*)d_in[15];
    const float* W1       = (const float*)d_in[16];
    const float* b1       = (const float*)d_in[17];
    const float* W2       = (const float*)d_in[18];
    const float* b2       = (const float*)d_in[19];
    const float* g1       = (const float*)d_in[20];
    const float* be1      = (const float*)d_in[21];
    const float* g2       = (const float*)d_in[22];
    const float* be2      = (const float*)d_in[23];
    const float* g3       = (const float*)d_in[24];
    const float* be3      = (const float*)d_in[25];
    float* out = (float*)d_out;

    float *x, *qkv, *sa, *tgtb, *kc, *vc, *ffn;
    cudaGetSymbolAddress((void**)&x,    g_x);
    cudaGetSymbolAddress((void**)&qkv,  g_qkv);
    cudaGetSymbolAddress((void**)&sa,   g_sa);
    cudaGetSymbolAddress((void**)&tgtb, g_tgt);
    cudaGetSymbolAddress((void**)&kc,   g_kc);
    cudaGetSymbolAddress((void**)&vc,   g_vc);
    cudaGetSymbolAddress((void**)&ffn,  g_ffn);

    // 1) x = LN1(tgt)
    layernorm_kernel<<<NT_, 256>>>(tgt, g1, be1, x);
    // 2) qkv = x @ W_qkv + b
    gemm_kernel<<<dim3(3 * Dd_ / 128, NT_ / 128), 256>>>(x, W_qkv, b_qkv, nullptr, qkv, NT_, 3 * Dd_, Dd_, 0);
    // 3) RoPE on q,k
    {
        int total = 2 * NT_ * Hh_ * (HD_ / 2);
        rope_kernel<<<(total + 255) / 256, 256>>>(qkv, rope_cos, rope_sin);
    }
    // 4) causal self-attention -> sa (b,s,D layout)
    self_attn_kernel<<<dim3(Ss_, Bb_ * Hh_), 128>>>(qkv, sa);
    // 5) tgtb = tgt + sa @ W_o + b_o
    gemm_kernel<<<dim3(Dd_ / 128, NT_ / 128), 256>>>(sa, W_o, b_o, tgt, tgtb, NT_, Dd_, Dd_, 0);
    // 6) x = LN2(tgtb)
    layernorm_kernel<<<NT_, 256>>>(tgtb, g2, be2, x);
    // 7) qc = x @ Wq_c (reuse qkv buffer)
    gemm_kernel<<<dim3(Dd_ / 128, NT_ / 128), 256>>>(x, Wq_c, bq_c, nullptr, qkv, NT_, Dd_, Dd_, 0);
    // 8) kc/vc = memory @ Wk_c / Wv_c   (B*MEM = 128 rows)
    gemm_kernel<<<dim3(Dd_ / 128, 1), 256>>>(memory, Wk_c, bk_c, nullptr, kc, Bb_ * MEM_, Dd_, Dd_, 0);
    gemm_kernel<<<dim3(Dd_ / 128, 1), 256>>>(memory, Wv_c, bv_c, nullptr, vc, Bb_ * MEM_, Dd_, Dd_, 0);
    // 9) cross-attention -> sa (reuse)
    cross_attn_kernel<<<dim3(Ss_, Bb_ * Hh_), 64>>>(qkv, kc, vc, sa);
    // 10) tgtb = tgtb + sa @ W_co + b_co (in-place residual, 1:1 element ownership)
    gemm_kernel<<<dim3(Dd_ / 128, NT_ / 128), 256>>>(sa, W_co, b_co, tgtb, tgtb, NT_, Dd_, Dd_, 0);
    // 11) x = LN3(tgtb)
    layernorm_kernel<<<NT_, 256>>>(tgtb, g3, be3, x);
    // 12) ffn = gelu(x @ W1 + b1)
    gemm_kernel<<<dim3(FF_ / 128, NT_ / 128), 256>>>(x, W1, b1, nullptr, ffn, NT_, FF_, Dd_, 1);
    // 13) out = tgtb + ffn @ W2 + b2
    gemm_kernel<<<dim3(Dd_ / 128, NT_ / 128), 256>>>(ffn, W2, b2, tgtb, out, NT_, Dd_, FF_, 0);
}

// round 2
// speedup vs baseline: 1.8923x; 1.8923x over previous
#include <cuda_runtime.h>
#include <math.h>

// Problem constants
#define Bb_  2
#define Ss_  2048
#define MEM_ 64
#define Dd_  1024
#define Hh_  16
#define FF_  4096
#define HD_  64
#define NT_  (Bb_ * Ss_)   // 4096 tokens

// -------------------- scratch (device globals; no runtime alloc) --------------------
__device__ float g_x   [(size_t)NT_ * Dd_];
__device__ float g_qkv [(size_t)NT_ * 3 * Dd_];
__device__ float g_sa  [(size_t)NT_ * Dd_];
__device__ float g_tgt [(size_t)NT_ * Dd_];
__device__ float g_kc  [(size_t)Bb_ * MEM_ * Dd_];
__device__ float g_vc  [(size_t)Bb_ * MEM_ * Dd_];
__device__ float g_ffn [(size_t)NT_ * FF_];

// -------------------- LayerNorm --------------------
__global__ void layernorm_kernel(const float* __restrict__ x,
                                 const float* __restrict__ g,
                                 const float* __restrict__ be,
                                 float* __restrict__ y)
{
    int row = blockIdx.x;
    int tid = threadIdx.x;
    const float* xr = x + (size_t)row * Dd_;
    float4 v = *(const float4*)(xr + tid * 4);

    __shared__ float red[8];
    __shared__ float s_mu, s_inv;

    float s = v.x + v.y + v.z + v.w;
    #pragma unroll
    for (int o = 16; o > 0; o >>= 1) s += __shfl_xor_sync(0xffffffffu, s, o);
    if ((tid & 31) == 0) red[tid >> 5] = s;
    __syncthreads();
    if (tid == 0) {
        float t = 0.f;
        #pragma unroll
        for (int i = 0; i < 8; i++) t += red[i];
        s_mu = t * (1.0f / Dd_);
    }
    __syncthreads();
    float mu = s_mu;
    float dx = v.x - mu, dy = v.y - mu, dz = v.z - mu, dw = v.w - mu;
    float q = dx*dx + dy*dy + dz*dz + dw*dw;
    #pragma unroll
    for (int o = 16; o > 0; o >>= 1) q += __shfl_xor_sync(0xffffffffu, q, o);
    if ((tid & 31) == 0) red[tid >> 5] = q;
    __syncthreads();
    if (tid == 0) {
        float t = 0.f;
        #pragma unroll
        for (int i = 0; i < 8; i++) t += red[i];
        s_inv = rsqrtf(t * (1.0f / Dd_) + 1e-5f);
    }
    __syncthreads();
    float inv = s_inv;
    int c = tid * 4;
    float* yr = y + (size_t)row * Dd_;
    yr[c + 0] = dx * inv * g[c + 0] + be[c + 0];
    yr[c + 1] = dy * inv * g[c + 1] + be[c + 1];
    yr[c + 2] = dz * inv * g[c + 2] + be[c + 2];
    yr[c + 3] = dw * inv * g[c + 3] + be[c + 3];
}

// -------------------- Tiled SGEMM --------------------
__global__ __launch_bounds__(256)
void gemm_kernel(const float* __restrict__ A, const float* __restrict__ Bm,
                 const float* __restrict__ bias, const float* __restrict__ res,
                 float* __restrict__ C, int Mr, int Nc, int Kd, int dogelu)
{
    __shared__ float As[16][128];
    __shared__ float Bs[16][128];

    int bx = blockIdx.x;
    int by = blockIdx.y;
    int tid = threadIdx.x;
    int tx = tid & 15;
    int ty = tid >> 4;

    float acc[8][8];
    #pragma unroll
    for (int i = 0; i < 8; i++)
        #pragma unroll
        for (int j = 0; j < 8; j++) acc[i][j] = 0.f;

    int arow = tid >> 2;
    int acol = (tid & 3) * 4;
    int brow = tid >> 5;
    int bcol = (tid & 31) * 4;

    const float* Ab = A + (size_t)(by * 128) * Kd;
    const float* Bbp = Bm + bx * 128;

    for (int k0 = 0; k0 < Kd; k0 += 16) {
        #pragma unroll
        for (int r = 0; r < 2; r++) {
            float4 a4 = *(const float4*)(Ab + (size_t)(arow + r * 64) * Kd + k0 + acol);
            As[acol + 0][arow + r * 64] = a4.x;
            As[acol + 1][arow + r * 64] = a4.y;
            As[acol + 2][arow + r * 64] = a4.z;
            As[acol + 3][arow + r * 64] = a4.w;
        }
        #pragma unroll
        for (int r = 0; r < 2; r++) {
            float4 b4 = *(const float4*)(Bbp + (size_t)(k0 + brow + r * 8) * Nc + bcol);
            *(float4*)&Bs[brow + r * 8][bcol] = b4;
        }
        __syncthreads();
        #pragma unroll
        for (int kk = 0; kk < 16; kk++) {
            float ra[8], rb[8];
            #pragma unroll
            for (int i = 0; i < 8; i++) ra[i] = As[kk][ty * 8 + i];
            #pragma unroll
            for (int j = 0; j < 8; j++) rb[j] = Bs[kk][tx * 8 + j];
            #pragma unroll
            for (int i = 0; i < 8; i++)
                #pragma unroll
                for (int j = 0; j < 8; j++)
                    acc[i][j] = fmaf(ra[i], rb[j], acc[i][j]);
        }
        __syncthreads();
    }

    #pragma unroll
    for (int i = 0; i < 8; i++) {
        int row = by * 128 + ty * 8 + i;
        #pragma unroll
        for (int j = 0; j < 8; j++) {
            int col = bx * 128 + tx * 8 + j;
            float c = acc[i][j] + bias[col];
            if (res) c += res[(size_t)row * Nc + col];
            if (dogelu) c = 0.5f * c * (1.0f + erff(c * 0.7071067811865475f));
            C[(size_t)row * Nc + col] = c;
        }
    }
}

// -------------------- RoPE --------------------
__global__ void rope_kernel(float* __restrict__ qkv,
                            const float* __restrict__ rc,
                            const float* __restrict__ rs)
{
    int idx = blockIdx.x * blockDim.x + threadIdx.x;
    int total = 2 * NT_ * Hh_ * (HD_ / 2);
    if (idx >= total) return;
    int t = idx & 1;
    int r = idx >> 1;
    int pair = r & 31;  r >>= 5;
    int h = r & 15;     r >>= 4;
    int s = r % Ss_;
    int b = r / Ss_;
    float* base = qkv + ((size_t)(b * Ss_ + s)) * (3 * Dd_) + t * Dd_ + h * HD_ + pair * 2;
    float c  = rc[s * 32 + pair];
    float sn = rs[s * 32 + pair];
    float e = base[0], o = base[1];
    base[0] = e * c - o * sn;
    base[1] = e * sn + o * c;
}

// -------------------- Tiled causal flash attention --------------------
// One block per (q-tile of 64, b*h). 256 threads, 4x4 register tile each.
// smem: Qt[64][65] (Q transposed), Ks[64][65] (K natural, aliased by Ps),
//       Vs[64][65]. 49,920 bytes dynamic.
#define FA_PAD 65
__global__ __launch_bounds__(256)
void flash_attn_kernel(const float* __restrict__ qkv, float* __restrict__ out)
{
    extern __shared__ float smf[];
    float* Qt = smf;                       // Qt[d*65 + i] = Q[i][d]
    float* Ks = smf + 64 * FA_PAD;         // Ks[j*65 + d] = K[j][d]  (alias: Ps)
    float* Vs = smf + 2 * 64 * FA_PAD;     // Vs[j*65 + d] = V[j][d]
    float* Ps = Ks;                        // Ps[i*65 + j] = P[i][j]

    const int qb = (int)gridDim.x - 1 - (int)blockIdx.x;  // heavy blocks first
    const int q0 = qb * 64;
    const int bh = blockIdx.y;
    const int b = bh >> 4, h = bh & 15;
    const int tid = threadIdx.x;
    const int tx = tid & 15, ty = tid >> 4;
    const int r0 = ty * 4, c0 = tx * 4;
    const size_t rs3 = 3 * Dd_;

    // load Q tile transposed (once)
    {
        const float* qbase = qkv + ((size_t)(b * Ss_ + q0)) * rs3 + h * HD_;
        #pragma unroll
        for (int cch = 0; cch < 4; cch++) {
            int L = cch * 256 + tid;
            int r = L >> 4;
            int dq = (L & 15) * 4;
            float4 v = *(const float4*)(qbase + (size_t)r * rs3 + dq);
            Qt[(dq + 0) * FA_PAD + r] = v.x;
            Qt[(dq + 1) * FA_PAD + r] = v.y;
            Qt[(dq + 2) * FA_PAD + r] = v.z;
            Qt[(dq + 3) * FA_PAD + r] = v.w;
        }
    }

    float acc[4][4];
    float m_i[4], l_i[4];
    #pragma unroll
    for (int i = 0; i < 4; i++) {
        m_i[i] = -1e30f; l_i[i] = 0.f;
        #pragma unroll
        for (int j = 0; j < 4; j++) acc[i][j] = 0.f;
    }

    const float* kbase = qkv + ((size_t)(b * Ss_)) * rs3 + Dd_ + h * HD_;
    const float* vbase = qkv + ((size_t)(b * Ss_)) * rs3 + 2 * Dd_ + h * HD_;
    const int ntiles = qb + 1;

    for (int t = 0; t < ntiles; t++) {
        const int k0 = t * 64;
        __syncthreads();   // prior tile's P@V reads complete before overwriting Ks/Vs

        // load K,V tiles (natural layout, odd stride)
        #pragma unroll
        for (int cch = 0; cch < 4; cch++) {
            int L = cch * 256 + tid;
            int r = L >> 4;
            int dq = (L & 15) * 4;
            const float* kp = kbase + (size_t)(k0 + r) * rs3 + dq;
            float4 kv = *(const float4*)kp;
            Ks[r * FA_PAD + dq + 0] = kv.x;
            Ks[r * FA_PAD + dq + 1] = kv.y;
            Ks[r * FA_PAD + dq + 2] = kv.z;
            Ks[r * FA_PAD + dq + 3] = kv.w;
            const float* vp = vbase + (size_t)(k0 + r) * rs3 + dq;
            float4 vv = *(const float4*)vp;
            Vs[r * FA_PAD + dq + 0] = vv.x;
            Vs[r * FA_PAD + dq + 1] = vv.y;
            Vs[r * FA_PAD + dq + 2] = vv.z;
            Vs[r * FA_PAD + dq + 3] = vv.w;
        }
        __syncthreads();

        // S = Q @ K^T (64x64 tile)
        float s[4][4];
        #pragma unroll
        for (int i = 0; i < 4; i++)
            #pragma unroll
            for (int j = 0; j < 4; j++) s[i][j] = 0.f;

        #pragma unroll 8
        for (int d = 0; d < 64; d++) {
            float ra[4], rb[4];
            #pragma unroll
            for (int i = 0; i < 4; i++) ra[i] = Qt[d * FA_PAD + r0 + i];
            #pragma unroll
            for (int j = 0; j < 4; j++) rb[j] = Ks[(c0 + j) * FA_PAD + d];
            #pragma unroll
            for (int i = 0; i < 4; i++)
                #pragma unroll
                for (int j = 0; j < 4; j++)
                    s[i][j] = fmaf(ra[i], rb[j], s[i][j]);
        }

        // scale + causal mask (only the diagonal tile has masked entries)
        const bool diag = (t == ntiles - 1);
        #pragma unroll
        for (int i = 0; i < 4; i++)
            #pragma unroll
            for (int j = 0; j < 4; j++) {
                float v = s[i][j] * 0.125f;
                if (diag && (c0 + j > r0 + i)) v = -1e30f;
                s[i][j] = v;
            }

        // online softmax (row groups = 16 lanes, xor-shuffle reduce)
        #pragma unroll
        for (int i = 0; i < 4; i++) {
            float rm = fmaxf(fmaxf(s[i][0], s[i][1]), fmaxf(s[i][2], s[i][3]));
            #pragma unroll
            for (int o = 8; o >= 1; o >>= 1)
                rm = fmaxf(rm, __shfl_xor_sync(0xffffffffu, rm, o));
            float mn = fmaxf(m_i[i], rm);
            float fac = __expf(m_i[i] - mn);
            m_i[i] = mn;
            float rsum = 0.f;
            #pragma unroll
            for (int j = 0; j < 4; j++) {
                float p = __expf(s[i][j] - mn);
                s[i][j] = p;
                rsum += p;
            }
            #pragma unroll
            for (int o = 8; o >= 1; o >>= 1)
                rsum += __shfl_xor_sync(0xffffffffu, rsum, o);
            l_i[i] = l_i[i] * fac + rsum;
            #pragma unroll
            for (int j = 0; j < 4; j++) acc[i][j] *= fac;
        }

        __syncthreads();   // all Ks reads done before Ps (alias) is written
        #pragma unroll
        for (int i = 0; i < 4; i++)
            #pragma unroll
            for (int j = 0; j < 4; j++)
                Ps[(r0 + i) * FA_PAD + c0 + j] = s[i][j];
        __syncthreads();

        // O += P @ V
        #pragma unroll 8
        for (int jj = 0; jj < 64; jj++) {
            float ra[4], rb[4];
            #pragma unroll
            for (int i = 0; i < 4; i++) ra[i] = Ps[(r0 + i) * FA_PAD + jj];
            #pragma unroll
            for (int j = 0; j < 4; j++) rb[j] = Vs[jj * FA_PAD + c0 + j];
            #pragma unroll
            for (int i = 0; i < 4; i++)
                #pragma unroll
                for (int j = 0; j < 4; j++)
                    acc[i][j] = fmaf(ra[i], rb[j], acc[i][j]);
        }
    }

    // epilogue: normalize and store (b,s,D layout)
    #pragma unroll
    for (int i = 0; i < 4; i++) {
        float inv = 1.0f / l_i[i];
        float* orow = out + ((size_t)(b * Ss_ + q0 + r0 + i)) * Dd_ + h * HD_ + c0;
        float4 o4;
        o4.x = acc[i][0] * inv;
        o4.y = acc[i][1] * inv;
        o4.z = acc[i][2] * inv;
        o4.w = acc[i][3] * inv;
        *(float4*)orow = o4;
    }
}

// -------------------- Cross-attention (64 keys) --------------------
__global__ __launch_bounds__(64)
void cross_attn_kernel(const float* __restrict__ qc, const float* __restrict__ kc,
                       const float* __restrict__ vc, float* __restrict__ out)
{
    int qidx = blockIdx.x;
    int bh   = blockIdx.y;
    int b = bh / Hh_, h = bh % Hh_;
    int tid = threadIdx.x;

    __shared__ float sq[HD_];
    __shared__ float p[MEM_];
    __shared__ float red[2];

    const float* qrow = qc + ((size_t)(b * Ss_ + qidx)) * Dd_ + h * HD_;
    sq[tid] = qrow[tid];
    __syncthreads();

    const float* krow = kc + ((size_t)(b * MEM_ + tid)) * Dd_ + h * HD_;
    float s = 0.f;
    #pragma unroll
    for (int d = 0; d < HD_; d += 4) {
        float4 k4 = *(const float4*)(krow + d);
        s = fmaf(sq[d + 0], k4.x, s);
        s = fmaf(sq[d + 1], k4.y, s);
        s = fmaf(sq[d + 2], k4.z, s);
        s = fmaf(sq[d + 3], k4.w, s);
    }
    s *= 0.125f;

    float m = s;
    #pragma unroll
    for (int o = 16; o > 0; o >>= 1) m = fmaxf(m, __shfl_xor_sync(0xffffffffu, m, o));
    if ((tid & 31) == 0) red[tid >> 5] = m;
    __syncthreads();
    float gm = fmaxf(red[0], red[1]);
    float pv = expf(s - gm);
    p[tid] = pv;
    float su = pv;
    #pragma unroll
    for (int o = 16; o > 0; o >>= 1) su += __shfl_xor_sync(0xffffffffu, su, o);
    __syncthreads();
    if ((tid & 31) == 0) red[tid >> 5] = su;
    __syncthreads();
    float gl = red[0] + red[1];

    const float* vbase = vc + ((size_t)(b * MEM_)) * Dd_ + h * HD_ + tid;
    float a = 0.f;
    #pragma unroll 4
    for (int j = 0; j < MEM_; j++)
        a = fmaf(p[j], vbase[(size_t)j * Dd_], a);

    out[((size_t)(b * Ss_ + qidx)) * Dd_ + h * HD_ + tid] = a / gl;
}

// -------------------- launch --------------------
extern "C" void kernel_launch(void* const* d_in, const int* in_sizes, int n_in,
                              void* d_out, int out_size)
{
    const float* tgt      = (const float*)d_in[0];
    const float* memory   = (const float*)d_in[1];
    const float* rope_cos = (const float*)d_in[2];
    const float* rope_sin = (const float*)d_in[3];
    const float* W_qkv    = (const float*)d_in[4];
    const float* b_qkv    = (const float*)d_in[5];
    const float* W_o      = (const float*)d_in[6];
    const float* b_o      = (const float*)d_in[7];
    const float* Wq_c     = (const float*)d_in[8];
    const float* bq_c     = (const float*)d_in[9];
    const float* Wk_c     = (const float*)d_in[10];
    const float* bk_c     = (const float*)d_in[11];
    const float* Wv_c     = (const float*)d_in[12];
    const float* bv_c     = (const float*)d_in[13];
    const float* W_co     = (const float*)d_in[14];
    const float* b_co     = (const float*)d_in[15];
    const float* W1       = (const float*)d_in[16];
    const float* b1       = (const float*)d_in[17];
    const float* W2       = (const float*)d_in[18];
    const float* b2       = (const float*)d_in[19];
    const float* g1       = (const float*)d_in[20];
    const float* be1      = (const float*)d_in[21];
    const float* g2       = (const float*)d_in[22];
    const float* be2      = (const float*)d_in[23];
    const float* g3       = (const float*)d_in[24];
    const float* be3      = (const float*)d_in[25];
    float* out = (float*)d_out;

    float *x, *qkv, *sa, *tgtb, *kc, *vc, *ffn;
    cudaGetSymbolAddress((void**)&x,    g_x);
    cudaGetSymbolAddress((void**)&qkv,  g_qkv);
    cudaGetSymbolAddress((void**)&sa,   g_sa);
    cudaGetSymbolAddress((void**)&tgtb, g_tgt);
    cudaGetSymbolAddress((void**)&kc,   g_kc);
    cudaGetSymbolAddress((void**)&vc,   g_vc);
    cudaGetSymbolAddress((void**)&ffn,  g_ffn);

    const int fa_smem = 3 * 64 * FA_PAD * (int)sizeof(float);  // 49,920 B
    cudaFuncSetAttribute(flash_attn_kernel,
                         cudaFuncAttributeMaxDynamicSharedMemorySize, fa_smem);

    // 1) x = LN1(tgt)
    layernorm_kernel<<<NT_, 256>>>(tgt, g1, be1, x);
    // 2) qkv = x @ W_qkv + b
    gemm_kernel<<<dim3(3 * Dd_ / 128, NT_ / 128), 256>>>(x, W_qkv, b_qkv, nullptr, qkv, NT_, 3 * Dd_, Dd_, 0);
    // 3) RoPE on q,k
    {
        int total = 2 * NT_ * Hh_ * (HD_ / 2);
        rope_kernel<<<(total + 255) / 256, 256>>>(qkv, rope_cos, rope_sin);
    }
    // 4) causal self-attention (tiled flash) -> sa
    flash_attn_kernel<<<dim3(Ss_ / 64, Bb_ * Hh_), 256, fa_smem>>>(qkv, sa);
    // 5) tgtb = tgt + sa @ W_o + b_o
    gemm_kernel<<<dim3(Dd_ / 128, NT_ / 128), 256>>>(sa, W_o, b_o, tgt, tgtb, NT_, Dd_, Dd_, 0);
    // 6) x = LN2(tgtb)
    layernorm_kernel<<<NT_, 256>>>(tgtb, g2, be2, x);
    // 7) qc = x @ Wq_c (reuse qkv buffer)
    gemm_kernel<<<dim3(Dd_ / 128, NT_ / 128), 256>>>(x, Wq_c, bq_c, nullptr, qkv, NT_, Dd_, Dd_, 0);
    // 8) kc/vc = memory @ Wk_c / Wv_c
    gemm_kernel<<<dim3(Dd_ / 128, 1), 256>>>(memory, Wk_c, bk_c, nullptr, kc, Bb_ * MEM_, Dd_, Dd_, 0);
    gemm_kernel<<<dim3(Dd_ / 128, 1), 256>>>(memory, Wv_c, bv_c, nullptr, vc, Bb_ * MEM_, Dd_, Dd_, 0);
    // 9) cross-attention -> sa (reuse)
    cross_attn_kernel<<<dim3(Ss_, Bb_ * Hh_), 64>>>(qkv, kc, vc, sa);
    // 10) tgtb += sa @ W_co + b_co
    gemm_kernel<<<dim3(Dd_ / 128, NT_ / 128), 256>>>(sa, W_co, b_co, tgtb, tgtb, NT_, Dd_, Dd_, 0);
    // 11) x = LN3(tgtb)
    layernorm_kernel<<<NT_, 256>>>(tgtb, g3, be3, x);
    // 12) ffn = gelu(x @ W1 + b1)
    gemm_kernel<<<dim3(FF_ / 128, NT_ / 128), 256>>>(x, W1, b1, nullptr, ffn, NT_, FF_, Dd_, 1);
    // 13) out = tgtb + ffn @ W2 + b2
    gemm_kernel<<<dim3(Dd_ / 128, NT_ / 128), 256>>>(ffn, W2, b2, tgtb, out, NT_, Dd_, FF_, 0);
}

// round 4
// speedup vs baseline: 3.2776x; 1.7320x over previous
#include <cuda_runtime.h>
#include <cstdint>
#include <math.h>

// Problem constants
#define Bb_  2
#define Ss_  2048
#define MEM_ 64
#define Dd_  1024
#define Hh_  16
#define FF_  4096
#define HD_  64
#define NT_  (Bb_ * Ss_)   // 4096 tokens

// -------------------- scratch (device globals; no runtime alloc) --------------------
__device__ float g_x   [(size_t)NT_ * Dd_];
__device__ float g_qkv [(size_t)NT_ * 3 * Dd_];
__device__ float g_sa  [(size_t)NT_ * Dd_];
__device__ float g_tgt [(size_t)NT_ * Dd_];
__device__ float g_kc  [(size_t)Bb_ * MEM_ * Dd_];
__device__ float g_vc  [(size_t)Bb_ * MEM_ * Dd_];
__device__ float g_ffn [(size_t)NT_ * FF_];

// -------------------- helpers --------------------
__device__ __forceinline__ uint32_t smem_u32(const void* p) {
    uint32_t a;
    asm("{ .reg .u64 t; cvta.to.shared.u64 t, %1; cvt.u32.u64 %0, t; }" : "=r"(a) : "l"(p));
    return a;
}
__device__ __forceinline__ float ftf32(float x) {
    float y;
    asm("cvt.rna.tf32.f32 %0, %1;" : "=f"(y) : "f"(x));
    return y;
}
__device__ __forceinline__ void sts128(uint32_t addr, float4 v) {
    asm volatile("st.shared.v4.f32 [%0], {%1,%2,%3,%4};"
                 :: "r"(addr), "f"(v.x), "f"(v.y), "f"(v.z), "f"(v.w) : "memory");
}
__device__ __forceinline__ float2 lds64(uint32_t addr) {
    float2 v;
    asm volatile("ld.shared.v2.f32 {%0,%1}, [%2];" : "=f"(v.x), "=f"(v.y) : "r"(addr));
    return v;
}
#define SWZ(b) ((b) ^ (((b) >> 3) & 0x70))

__device__ __forceinline__ void mma_tf32(float* d, const uint32_t* a, uint32_t b0, uint32_t b1) {
    asm volatile(
        "mma.sync.aligned.m16n8k8.row.col.f32.tf32.tf32.f32 "
        "{%0,%1,%2,%3}, {%4,%5,%6,%7}, {%8,%9}, {%0,%1,%2,%3};"
        : "+f"(d[0]), "+f"(d[1]), "+f"(d[2]), "+f"(d[3])
        : "r"(a[0]), "r"(a[1]), "r"(a[2]), "r"(a[3]), "r"(b0), "r"(b1));
}

// -------------------- LayerNorm --------------------
__global__ void layernorm_kernel(const float* __restrict__ x,
                                 const float* __restrict__ g,
                                 const float* __restrict__ be,
                                 float* __restrict__ y)
{
    int row = blockIdx.x;
    int tid = threadIdx.x;
    const float* xr = x + (size_t)row * Dd_;
    float4 v = *(const float4*)(xr + tid * 4);

    __shared__ float red[8];
    __shared__ float s_mu, s_inv;

    float s = v.x + v.y + v.z + v.w;
    #pragma unroll
    for (int o = 16; o > 0; o >>= 1) s += __shfl_xor_sync(0xffffffffu, s, o);
    if ((tid & 31) == 0) red[tid >> 5] = s;
    __syncthreads();
    if (tid == 0) {
        float t = 0.f;
        #pragma unroll
        for (int i = 0; i < 8; i++) t += red[i];
        s_mu = t * (1.0f / Dd_);
    }
    __syncthreads();
    float mu = s_mu;
    float dx = v.x - mu, dy = v.y - mu, dz = v.z - mu, dw = v.w - mu;
    float q = dx*dx + dy*dy + dz*dz + dw*dw;
    #pragma unroll
    for (int o = 16; o > 0; o >>= 1) q += __shfl_xor_sync(0xffffffffu, q, o);
    if ((tid & 31) == 0) red[tid >> 5] = q;
    __syncthreads();
    if (tid == 0) {
        float t = 0.f;
        #pragma unroll
        for (int i = 0; i < 8; i++) t += red[i];
        s_inv = rsqrtf(t * (1.0f / Dd_) + 1e-5f);
    }
    __syncthreads();
    float inv = s_inv;
    int c = tid * 4;
    float* yr = y + (size_t)row * Dd_;
    yr[c + 0] = dx * inv * g[c + 0] + be[c + 0];
    yr[c + 1] = dy * inv * g[c + 1] + be[c + 1];
    yr[c + 2] = dz * inv * g[c + 2] + be[c + 2];
    yr[c + 3] = dw * inv * g[c + 3] + be[c + 3];
}

// -------------------- tf32 mma.sync GEMM: C = A(MxK) @ W(KxN) + bias [+res] [gelu] ----
// CTA tile 128x128, BK=32, 256 threads (8 warps, 4x2), warp tile 32x64.
// smem per stage: A[128 rows][128B] + B(=W^T)[128 n-rows][128B], SW128 swizzle. 2 stages.
#define GM_STAGE 32768
#define GM_SMEM  (2 * GM_STAGE + 1024)
__global__ __launch_bounds__(256)
void gemm_mma(const float* __restrict__ A, const float* __restrict__ W,
              const float* __restrict__ bias, const float* __restrict__ res,
              float* __restrict__ C, int Nc, int Kd, int dogelu)
{
    extern __shared__ float dyns[];
    const uint32_t sbase = (smem_u32(dyns) + 1023u) & ~1023u;

    const int tid  = threadIdx.x;
    const int lane = tid & 31, wid = tid >> 5;
    const int gid  = lane >> 2, qd = lane & 3;
    const int wm   = (wid >> 1) * 32;   // warp M offset in tile
    const int wn   = (wid & 1) * 64;    // warp N offset in tile
    const int n0   = blockIdx.x * 128;
    const int m0   = blockIdx.y * 128;

    float d[2][8][4];
    #pragma unroll
    for (int mt = 0; mt < 2; mt++)
        #pragma unroll
        for (int nt = 0; nt < 8; nt++)
            #pragma unroll
            for (int e = 0; e < 4; e++) d[mt][nt][e] = 0.f;

    const int nsteps = Kd >> 5;
    float4 pa[4], pb[4];

    // ---- global loads for tile kstep into registers ----
    auto ldg_tile = [&](int kstep) {
        const int k0 = kstep * 32;
        const float* Ab = A + (size_t)m0 * Kd + k0;
        #pragma unroll
        for (int p = 0; p < 4; p++) {
            int task = p * 256 + tid;
            int r = task >> 3, c4 = task & 7;
            pa[p] = *(const float4*)(Ab + (size_t)r * Kd + c4 * 4);
        }
        const float* Wb = W + (size_t)k0 * Nc + n0;
        #pragma unroll
        for (int p = 0; p < 4; p++) {
            int task = p * 256 + tid;
            int kg = task >> 7, n = task & 127;
            pb[p].x = Wb[(size_t)(kg * 4 + 0) * Nc + n];
            pb[p].y = Wb[(size_t)(kg * 4 + 1) * Nc + n];
            pb[p].z = Wb[(size_t)(kg * 4 + 2) * Nc + n];
            pb[p].w = Wb[(size_t)(kg * 4 + 3) * Nc + n];
        }
    };
    // ---- store registers into smem stage s (tf32-rounded, swizzled) ----
    auto sts_tile = [&](int s) {
        const uint32_t aA = sbase + s * GM_STAGE;
        const uint32_t bA = aA + 16384u;
        #pragma unroll
        for (int p = 0; p < 4; p++) {
            int task = p * 256 + tid;
            int r = task >> 3, c4 = task & 7;
            float4 w4;
            w4.x = ftf32(pa[p].x); w4.y = ftf32(pa[p].y);
            w4.z = ftf32(pa[p].z); w4.w = ftf32(pa[p].w);
            sts128(aA + SWZ((uint32_t)(r * 128 + c4 * 16)), w4);
        }
        #pragma unroll
        for (int p = 0; p < 4; p++) {
            int task = p * 256 + tid;
            int kg = task >> 7, n = task & 127;
            float4 w4;
            w4.x = ftf32(pb[p].x); w4.y = ftf32(pb[p].y);
            w4.z = ftf32(pb[p].z); w4.w = ftf32(pb[p].w);
            sts128(bA + SWZ((uint32_t)(n * 128 + kg * 16)), w4);
        }
    };

    ldg_tile(0);
    sts_tile(0);
    __syncthreads();

    for (int i = 0; i < nsteps; i++) {
        const int s = i & 1;
        if (i + 1 < nsteps) ldg_tile(i + 1);

        const uint32_t aA = sbase + s * GM_STAGE;
        const uint32_t bA = aA + 16384u;
        #pragma unroll
        for (int ks = 0; ks < 4; ks++) {
            uint32_t afr[2][4];
            #pragma unroll
            for (int mt = 0; mt < 2; mt++) {
                int r = wm + mt * 16 + gid;
                float2 lo = lds64(aA + SWZ((uint32_t)(r * 128 + ks * 32 + qd * 8)));
                float2 hi = lds64(aA + SWZ((uint32_t)((r + 8) * 128 + ks * 32 + qd * 8)));
                afr[mt][0] = __float_as_uint(lo.x);
                afr[mt][1] = __float_as_uint(hi.x);
                afr[mt][2] = __float_as_uint(lo.y);
                afr[mt][3] = __float_as_uint(hi.y);
            }
            #pragma unroll
            for (int nt = 0; nt < 8; nt++) {
                int n = wn + nt * 8 + gid;
                float2 bf = lds64(bA + SWZ((uint32_t)(n * 128 + ks * 32 + qd * 8)));
                uint32_t b0 = __float_as_uint(bf.x);
                uint32_t b1 = __float_as_uint(bf.y);
                mma_tf32(d[0][nt], afr[0], b0, b1);
                mma_tf32(d[1][nt], afr[1], b0, b1);
            }
        }

        if (i + 1 < nsteps) sts_tile(s ^ 1);
        __syncthreads();
    }

    // ---- epilogue: bias [+res] [gelu], float2 stores ----
    #pragma unroll
    for (int mt = 0; mt < 2; mt++) {
        #pragma unroll
        for (int nt = 0; nt < 8; nt++) {
            const int r0  = m0 + wm + mt * 16 + gid;
            const int col = n0 + wn + nt * 8 + qd * 2;
            float2 b2 = *(const float2*)(bias + col);
            #pragma unroll
            for (int half = 0; half < 2; half++) {
                const int row = r0 + half * 8;
                float ox = d[mt][nt][half * 2 + 0] + b2.x;
                float oy = d[mt][nt][half * 2 + 1] + b2.y;
                if (res) {
                    float2 r2 = *(const float2*)(res + (size_t)row * Nc + col);
                    ox += r2.x; oy += r2.y;
                }
                if (dogelu) {
                    ox = 0.5f * ox * (1.0f + erff(ox * 0.7071067811865475f));
                    oy = 0.5f * oy * (1.0f + erff(oy * 0.7071067811865475f));
                }
                float2 o2; o2.x = ox; o2.y = oy;
                *(float2*)(C + (size_t)row * Nc + col) = o2;
            }
        }
    }
}

// -------------------- RoPE --------------------
__global__ void rope_kernel(float* __restrict__ qkv,
                            const float* __restrict__ rc,
                            const float* __restrict__ rs)
{
    int idx = blockIdx.x * blockDim.x + threadIdx.x;
    int total = 2 * NT_ * Hh_ * (HD_ / 2);
    if (idx >= total) return;
    int t = idx & 1;
    int r = idx >> 1;
    int pair = r & 31;  r >>= 5;
    int h = r & 15;     r >>= 4;
    int s = r % Ss_;
    int b = r / Ss_;
    float* base = qkv + ((size_t)(b * Ss_ + s)) * (3 * Dd_) + t * Dd_ + h * HD_ + pair * 2;
    float c  = rc[s * 32 + pair];
    float sn = rs[s * 32 + pair];
    float e = base[0], o = base[1];
    base[0] = e * c - o * sn;
    base[1] = e * sn + o * c;
}

// -------------------- Tiled causal flash attention --------------------
#define FA_PAD 65
__global__ __launch_bounds__(256)
void flash_attn_kernel(const float* __restrict__ qkv, float* __restrict__ out)
{
    extern __shared__ float smf[];
    float* Qt = smf;
    float* Ks = smf + 64 * FA_PAD;
    float* Vs = smf + 2 * 64 * FA_PAD;
    float* Ps = Ks;

    const int qb = (int)gridDim.x - 1 - (int)blockIdx.x;
    const int q0 = qb * 64;
    const int bh = blockIdx.y;
    const int b = bh >> 4, h = bh & 15;
    const int tid = threadIdx.x;
    const int tx = tid & 15, ty = tid >> 4;
    const int r0 = ty * 4, c0 = tx * 4;
    const size_t rs3 = 3 * Dd_;

    {
        const float* qbase = qkv + ((size_t)(b * Ss_ + q0)) * rs3 + h * HD_;
        #pragma unroll
        for (int cch = 0; cch < 4; cch++) {
            int L = cch * 256 + tid;
            int r = L >> 4;
            int dq = (L & 15) * 4;
            float4 v = *(const float4*)(qbase + (size_t)r * rs3 + dq);
            Qt[(dq + 0) * FA_PAD + r] = v.x;
            Qt[(dq + 1) * FA_PAD + r] = v.y;
            Qt[(dq + 2) * FA_PAD + r] = v.z;
            Qt[(dq + 3) * FA_PAD + r] = v.w;
        }
    }

    float acc[4][4];
    float m_i[4], l_i[4];
    #pragma unroll
    for (int i = 0; i < 4; i++) {
        m_i[i] = -1e30f; l_i[i] = 0.f;
        #pragma unroll
        for (int j = 0; j < 4; j++) acc[i][j] = 0.f;
    }

    const float* kbase = qkv + ((size_t)(b * Ss_)) * rs3 + Dd_ + h * HD_;
    const float* vbase = qkv + ((size_t)(b * Ss_)) * rs3 + 2 * Dd_ + h * HD_;
    const int ntiles = qb + 1;

    for (int t = 0; t < ntiles; t++) {
        const int k0 = t * 64;
        __syncthreads();

        #pragma unroll
        for (int cch = 0; cch < 4; cch++) {
            int L = cch * 256 + tid;
            int r = L >> 4;
            int dq = (L & 15) * 4;
            const float* kp = kbase + (size_t)(k0 + r) * rs3 + dq;
            float4 kv = *(const float4*)kp;
            Ks[r * FA_PAD + dq + 0] = kv.x;
            Ks[r * FA_PAD + dq + 1] = kv.y;
            Ks[r * FA_PAD + dq + 2] = kv.z;
            Ks[r * FA_PAD + dq + 3] = kv.w;
            const float* vp = vbase + (size_t)(k0 + r) * rs3 + dq;
            float4 vv = *(const float4*)vp;
            Vs[r * FA_PAD + dq + 0] = vv.x;
            Vs[r * FA_PAD + dq + 1] = vv.y;
            Vs[r * FA_PAD + dq + 2] = vv.z;
            Vs[r * FA_PAD + dq + 3] = vv.w;
        }
        __syncthreads();

        float s[4][4];
        #pragma unroll
        for (int i = 0; i < 4; i++)
            #pragma unroll
            for (int j = 0; j < 4; j++) s[i][j] = 0.f;

        #pragma unroll 8
        for (int dI = 0; dI < 64; dI++) {
            float ra[4], rb[4];
            #pragma unroll
            for (int i = 0; i < 4; i++) ra[i] = Qt[dI * FA_PAD + r0 + i];
            #pragma unroll
            for (int j = 0; j < 4; j++) rb[j] = Ks[(c0 + j) * FA_PAD + dI];
            #pragma unroll
            for (int i = 0; i < 4; i++)
                #pragma unroll
                for (int j = 0; j < 4; j++)
                    s[i][j] = fmaf(ra[i], rb[j], s[i][j]);
        }

        const bool diag = (t == ntiles - 1);
        #pragma unroll
        for (int i = 0; i < 4; i++)
            #pragma unroll
            for (int j = 0; j < 4; j++) {
                float v = s[i][j] * 0.125f;
                if (diag && (c0 + j > r0 + i)) v = -1e30f;
                s[i][j] = v;
            }

        #pragma unroll
        for (int i = 0; i < 4; i++) {
            float rm = fmaxf(fmaxf(s[i][0], s[i][1]), fmaxf(s[i][2], s[i][3]));
            #pragma unroll
            for (int o = 8; o >= 1; o >>= 1)
                rm = fmaxf(rm, __shfl_xor_sync(0xffffffffu, rm, o));
            float mn = fmaxf(m_i[i], rm);
            float fac = __expf(m_i[i] - mn);
            m_i[i] = mn;
            float rsum = 0.f;
            #pragma unroll
            for (int j = 0; j < 4; j++) {
                float p = __expf(s[i][j] - mn);
                s[i][j] = p;
                rsum += p;
            }
            #pragma unroll
            for (int o = 8; o >= 1; o >>= 1)
                rsum += __shfl_xor_sync(0xffffffffu, rsum, o);
            l_i[i] = l_i[i] * fac + rsum;
            #pragma unroll
            for (int j = 0; j < 4; j++) acc[i][j] *= fac;
        }

        __syncthreads();
        #pragma unroll
        for (int i = 0; i < 4; i++)
            #pragma unroll
            for (int j = 0; j < 4; j++)
                Ps[(r0 + i) * FA_PAD + c0 + j] = s[i][j];
        __syncthreads();

        #pragma unroll 8
        for (int jj = 0; jj < 64; jj++) {
            float ra[4], rb[4];
            #pragma unroll
            for (int i = 0; i < 4; i++) ra[i] = Ps[(r0 + i) * FA_PAD + jj];
            #pragma unroll
            for (int j = 0; j < 4; j++) rb[j] = Vs[jj * FA_PAD + c0 + j];
            #pragma unroll
            for (int i = 0; i < 4; i++)
                #pragma unroll
                for (int j = 0; j < 4; j++)
                    acc[i][j] = fmaf(ra[i], rb[j], acc[i][j]);
        }
    }

    #pragma unroll
    for (int i = 0; i < 4; i++) {
        float inv = 1.0f / l_i[i];
        float* orow = out + ((size_t)(b * Ss_ + q0 + r0 + i)) * Dd_ + h * HD_ + c0;
        float4 o4;
        o4.x = acc[i][0] * inv;
        o4.y = acc[i][1] * inv;
        o4.z = acc[i][2] * inv;
        o4.w = acc[i][3] * inv;
        *(float4*)orow = o4;
    }
}

// -------------------- Cross-attention (64 keys) --------------------
__global__ __launch_bounds__(64)
void cross_attn_kernel(const float* __restrict__ qc, const float* __restrict__ kc,
                       const float* __restrict__ vc, float* __restrict__ out)
{
    int qidx = blockIdx.x;
    int bh   = blockIdx.y;
    int b = bh / Hh_, h = bh % Hh_;
    int tid = threadIdx.x;

    __shared__ float sq[HD_];
    __shared__ float p[MEM_];
    __shared__ float red[2];

    const float* qrow = qc + ((size_t)(b * Ss_ + qidx)) * Dd_ + h * HD_;
    sq[tid] = qrow[tid];
    __syncthreads();

    const float* krow = kc + ((size_t)(b * MEM_ + tid)) * Dd_ + h * HD_;
    float s = 0.f;
    #pragma unroll
    for (int d = 0; d < HD_; d += 4) {
        float4 k4 = *(const float4*)(krow + d);
        s = fmaf(sq[d + 0], k4.x, s);
        s = fmaf(sq[d + 1], k4.y, s);
        s = fmaf(sq[d + 2], k4.z, s);
        s = fmaf(sq[d + 3], k4.w, s);
    }
    s *= 0.125f;

    float m = s;
    #pragma unroll
    for (int o = 16; o > 0; o >>= 1) m = fmaxf(m, __shfl_xor_sync(0xffffffffu, m, o));
    if ((tid & 31) == 0) red[tid >> 5] = m;
    __syncthreads();
    float gm = fmaxf(red[0], red[1]);
    float pv = expf(s - gm);
    p[tid] = pv;
    float su = pv;
    #pragma unroll
    for (int o = 16; o > 0; o >>= 1) su += __shfl_xor_sync(0xffffffffu, su, o);
    __syncthreads();
    if ((tid & 31) == 0) red[tid >> 5] = su;
    __syncthreads();
    float gl = red[0] + red[1];

    const float* vbase = vc + ((size_t)(b * MEM_)) * Dd_ + h * HD_ + tid;
    float a = 0.f;
    #pragma unroll 4
    for (int j = 0; j < MEM_; j++)
        a = fmaf(p[j], vbase[(size_t)j * Dd_], a);

    out[((size_t)(b * Ss_ + qidx)) * Dd_ + h * HD_ + tid] = a / gl;
}

// -------------------- launch --------------------
extern "C" void kernel_launch(void* const* d_in, const int* in_sizes, int n_in,
                              void* d_out, int out_size)
{
    const float* tgt      = (const float*)d_in[0];
    const float* memory   = (const float*)d_in[1];
    const float* rope_cos = (const float*)d_in[2];
    const float* rope_sin = (const float*)d_in[3];
    const float* W_qkv    = (const float*)d_in[4];
    const float* b_qkv    = (const float*)d_in[5];
    const float* W_o      = (const float*)d_in[6];
    const float* b_o      = (const float*)d_in[7];
    const float* Wq_c     = (const float*)d_in[8];
    const float* bq_c     = (const float*)d_in[9];
    const float* Wk_c     = (const float*)d_in[10];
    const float* bk_c     = (const float*)d_in[11];
    const float* Wv_c     = (const float*)d_in[12];
    const float* bv_c     = (const float*)d_in[13];
    const float* W_co     = (const float*)d_in[14];
    const float* b_co     = (const float*)d_in[15];
    const float* W1       = (const float*)d_in[16];
    const float* b1       = (const float*)d_in[17];
    const float* W2       = (const float*)d_in[18];
    const float* b2       = (const float*)d_in[19];
    const float* g1       = (const float*)d_in[20];
    const float* be1      = (const float*)d_in[21];
    const float* g2       = (const float*)d_in[22];
    const float* be2      = (const float*)d_in[23];
    const float* g3       = (const float*)d_in[24];
    const float* be3      = (const float*)d_in[25];
    float* out = (float*)d_out;

    float *x, *qkv, *sa, *tgtb, *kc, *vc, *ffn;
    cudaGetSymbolAddress((void**)&x,    g_x);
    cudaGetSymbolAddress((void**)&qkv,  g_qkv);
    cudaGetSymbolAddress((void**)&sa,   g_sa);
    cudaGetSymbolAddress((void**)&tgtb, g_tgt);
    cudaGetSymbolAddress((void**)&kc,   g_kc);
    cudaGetSymbolAddress((void**)&vc,   g_vc);
    cudaGetSymbolAddress((void**)&ffn,  g_ffn);

    const int fa_smem = 3 * 64 * FA_PAD * (int)sizeof(float);
    cudaFuncSetAttribute(flash_attn_kernel,
                         cudaFuncAttributeMaxDynamicSharedMemorySize, fa_smem);
    cudaFuncSetAttribute(gemm_mma,
                         cudaFuncAttributeMaxDynamicSharedMemorySize, GM_SMEM);

    // 1) x = LN1(tgt)
    layernorm_kernel<<<NT_, 256>>>(tgt, g1, be1, x);
    // 2) qkv = x @ W_qkv + b
    gemm_mma<<<dim3(3 * Dd_ / 128, NT_ / 128), 256, GM_SMEM>>>(x, W_qkv, b_qkv, nullptr, qkv, 3 * Dd_, Dd_, 0);
    // 3) RoPE on q,k
    {
        int total = 2 * NT_ * Hh_ * (HD_ / 2);
        rope_kernel<<<(total + 255) / 256, 256>>>(qkv, rope_cos, rope_sin);
    }
    // 4) causal self-attention (tiled flash) -> sa
    flash_attn_kernel<<<dim3(Ss_ / 64, Bb_ * Hh_), 256, fa_smem>>>(qkv, sa);
    // 5) tgtb = tgt + sa @ W_o + b_o
    gemm_mma<<<dim3(Dd_ / 128, NT_ / 128), 256, GM_SMEM>>>(sa, W_o, b_o, tgt, tgtb, Dd_, Dd_, 0);
    // 6) x = LN2(tgtb)
    layernorm_kernel<<<NT_, 256>>>(tgtb, g2, be2, x);
    // 7) qc = x @ Wq_c (reuse qkv buffer)
    gemm_mma<<<dim3(Dd_ / 128, NT_ / 128), 256, GM_SMEM>>>(x, Wq_c, bq_c, nullptr, qkv, Dd_, Dd_, 0);
    // 8) kc/vc = memory @ Wk_c / Wv_c  (128 rows = 1 M-tile)
    gemm_mma<<<dim3(Dd_ / 128, 1), 256, GM_SMEM>>>(memory, Wk_c, bk_c, nullptr, kc, Dd_, Dd_, 0);
    gemm_mma<<<dim3(Dd_ / 128, 1), 256, GM_SMEM>>>(memory, Wv_c, bv_c, nullptr, vc, Dd_, Dd_, 0);
    // 9) cross-attention -> sa (reuse)
    cross_attn_kernel<<<dim3(Ss_, Bb_ * Hh_), 64>>>(qkv, kc, vc, sa);
    // 10) tgtb += sa @ W_co + b_co
    gemm_mma<<<dim3(Dd_ / 128, NT_ / 128), 256, GM_SMEM>>>(sa, W_co, b_co, tgtb, tgtb, Dd_, Dd_, 0);
    // 11) x = LN3(tgtb)
    layernorm_kernel<<<NT_, 256>>>(tgtb, g3, be3, x);
    // 12) ffn = gelu(x @ W1 + b1)
    gemm_mma<<<dim3(FF_ / 128, NT_ / 128), 256, GM_SMEM>>>(x, W1, b1, nullptr, ffn, FF_, Dd_, 1);
    // 13) out = tgtb + ffn @ W2 + b2
    gemm_mma<<<dim3(Dd_ / 128, NT_ / 128), 256, GM_SMEM>>>(ffn, W2, b2, tgtb, out, Dd_, FF_, 0);
}

// round 5
// speedup vs baseline: 4.1163x; 1.2559x over previous
#include <cuda_runtime.h>
#include <cstdint>
#include <math.h>

// Problem constants
#define Bb_  2
#define Ss_  2048
#define MEM_ 64
#define Dd_  1024
#define Hh_  16
#define FF_  4096
#define HD_  64
#define NT_  (Bb_ * Ss_)   // 4096 tokens

// -------------------- scratch (device globals; no runtime alloc) --------------------
__device__ float g_x   [(size_t)NT_ * Dd_];
__device__ float g_qkv [(size_t)NT_ * 3 * Dd_];
__device__ float g_sa  [(size_t)NT_ * Dd_];
__device__ float g_tgt [(size_t)NT_ * Dd_];
__device__ float g_kc  [(size_t)Bb_ * MEM_ * Dd_];
__device__ float g_vc  [(size_t)Bb_ * MEM_ * Dd_];
__device__ float g_ffn [(size_t)NT_ * FF_];

// -------------------- helpers --------------------
__device__ __forceinline__ uint32_t smem_u32(const void* p) {
    uint32_t a;
    asm("{ .reg .u64 t; cvta.to.shared.u64 t, %1; cvt.u32.u64 %0, t; }" : "=r"(a) : "l"(p));
    return a;
}
__device__ __forceinline__ float ftf32(float x) {
    float y;
    asm("cvt.rna.tf32.f32 %0, %1;" : "=f"(y) : "f"(x));
    return y;
}
__device__ __forceinline__ void sts128(uint32_t addr, float4 v) {
    asm volatile("st.shared.v4.f32 [%0], {%1,%2,%3,%4};"
                 :: "r"(addr), "f"(v.x), "f"(v.y), "f"(v.z), "f"(v.w) : "memory");
}
__device__ __forceinline__ float2 lds64(uint32_t addr) {
    float2 v;
    asm volatile("ld.shared.v2.f32 {%0,%1}, [%2];" : "=f"(v.x), "=f"(v.y) : "r"(addr));
    return v;
}
#define SWZ(b) ((b) ^ (((b) >> 3) & 0x70))

__device__ __forceinline__ void mma_tf32(float* d, const uint32_t* a, uint32_t b0, uint32_t b1) {
    asm volatile(
        "mma.sync.aligned.m16n8k8.row.col.f32.tf32.tf32.f32 "
        "{%0,%1,%2,%3}, {%4,%5,%6,%7}, {%8,%9}, {%0,%1,%2,%3};"
        : "+f"(d[0]), "+f"(d[1]), "+f"(d[2]), "+f"(d[3])
        : "r"(a[0]), "r"(a[1]), "r"(a[2]), "r"(a[3]), "r"(b0), "r"(b1));
}

// -------------------- LayerNorm --------------------
__global__ void layernorm_kernel(const float* __restrict__ x,
                                 const float* __restrict__ g,
                                 const float* __restrict__ be,
                                 float* __restrict__ y)
{
    int row = blockIdx.x;
    int tid = threadIdx.x;
    const float* xr = x + (size_t)row * Dd_;
    float4 v = *(const float4*)(xr + tid * 4);

    __shared__ float red[8];
    __shared__ float s_mu, s_inv;

    float s = v.x + v.y + v.z + v.w;
    #pragma unroll
    for (int o = 16; o > 0; o >>= 1) s += __shfl_xor_sync(0xffffffffu, s, o);
    if ((tid & 31) == 0) red[tid >> 5] = s;
    __syncthreads();
    if (tid == 0) {
        float t = 0.f;
        #pragma unroll
        for (int i = 0; i < 8; i++) t += red[i];
        s_mu = t * (1.0f / Dd_);
    }
    __syncthreads();
    float mu = s_mu;
    float dx = v.x - mu, dy = v.y - mu, dz = v.z - mu, dw = v.w - mu;
    float q = dx*dx + dy*dy + dz*dz + dw*dw;
    #pragma unroll
    for (int o = 16; o > 0; o >>= 1) q += __shfl_xor_sync(0xffffffffu, q, o);
    if ((tid & 31) == 0) red[tid >> 5] = q;
    __syncthreads();
    if (tid == 0) {
        float t = 0.f;
        #pragma unroll
        for (int i = 0; i < 8; i++) t += red[i];
        s_inv = rsqrtf(t * (1.0f / Dd_) + 1e-5f);
    }
    __syncthreads();
    float inv = s_inv;
    int c = tid * 4;
    float* yr = y + (size_t)row * Dd_;
    yr[c + 0] = dx * inv * g[c + 0] + be[c + 0];
    yr[c + 1] = dy * inv * g[c + 1] + be[c + 1];
    yr[c + 2] = dz * inv * g[c + 2] + be[c + 2];
    yr[c + 3] = dw * inv * g[c + 3] + be[c + 3];
}

// -------------------- tf32 mma.sync GEMM: C = A(MxK) @ W(KxN) + bias [+res] [gelu] ----
#define GM_STAGE 32768
#define GM_SMEM  (2 * GM_STAGE + 1024)
__global__ __launch_bounds__(256)
void gemm_mma(const float* __restrict__ A, const float* __restrict__ W,
              const float* __restrict__ bias, const float* __restrict__ res,
              float* __restrict__ C, int Nc, int Kd, int dogelu)
{
    extern __shared__ float dyns[];
    const uint32_t sbase = (smem_u32(dyns) + 1023u) & ~1023u;

    const int tid  = threadIdx.x;
    const int lane = tid & 31, wid = tid >> 5;
    const int gid  = lane >> 2, qd = lane & 3;
    const int wm   = (wid >> 1) * 32;
    const int wn   = (wid & 1) * 64;
    const int n0   = blockIdx.x * 128;
    const int m0   = blockIdx.y * 128;

    float d[2][8][4];
    #pragma unroll
    for (int mt = 0; mt < 2; mt++)
        #pragma unroll
        for (int nt = 0; nt < 8; nt++)
            #pragma unroll
            for (int e = 0; e < 4; e++) d[mt][nt][e] = 0.f;

    const int nsteps = Kd >> 5;
    float4 pa[4], pb[4];

    auto ldg_tile = [&](int kstep) {
        const int k0 = kstep * 32;
        const float* Ab = A + (size_t)m0 * Kd + k0;
        #pragma unroll
        for (int p = 0; p < 4; p++) {
            int task = p * 256 + tid;
            int r = task >> 3, c4 = task & 7;
            pa[p] = *(const float4*)(Ab + (size_t)r * Kd + c4 * 4);
        }
        const float* Wb = W + (size_t)k0 * Nc + n0;
        #pragma unroll
        for (int p = 0; p < 4; p++) {
            int task = p * 256 + tid;
            int kg = task >> 7, n = task & 127;
            pb[p].x = Wb[(size_t)(kg * 4 + 0) * Nc + n];
            pb[p].y = Wb[(size_t)(kg * 4 + 1) * Nc + n];
            pb[p].z = Wb[(size_t)(kg * 4 + 2) * Nc + n];
            pb[p].w = Wb[(size_t)(kg * 4 + 3) * Nc + n];
        }
    };
    auto sts_tile = [&](int s) {
        const uint32_t aA = sbase + s * GM_STAGE;
        const uint32_t bA = aA + 16384u;
        #pragma unroll
        for (int p = 0; p < 4; p++) {
            int task = p * 256 + tid;
            int r = task >> 3, c4 = task & 7;
            float4 w4;
            w4.x = ftf32(pa[p].x); w4.y = ftf32(pa[p].y);
            w4.z = ftf32(pa[p].z); w4.w = ftf32(pa[p].w);
            sts128(aA + SWZ((uint32_t)(r * 128 + c4 * 16)), w4);
        }
        #pragma unroll
        for (int p = 0; p < 4; p++) {
            int task = p * 256 + tid;
            int kg = task >> 7, n = task & 127;
            float4 w4;
            w4.x = ftf32(pb[p].x); w4.y = ftf32(pb[p].y);
            w4.z = ftf32(pb[p].z); w4.w = ftf32(pb[p].w);
            sts128(bA + SWZ((uint32_t)(n * 128 + kg * 16)), w4);
        }
    };

    ldg_tile(0);
    sts_tile(0);
    __syncthreads();

    for (int i = 0; i < nsteps; i++) {
        const int s = i & 1;
        if (i + 1 < nsteps) ldg_tile(i + 1);

        const uint32_t aA = sbase + s * GM_STAGE;
        const uint32_t bA = aA + 16384u;
        #pragma unroll
        for (int ks = 0; ks < 4; ks++) {
            uint32_t afr[2][4];
            #pragma unroll
            for (int mt = 0; mt < 2; mt++) {
                int r = wm + mt * 16 + gid;
                float2 lo = lds64(aA + SWZ((uint32_t)(r * 128 + ks * 32 + qd * 8)));
                float2 hi = lds64(aA + SWZ((uint32_t)((r + 8) * 128 + ks * 32 + qd * 8)));
                afr[mt][0] = __float_as_uint(lo.x);
                afr[mt][1] = __float_as_uint(hi.x);
                afr[mt][2] = __float_as_uint(lo.y);
                afr[mt][3] = __float_as_uint(hi.y);
            }
            #pragma unroll
            for (int nt = 0; nt < 8; nt++) {
                int n = wn + nt * 8 + gid;
                float2 bf = lds64(bA + SWZ((uint32_t)(n * 128 + ks * 32 + qd * 8)));
                uint32_t b0 = __float_as_uint(bf.x);
                uint32_t b1 = __float_as_uint(bf.y);
                mma_tf32(d[0][nt], afr[0], b0, b1);
                mma_tf32(d[1][nt], afr[1], b0, b1);
            }
        }

        if (i + 1 < nsteps) sts_tile(s ^ 1);
        __syncthreads();
    }

    #pragma unroll
    for (int mt = 0; mt < 2; mt++) {
        #pragma unroll
        for (int nt = 0; nt < 8; nt++) {
            const int r0  = m0 + wm + mt * 16 + gid;
            const int col = n0 + wn + nt * 8 + qd * 2;
            float2 b2 = *(const float2*)(bias + col);
            #pragma unroll
            for (int half = 0; half < 2; half++) {
                const int row = r0 + half * 8;
                float ox = d[mt][nt][half * 2 + 0] + b2.x;
                float oy = d[mt][nt][half * 2 + 1] + b2.y;
                if (res) {
                    float2 r2 = *(const float2*)(res + (size_t)row * Nc + col);
                    ox += r2.x; oy += r2.y;
                }
                if (dogelu) {
                    ox = 0.5f * ox * (1.0f + erff(ox * 0.7071067811865475f));
                    oy = 0.5f * oy * (1.0f + erff(oy * 0.7071067811865475f));
                }
                float2 o2; o2.x = ox; o2.y = oy;
                *(float2*)(C + (size_t)row * Nc + col) = o2;
            }
        }
    }
}

// -------------------- RoPE --------------------
__global__ void rope_kernel(float* __restrict__ qkv,
                            const float* __restrict__ rc,
                            const float* __restrict__ rs)
{
    int idx = blockIdx.x * blockDim.x + threadIdx.x;
    int total = 2 * NT_ * Hh_ * (HD_ / 2);
    if (idx >= total) return;
    int t = idx & 1;
    int r = idx >> 1;
    int pair = r & 31;  r >>= 5;
    int h = r & 15;     r >>= 4;
    int s = r % Ss_;
    int b = r / Ss_;
    float* base = qkv + ((size_t)(b * Ss_ + s)) * (3 * Dd_) + t * Dd_ + h * HD_ + pair * 2;
    float c  = rc[s * 32 + pair];
    float sn = rs[s * 32 + pair];
    float e = base[0], o = base[1];
    base[0] = e * c - o * sn;
    base[1] = e * sn + o * c;
}

// -------------------- tf32 mma flash attention --------------------
// 1 block = 64 queries x (b,h). 128 threads / 4 warps; warp owns 16 query rows.
// Q frags in registers (loaded once, pre-scaled). K,V staged per 64-key tile.
// S C-frags double as P A-frags (paired-k permutation) -> no smem round-trip.
#define FA2_PAD  68
#define FA2_SMEM (2 * 64 * FA2_PAD * 4)   // 34,816 B
__global__ __launch_bounds__(128)
void flash_attn_tc(const float* __restrict__ qkv, float* __restrict__ out)
{
    extern __shared__ float sm2[];
    float* Ks = sm2;                   // K natural [j][d], pad 68 (also stages Q)
    float* Vs = sm2 + 64 * FA2_PAD;    // V natural [j][d], pad 68

    const int qb = (int)gridDim.x - 1 - (int)blockIdx.x;  // heavy blocks first
    const int q0 = qb * 64;
    const int bh = blockIdx.y;
    const int b = bh >> 4, h = bh & 15;
    const int tid = threadIdx.x, lane = tid & 31, wid = tid >> 5;
    const int gid = lane >> 2, qd = lane & 3;
    const int wr = wid * 16;
    const size_t rs3 = 3 * Dd_;

    const float* qbase = qkv + (size_t)(b * Ss_ + q0) * rs3 + h * HD_;
    const float* kbase = qkv + (size_t)(b * Ss_) * rs3 + Dd_ + h * HD_;
    const float* vbase = qkv + (size_t)(b * Ss_) * rs3 + 2 * Dd_ + h * HD_;

    // stage Q (tf32-rounded, pre-scaled by 1/8) into Ks
    #pragma unroll
    for (int p = 0; p < 8; p++) {
        int L = p * 128 + tid;
        int r = L >> 4, d4 = (L & 15) * 4;
        float4 v = *(const float4*)(qbase + (size_t)r * rs3 + d4);
        float4 w;
        w.x = ftf32(v.x) * 0.125f; w.y = ftf32(v.y) * 0.125f;
        w.z = ftf32(v.z) * 0.125f; w.w = ftf32(v.w) * 0.125f;
        *(float4*)(Ks + r * FA2_PAD + d4) = w;
    }
    __syncthreads();

    // Q fragments (A-layout, paired-k permutation)
    uint32_t qf[8][4];
    #pragma unroll
    for (int kt = 0; kt < 8; kt++) {
        float2 lo = *(const float2*)(Ks + (wr + gid) * FA2_PAD + kt * 8 + qd * 2);
        float2 hi = *(const float2*)(Ks + (wr + gid + 8) * FA2_PAD + kt * 8 + qd * 2);
        qf[kt][0] = __float_as_uint(lo.x);
        qf[kt][1] = __float_as_uint(hi.x);
        qf[kt][2] = __float_as_uint(lo.y);
        qf[kt][3] = __float_as_uint(hi.y);
    }
    __syncthreads();

    float of[8][4];
    #pragma unroll
    for (int nt = 0; nt < 8; nt++)
        #pragma unroll
        for (int e = 0; e < 4; e++) of[nt][e] = 0.f;
    float m1 = -1e30f, m2 = -1e30f, l1 = 0.f, l2 = 0.f;

    const int aq1 = q0 + wr + gid;

    for (int t = 0; t <= qb; t++) {
        const int k0 = t * 64;
        // load K,V tiles (tf32-rounded)
        #pragma unroll
        for (int p = 0; p < 8; p++) {
            int L = p * 128 + tid;
            int r = L >> 4, d4 = (L & 15) * 4;
            float4 kv = *(const float4*)(kbase + (size_t)(k0 + r) * rs3 + d4);
            float4 kw;
            kw.x = ftf32(kv.x); kw.y = ftf32(kv.y); kw.z = ftf32(kv.z); kw.w = ftf32(kv.w);
            *(float4*)(Ks + r * FA2_PAD + d4) = kw;
            float4 vv = *(const float4*)(vbase + (size_t)(k0 + r) * rs3 + d4);
            float4 vw;
            vw.x = ftf32(vv.x); vw.y = ftf32(vv.y); vw.z = ftf32(vv.z); vw.w = ftf32(vv.w);
            *(float4*)(Vs + r * FA2_PAD + d4) = vw;
        }
        __syncthreads();

        // S = Q @ K^T  (scaled already via Q)
        float sf[8][4];
        #pragma unroll
        for (int nt = 0; nt < 8; nt++)
            #pragma unroll
            for (int e = 0; e < 4; e++) sf[nt][e] = 0.f;

        #pragma unroll
        for (int kt = 0; kt < 8; kt++) {
            #pragma unroll
            for (int nt = 0; nt < 8; nt++) {
                float2 bk = *(const float2*)(Ks + (nt * 8 + gid) * FA2_PAD + kt * 8 + qd * 2);
                mma_tf32(sf[nt], qf[kt], __float_as_uint(bk.x), __float_as_uint(bk.y));
            }
        }

        // causal mask (diagonal tile only)
        if (t == qb) {
            #pragma unroll
            for (int nt = 0; nt < 8; nt++) {
                int c = k0 + nt * 8 + qd * 2;
                if (c     > aq1)     sf[nt][0] = -1e30f;
                if (c + 1 > aq1)     sf[nt][1] = -1e30f;
                if (c     > aq1 + 8) sf[nt][2] = -1e30f;
                if (c + 1 > aq1 + 8) sf[nt][3] = -1e30f;
            }
        }

        // online softmax over quad lanes
        float mx1 = -1e30f, mx2 = -1e30f;
        #pragma unroll
        for (int nt = 0; nt < 8; nt++) {
            mx1 = fmaxf(mx1, fmaxf(sf[nt][0], sf[nt][1]));
            mx2 = fmaxf(mx2, fmaxf(sf[nt][2], sf[nt][3]));
        }
        mx1 = fmaxf(mx1, __shfl_xor_sync(0xffffffffu, mx1, 1));
        mx1 = fmaxf(mx1, __shfl_xor_sync(0xffffffffu, mx1, 2));
        mx2 = fmaxf(mx2, __shfl_xor_sync(0xffffffffu, mx2, 1));
        mx2 = fmaxf(mx2, __shfl_xor_sync(0xffffffffu, mx2, 2));
        float nm1 = fmaxf(m1, mx1), nm2 = fmaxf(m2, mx2);
        float f1 = __expf(m1 - nm1), f2v = __expf(m2 - nm2);
        m1 = nm1; m2 = nm2;
        float s1 = 0.f, s2 = 0.f;
        #pragma unroll
        for (int nt = 0; nt < 8; nt++) {
            sf[nt][0] = __expf(sf[nt][0] - nm1); s1 += sf[nt][0];
            sf[nt][1] = __expf(sf[nt][1] - nm1); s1 += sf[nt][1];
            sf[nt][2] = __expf(sf[nt][2] - nm2); s2 += sf[nt][2];
            sf[nt][3] = __expf(sf[nt][3] - nm2); s2 += sf[nt][3];
        }
        s1 += __shfl_xor_sync(0xffffffffu, s1, 1);
        s1 += __shfl_xor_sync(0xffffffffu, s1, 2);
        s2 += __shfl_xor_sync(0xffffffffu, s2, 1);
        s2 += __shfl_xor_sync(0xffffffffu, s2, 2);
        l1 = l1 * f1 + s1;
        l2 = l2 * f2v + s2;
        #pragma unroll
        for (int nt = 0; nt < 8; nt++) {
            of[nt][0] *= f1;  of[nt][1] *= f1;
            of[nt][2] *= f2v; of[nt][3] *= f2v;
        }

        // O += P @ V  (P C-frags reused as A-frags: {c0,c2,c1,c3})
        #pragma unroll
        for (int kt = 0; kt < 8; kt++) {
            uint32_t af[4] = { __float_as_uint(sf[kt][0]), __float_as_uint(sf[kt][2]),
                               __float_as_uint(sf[kt][1]), __float_as_uint(sf[kt][3]) };
            const float* vrow0 = Vs + (kt * 8 + qd * 2) * FA2_PAD;
            const float* vrow1 = vrow0 + FA2_PAD;
            #pragma unroll
            for (int nt = 0; nt < 8; nt++) {
                uint32_t b0 = __float_as_uint(vrow0[nt * 8 + gid]);
                uint32_t b1 = __float_as_uint(vrow1[nt * 8 + gid]);
                mma_tf32(of[nt], af, b0, b1);
            }
        }
        __syncthreads();
    }

    // epilogue: normalize, store (b,s,D layout), v2 stores
    float inv1 = 1.0f / l1, inv2 = 1.0f / l2;
    float* o1base = out + (size_t)(b * Ss_ + aq1) * Dd_ + h * HD_;
    float* o2base = out + (size_t)(b * Ss_ + aq1 + 8) * Dd_ + h * HD_;
    #pragma unroll
    for (int nt = 0; nt < 8; nt++) {
        float2 o1; o1.x = of[nt][0] * inv1; o1.y = of[nt][1] * inv1;
        float2 o2; o2.x = of[nt][2] * inv2; o2.y = of[nt][3] * inv2;
        *(float2*)(o1base + nt * 8 + qd * 2) = o1;
        *(float2*)(o2base + nt * 8 + qd * 2) = o2;
    }
}

// -------------------- Cross-attention (64 keys) --------------------
__global__ __launch_bounds__(64)
void cross_attn_kernel(const float* __restrict__ qc, const float* __restrict__ kc,
                       const float* __restrict__ vc, float* __restrict__ out)
{
    int qidx = blockIdx.x;
    int bh   = blockIdx.y;
    int b = bh / Hh_, h = bh % Hh_;
    int tid = threadIdx.x;

    __shared__ float sq[HD_];
    __shared__ float p[MEM_];
    __shared__ float red[2];

    const float* qrow = qc + ((size_t)(b * Ss_ + qidx)) * Dd_ + h * HD_;
    sq[tid] = qrow[tid];
    __syncthreads();

    const float* krow = kc + ((size_t)(b * MEM_ + tid)) * Dd_ + h * HD_;
    float s = 0.f;
    #pragma unroll
    for (int d = 0; d < HD_; d += 4) {
        float4 k4 = *(const float4*)(krow + d);
        s = fmaf(sq[d + 0], k4.x, s);
        s = fmaf(sq[d + 1], k4.y, s);
        s = fmaf(sq[d + 2], k4.z, s);
        s = fmaf(sq[d + 3], k4.w, s);
    }
    s *= 0.125f;

    float m = s;
    #pragma unroll
    for (int o = 16; o > 0; o >>= 1) m = fmaxf(m, __shfl_xor_sync(0xffffffffu, m, o));
    if ((tid & 31) == 0) red[tid >> 5] = m;
    __syncthreads();
    float gm = fmaxf(red[0], red[1]);
    float pv = expf(s - gm);
    p[tid] = pv;
    float su = pv;
    #pragma unroll
    for (int o = 16; o > 0; o >>= 1) su += __shfl_xor_sync(0xffffffffu, su, o);
    __syncthreads();
    if ((tid & 31) == 0) red[tid >> 5] = su;
    __syncthreads();
    float gl = red[0] + red[1];

    const float* vbase = vc + ((size_t)(b * MEM_)) * Dd_ + h * HD_ + tid;
    float a = 0.f;
    #pragma unroll 4
    for (int j = 0; j < MEM_; j++)
        a = fmaf(p[j], vbase[(size_t)j * Dd_], a);

    out[((size_t)(b * Ss_ + qidx)) * Dd_ + h * HD_ + tid] = a / gl;
}

// -------------------- launch --------------------
extern "C" void kernel_launch(void* const* d_in, const int* in_sizes, int n_in,
                              void* d_out, int out_size)
{
    const float* tgt      = (const float*)d_in[0];
    const float* memory   = (const float*)d_in[1];
    const float* rope_cos = (const float*)d_in[2];
    const float* rope_sin = (const float*)d_in[3];
    const float* W_qkv    = (const float*)d_in[4];
    const float* b_qkv    = (const float*)d_in[5];
    const float* W_o      = (const float*)d_in[6];
    const float* b_o      = (const float*)d_in[7];
    const float* Wq_c     = (const float*)d_in[8];
    const float* bq_c     = (const float*)d_in[9];
    const float* Wk_c     = (const float*)d_in[10];
    const float* bk_c     = (const float*)d_in[11];
    const float* Wv_c     = (const float*)d_in[12];
    const float* bv_c     = (const float*)d_in[13];
    const float* W_co     = (const float*)d_in[14];
    const float* b_co     = (const float*)d_in[15];
    const float* W1       = (const float*)d_in[16];
    const float* b1       = (const float*)d_in[17];
    const float* W2       = (const float*)d_in[18];
    const float* b2       = (const float*)d_in[19];
    const float* g1       = (const float*)d_in[20];
    const float* be1      = (const float*)d_in[21];
    const float* g2       = (const float*)d_in[22];
    const float* be2      = (const float*)d_in[23];
    const float* g3       = (const float*)d_in[24];
    const float* be3      = (const float*)d_in[25];
    float* out = (float*)d_out;

    float *x, *qkv, *sa, *tgtb, *kc, *vc, *ffn;
    cudaGetSymbolAddress((void**)&x,    g_x);
    cudaGetSymbolAddress((void**)&qkv,  g_qkv);
    cudaGetSymbolAddress((void**)&sa,   g_sa);
    cudaGetSymbolAddress((void**)&tgtb, g_tgt);
    cudaGetSymbolAddress((void**)&kc,   g_kc);
    cudaGetSymbolAddress((void**)&vc,   g_vc);
    cudaGetSymbolAddress((void**)&ffn,  g_ffn);

    cudaFuncSetAttribute(flash_attn_tc,
                         cudaFuncAttributeMaxDynamicSharedMemorySize, FA2_SMEM);
    cudaFuncSetAttribute(gemm_mma,
                         cudaFuncAttributeMaxDynamicSharedMemorySize, GM_SMEM);

    // 1) x = LN1(tgt)
    layernorm_kernel<<<NT_, 256>>>(tgt, g1, be1, x);
    // 2) qkv = x @ W_qkv + b
    gemm_mma<<<dim3(3 * Dd_ / 128, NT_ / 128), 256, GM_SMEM>>>(x, W_qkv, b_qkv, nullptr, qkv, 3 * Dd_, Dd_, 0);
    // 3) RoPE on q,k
    {
        int total = 2 * NT_ * Hh_ * (HD_ / 2);
        rope_kernel<<<(total + 255) / 256, 256>>>(qkv, rope_cos, rope_sin);
    }
    // 4) causal self-attention (tf32 mma flash) -> sa
    flash_attn_tc<<<dim3(Ss_ / 64, Bb_ * Hh_), 128, FA2_SMEM>>>(qkv, sa);
    // 5) tgtb = tgt + sa @ W_o + b_o
    gemm_mma<<<dim3(Dd_ / 128, NT_ / 128), 256, GM_SMEM>>>(sa, W_o, b_o, tgt, tgtb, Dd_, Dd_, 0);
    // 6) x = LN2(tgtb)
    layernorm_kernel<<<NT_, 256>>>(tgtb, g2, be2, x);
    // 7) qc = x @ Wq_c (reuse qkv buffer)
    gemm_mma<<<dim3(Dd_ / 128, NT_ / 128), 256, GM_SMEM>>>(x, Wq_c, bq_c, nullptr, qkv, Dd_, Dd_, 0);
    // 8) kc/vc = memory @ Wk_c / Wv_c
    gemm_mma<<<dim3(Dd_ / 128, 1), 256, GM_SMEM>>>(memory, Wk_c, bk_c, nullptr, kc, Dd_, Dd_, 0);
    gemm_mma<<<dim3(Dd_ / 128, 1), 256, GM_SMEM>>>(memory, Wv_c, bv_c, nullptr, vc, Dd_, Dd_, 0);
    // 9) cross-attention -> sa (reuse)
    cross_attn_kernel<<<dim3(Ss_, Bb_ * Hh_), 64>>>(qkv, kc, vc, sa);
    // 10) tgtb += sa @ W_co + b_co
    gemm_mma<<<dim3(Dd_ / 128, NT_ / 128), 256, GM_SMEM>>>(sa, W_co, b_co, tgtb, tgtb, Dd_, Dd_, 0);
    // 11) x = LN3(tgtb)
    layernorm_kernel<<<NT_, 256>>>(tgtb, g3, be3, x);
    // 12) ffn = gelu(x @ W1 + b1)
    gemm_mma<<<dim3(FF_ / 128, NT_ / 128), 256, GM_SMEM>>>(x, W1, b1, nullptr, ffn, FF_, Dd_, 1);
    // 13) out = tgtb + ffn @ W2 + b2
    gemm_mma<<<dim3(Dd_ / 128, NT_ / 128), 256, GM_SMEM>>>(ffn, W2, b2, tgtb, out, Dd_, FF_, 0);
}

// round 6
// speedup vs baseline: 4.3862x; 1.0656x over previous
#include <cuda_runtime.h>
#include <cstdint>
#include <math.h>

// Problem constants
#define Bb_  2
#define Ss_  2048
#define MEM_ 64
#define Dd_  1024
#define Hh_  16
#define FF_  4096
#define HD_  64
#define NT_  (Bb_ * Ss_)   // 4096 tokens

// -------------------- scratch (device globals; no runtime alloc) --------------------
__device__ float g_x   [(size_t)NT_ * Dd_];
__device__ float g_qkv [(size_t)NT_ * 3 * Dd_];
__device__ float g_sa  [(size_t)NT_ * Dd_];
__device__ float g_tgt [(size_t)NT_ * Dd_];
__device__ float g_kc  [(size_t)Bb_ * MEM_ * Dd_];
__device__ float g_vc  [(size_t)Bb_ * MEM_ * Dd_];
__device__ float g_ffn [(size_t)NT_ * FF_];
__device__ float g_wT  [(size_t)16 * 1024 * 1024];   // transposed tf32 weights

// offsets into g_wT (floats)
#define WT_QKV 0u
#define WT_O   (3u * 1024u * 1024u)
#define WT_QC  (4u * 1024u * 1024u)
#define WT_KC  (5u * 1024u * 1024u)
#define WT_VC  (6u * 1024u * 1024u)
#define WT_CO  (7u * 1024u * 1024u)
#define WT_W1  (8u * 1024u * 1024u)
#define WT_W2  (12u * 1024u * 1024u)

// -------------------- helpers --------------------
__device__ __forceinline__ uint32_t smem_u32(const void* p) {
    uint32_t a;
    asm("{ .reg .u64 t; cvta.to.shared.u64 t, %1; cvt.u32.u64 %0, t; }" : "=r"(a) : "l"(p));
    return a;
}
__device__ __forceinline__ float ftf32(float x) {
    float y;
    asm("cvt.rna.tf32.f32 %0, %1;" : "=f"(y) : "f"(x));
    return y;
}
__device__ __forceinline__ float2 lds64(uint32_t addr) {
    float2 v;
    asm volatile("ld.shared.v2.f32 {%0,%1}, [%2];" : "=f"(v.x), "=f"(v.y) : "r"(addr));
    return v;
}
__device__ __forceinline__ void cpa16(uint32_t dst, const float* src) {
    asm volatile("cp.async.cg.shared.global [%0], [%1], 16;" :: "r"(dst), "l"(src));
}
#define CPA_COMMIT() asm volatile("cp.async.commit_group;" ::: "memory")
#define CPA_WAIT1()  asm volatile("cp.async.wait_group 1;"  ::: "memory")
#define CPA_WAIT0()  asm volatile("cp.async.wait_group 0;"  ::: "memory")
#define SWZ(b) ((b) ^ (((b) >> 3) & 0x70))

__device__ __forceinline__ void mma_tf32(float* d, const uint32_t* a, uint32_t b0, uint32_t b1) {
    asm volatile(
        "mma.sync.aligned.m16n8k8.row.col.f32.tf32.tf32.f32 "
        "{%0,%1,%2,%3}, {%4,%5,%6,%7}, {%8,%9}, {%0,%1,%2,%3};"
        : "+f"(d[0]), "+f"(d[1]), "+f"(d[2]), "+f"(d[3])
        : "r"(a[0]), "r"(a[1]), "r"(a[2]), "r"(a[3]), "r"(b0), "r"(b1));
}

// -------------------- weight transpose + tf32 round (once per launch) --------------------
__global__ void transpose_tf32(const float* __restrict__ W, float* __restrict__ WT,
                               int K, int N)
{
    __shared__ float t[32][33];
    const int n0 = blockIdx.x * 32, k0 = blockIdx.y * 32;
    const int tx = threadIdx.x, ty = threadIdx.y;   // 32 x 8
    #pragma unroll
    for (int r = 0; r < 32; r += 8)
        t[ty + r][tx] = W[(size_t)(k0 + ty + r) * N + n0 + tx];
    __syncthreads();
    #pragma unroll
    for (int r = 0; r < 32; r += 8)
        WT[(size_t)(n0 + ty + r) * K + k0 + tx] = ftf32(t[tx][ty + r]);
}

// -------------------- LayerNorm --------------------
__global__ void layernorm_kernel(const float* __restrict__ x,
                                 const float* __restrict__ g,
                                 const float* __restrict__ be,
                                 float* __restrict__ y)
{
    int row = blockIdx.x;
    int tid = threadIdx.x;
    const float* xr = x + (size_t)row * Dd_;
    float4 v = *(const float4*)(xr + tid * 4);

    __shared__ float red[8];
    __shared__ float s_mu, s_inv;

    float s = v.x + v.y + v.z + v.w;
    #pragma unroll
    for (int o = 16; o > 0; o >>= 1) s += __shfl_xor_sync(0xffffffffu, s, o);
    if ((tid & 31) == 0) red[tid >> 5] = s;
    __syncthreads();
    if (tid == 0) {
        float t = 0.f;
        #pragma unroll
        for (int i = 0; i < 8; i++) t += red[i];
        s_mu = t * (1.0f / Dd_);
    }
    __syncthreads();
    float mu = s_mu;
    float dx = v.x - mu, dy = v.y - mu, dz = v.z - mu, dw = v.w - mu;
    float q = dx*dx + dy*dy + dz*dz + dw*dw;
    #pragma unroll
    for (int o = 16; o > 0; o >>= 1) q += __shfl_xor_sync(0xffffffffu, q, o);
    if ((tid & 31) == 0) red[tid >> 5] = q;
    __syncthreads();
    if (tid == 0) {
        float t = 0.f;
        #pragma unroll
        for (int i = 0; i < 8; i++) t += red[i];
        s_inv = rsqrtf(t * (1.0f / Dd_) + 1e-5f);
    }
    __syncthreads();
    float inv = s_inv;
    int c = tid * 4;
    float* yr = y + (size_t)row * Dd_;
    yr[c + 0] = dx * inv * g[c + 0] + be[c + 0];
    yr[c + 1] = dy * inv * g[c + 1] + be[c + 1];
    yr[c + 2] = dz * inv * g[c + 2] + be[c + 2];
    yr[c + 3] = dw * inv * g[c + 3] + be[c + 3];
}

// -------------------- tf32 mma GEMM, cp.async 3-stage ---------------------------------
// C = A(MxK) @ WT^T + bias [+res] [gelu], WT is [N][K] row-major (pre-rounded tf32).
// CTA tile 128x128, BK=32, 256 threads (8 warps, 4x2), warp tile 32x64.
#define GM_STAGE 32768
#define GM_SMEM  (3 * GM_STAGE + 1024)
__global__ __launch_bounds__(256)
void gemm_mma(const float* __restrict__ A, const float* __restrict__ WT,
              const float* __restrict__ bias, const float* __restrict__ res,
              float* __restrict__ C, int Nc, int Kd, int dogelu)
{
    extern __shared__ float dyns[];
    const uint32_t sbase = (smem_u32(dyns) + 1023u) & ~1023u;

    const int tid  = threadIdx.x;
    const int lane = tid & 31, wid = tid >> 5;
    const int gid  = lane >> 2, qd = lane & 3;
    const int wm   = (wid >> 1) * 32;
    const int wn   = (wid & 1) * 64;
    const int n0   = blockIdx.x * 128;
    const int m0   = blockIdx.y * 128;

    float d[2][8][4];
    #pragma unroll
    for (int mt = 0; mt < 2; mt++)
        #pragma unroll
        for (int nt = 0; nt < 8; nt++)
            #pragma unroll
            for (int e = 0; e < 4; e++) d[mt][nt][e] = 0.f;

    const int nsteps = Kd >> 5;
    const float* Abase = A  + (size_t)m0 * Kd;
    const float* Bbase = WT + (size_t)n0 * Kd;

    // issue cp.async for stage kstep into slot s, then commit
    auto cpa_tile = [&](int kstep, int s) {
        const int k0 = kstep * 32;
        const uint32_t aA = sbase + s * GM_STAGE;
        const uint32_t bA = aA + 16384u;
        #pragma unroll
        for (int p = 0; p < 4; p++) {
            int task = p * 256 + tid;
            int r = task >> 3, c = task & 7;
            cpa16(aA + SWZ((uint32_t)(r * 128 + c * 16)), Abase + (size_t)r * Kd + k0 + c * 4);
        }
        #pragma unroll
        for (int p = 0; p < 4; p++) {
            int task = p * 256 + tid;
            int r = task >> 3, c = task & 7;
            cpa16(bA + SWZ((uint32_t)(r * 128 + c * 16)), Bbase + (size_t)r * Kd + k0 + c * 4);
        }
        CPA_COMMIT();
    };

    cpa_tile(0, 0);
    cpa_tile(1, 1);

    for (int i = 0; i < nsteps; i++) {
        const int s = i % 3;
        if (i == nsteps - 1) { CPA_WAIT0(); } else { CPA_WAIT1(); }
        __syncthreads();
        if (i + 2 < nsteps) cpa_tile(i + 2, (i + 2) % 3);

        const uint32_t aA = sbase + s * GM_STAGE;
        const uint32_t bA = aA + 16384u;
        #pragma unroll
        for (int ks = 0; ks < 4; ks++) {
            uint32_t afr[2][4];
            #pragma unroll
            for (int mt = 0; mt < 2; mt++) {
                int r = wm + mt * 16 + gid;
                float2 lo = lds64(aA + SWZ((uint32_t)(r * 128 + ks * 32 + qd * 8)));
                float2 hi = lds64(aA + SWZ((uint32_t)((r + 8) * 128 + ks * 32 + qd * 8)));
                afr[mt][0] = __float_as_uint(lo.x);
                afr[mt][1] = __float_as_uint(hi.x);
                afr[mt][2] = __float_as_uint(lo.y);
                afr[mt][3] = __float_as_uint(hi.y);
            }
            #pragma unroll
            for (int nt = 0; nt < 8; nt++) {
                int n = wn + nt * 8 + gid;
                float2 bf = lds64(bA + SWZ((uint32_t)(n * 128 + ks * 32 + qd * 8)));
                uint32_t b0 = __float_as_uint(bf.x);
                uint32_t b1 = __float_as_uint(bf.y);
                mma_tf32(d[0][nt], afr[0], b0, b1);
                mma_tf32(d[1][nt], afr[1], b0, b1);
            }
        }
    }

    // ---- epilogue: bias [+res] [gelu], float2 stores ----
    #pragma unroll
    for (int mt = 0; mt < 2; mt++) {
        #pragma unroll
        for (int nt = 0; nt < 8; nt++) {
            const int r0  = m0 + wm + mt * 16 + gid;
            const int col = n0 + wn + nt * 8 + qd * 2;
            float2 b2 = *(const float2*)(bias + col);
            #pragma unroll
            for (int half = 0; half < 2; half++) {
                const int row = r0 + half * 8;
                float ox = d[mt][nt][half * 2 + 0] + b2.x;
                float oy = d[mt][nt][half * 2 + 1] + b2.y;
                if (res) {
                    float2 r2 = *(const float2*)(res + (size_t)row * Nc + col);
                    ox += r2.x; oy += r2.y;
                }
                if (dogelu) {
                    ox = 0.5f * ox * (1.0f + erff(ox * 0.7071067811865475f));
                    oy = 0.5f * oy * (1.0f + erff(oy * 0.7071067811865475f));
                }
                float2 o2; o2.x = ox; o2.y = oy;
                *(float2*)(C + (size_t)row * Nc + col) = o2;
            }
        }
    }
}

// -------------------- RoPE --------------------
__global__ void rope_kernel(float* __restrict__ qkv,
                            const float* __restrict__ rc,
                            const float* __restrict__ rs)
{
    int idx = blockIdx.x * blockDim.x + threadIdx.x;
    int total = 2 * NT_ * Hh_ * (HD_ / 2);
    if (idx >= total) return;
    int t = idx & 1;
    int r = idx >> 1;
    int pair = r & 31;  r >>= 5;
    int h = r & 15;     r >>= 4;
    int s = r % Ss_;
    int b = r / Ss_;
    float* base = qkv + ((size_t)(b * Ss_ + s)) * (3 * Dd_) + t * Dd_ + h * HD_ + pair * 2;
    float c  = rc[s * 32 + pair];
    float sn = rs[s * 32 + pair];
    float e = base[0], o = base[1];
    base[0] = e * c - o * sn;
    base[1] = e * sn + o * c;
}

// -------------------- tf32 mma flash attention --------------------
#define FA2_PAD  68
#define FA2_SMEM (2 * 64 * FA2_PAD * 4)   // 34,816 B
__global__ __launch_bounds__(128)
void flash_attn_tc(const float* __restrict__ qkv, float* __restrict__ out)
{
    extern __shared__ float sm2[];
    float* Ks = sm2;
    float* Vs = sm2 + 64 * FA2_PAD;

    const int qb = (int)gridDim.x - 1 - (int)blockIdx.x;
    const int q0 = qb * 64;
    const int bh = blockIdx.y;
    const int b = bh >> 4, h = bh & 15;
    const int tid = threadIdx.x, lane = tid & 31, wid = tid >> 5;
    const int gid = lane >> 2, qd = lane & 3;
    const int wr = wid * 16;
    const size_t rs3 = 3 * Dd_;

    const float* qbase = qkv + (size_t)(b * Ss_ + q0) * rs3 + h * HD_;
    const float* kbase = qkv + (size_t)(b * Ss_) * rs3 + Dd_ + h * HD_;
    const float* vbase = qkv + (size_t)(b * Ss_) * rs3 + 2 * Dd_ + h * HD_;

    #pragma unroll
    for (int p = 0; p < 8; p++) {
        int L = p * 128 + tid;
        int r = L >> 4, d4 = (L & 15) * 4;
        float4 v = *(const float4*)(qbase + (size_t)r * rs3 + d4);
        float4 w;
        w.x = ftf32(v.x) * 0.125f; w.y = ftf32(v.y) * 0.125f;
        w.z = ftf32(v.z) * 0.125f; w.w = ftf32(v.w) * 0.125f;
        *(float4*)(Ks + r * FA2_PAD + d4) = w;
    }
    __syncthreads();

    uint32_t qf[8][4];
    #pragma unroll
    for (int kt = 0; kt < 8; kt++) {
        float2 lo = *(const float2*)(Ks + (wr + gid) * FA2_PAD + kt * 8 + qd * 2);
        float2 hi = *(const float2*)(Ks + (wr + gid + 8) * FA2_PAD + kt * 8 + qd * 2);
        qf[kt][0] = __float_as_uint(lo.x);
        qf[kt][1] = __float_as_uint(hi.x);
        qf[kt][2] = __float_as_uint(lo.y);
        qf[kt][3] = __float_as_uint(hi.y);
    }
    __syncthreads();

    float of[8][4];
    #pragma unroll
    for (int nt = 0; nt < 8; nt++)
        #pragma unroll
        for (int e = 0; e < 4; e++) of[nt][e] = 0.f;
    float m1 = -1e30f, m2 = -1e30f, l1 = 0.f, l2 = 0.f;

    const int aq1 = q0 + wr + gid;

    for (int t = 0; t <= qb; t++) {
        const int k0 = t * 64;
        #pragma unroll
        for (int p = 0; p < 8; p++) {
            int L = p * 128 + tid;
            int r = L >> 4, d4 = (L & 15) * 4;
            float4 kv = *(const float4*)(kbase + (size_t)(k0 + r) * rs3 + d4);
            float4 kw;
            kw.x = ftf32(kv.x); kw.y = ftf32(kv.y); kw.z = ftf32(kv.z); kw.w = ftf32(kv.w);
            *(float4*)(Ks + r * FA2_PAD + d4) = kw;
            float4 vv = *(const float4*)(vbase + (size_t)(k0 + r) * rs3 + d4);
            float4 vw;
            vw.x = ftf32(vv.x); vw.y = ftf32(vv.y); vw.z = ftf32(vv.z); vw.w = ftf32(vv.w);
            *(float4*)(Vs + r * FA2_PAD + d4) = vw;
        }
        __syncthreads();

        float sf[8][4];
        #pragma unroll
        for (int nt = 0; nt < 8; nt++)
            #pragma unroll
            for (int e = 0; e < 4; e++) sf[nt][e] = 0.f;

        #pragma unroll
        for (int kt = 0; kt < 8; kt++) {
            #pragma unroll
            for (int nt = 0; nt < 8; nt++) {
                float2 bk = *(const float2*)(Ks + (nt * 8 + gid) * FA2_PAD + kt * 8 + qd * 2);
                mma_tf32(sf[nt], qf[kt], __float_as_uint(bk.x), __float_as_uint(bk.y));
            }
        }

        if (t == qb) {
            #pragma unroll
            for (int nt = 0; nt < 8; nt++) {
                int c = k0 + nt * 8 + qd * 2;
                if (c     > aq1)     sf[nt][0] = -1e30f;
                if (c + 1 > aq1)     sf[nt][1] = -1e30f;
                if (c     > aq1 + 8) sf[nt][2] = -1e30f;
                if (c + 1 > aq1 + 8) sf[nt][3] = -1e30f;
            }
        }

        float mx1 = -1e30f, mx2 = -1e30f;
        #pragma unroll
        for (int nt = 0; nt < 8; nt++) {
            mx1 = fmaxf(mx1, fmaxf(sf[nt][0], sf[nt][1]));
            mx2 = fmaxf(mx2, fmaxf(sf[nt][2], sf[nt][3]));
        }
        mx1 = fmaxf(mx1, __shfl_xor_sync(0xffffffffu, mx1, 1));
        mx1 = fmaxf(mx1, __shfl_xor_sync(0xffffffffu, mx1, 2));
        mx2 = fmaxf(mx2, __shfl_xor_sync(0xffffffffu, mx2, 1));
        mx2 = fmaxf(mx2, __shfl_xor_sync(0xffffffffu, mx2, 2));
        float nm1 = fmaxf(m1, mx1), nm2 = fmaxf(m2, mx2);
        float f1 = __expf(m1 - nm1), f2v = __expf(m2 - nm2);
        m1 = nm1; m2 = nm2;
        float s1 = 0.f, s2 = 0.f;
        #pragma unroll
        for (int nt = 0; nt < 8; nt++) {
            sf[nt][0] = __expf(sf[nt][0] - nm1); s1 += sf[nt][0];
            sf[nt][1] = __expf(sf[nt][1] - nm1); s1 += sf[nt][1];
            sf[nt][2] = __expf(sf[nt][2] - nm2); s2 += sf[nt][2];
            sf[nt][3] = __expf(sf[nt][3] - nm2); s2 += sf[nt][3];
        }
        s1 += __shfl_xor_sync(0xffffffffu, s1, 1);
        s1 += __shfl_xor_sync(0xffffffffu, s1, 2);
        s2 += __shfl_xor_sync(0xffffffffu, s2, 1);
        s2 += __shfl_xor_sync(0xffffffffu, s2, 2);
        l1 = l1 * f1 + s1;
        l2 = l2 * f2v + s2;
        #pragma unroll
        for (int nt = 0; nt < 8; nt++) {
            of[nt][0] *= f1;  of[nt][1] *= f1;
            of[nt][2] *= f2v; of[nt][3] *= f2v;
        }

        #pragma unroll
        for (int kt = 0; kt < 8; kt++) {
            uint32_t af[4] = { __float_as_uint(sf[kt][0]), __float_as_uint(sf[kt][2]),
                               __float_as_uint(sf[kt][1]), __float_as_uint(sf[kt][3]) };
            const float* vrow0 = Vs + (kt * 8 + qd * 2) * FA2_PAD;
            const float* vrow1 = vrow0 + FA2_PAD;
            #pragma unroll
            for (int nt = 0; nt < 8; nt++) {
                uint32_t b0 = __float_as_uint(vrow0[nt * 8 + gid]);
                uint32_t b1 = __float_as_uint(vrow1[nt * 8 + gid]);
                mma_tf32(of[nt], af, b0, b1);
            }
        }
        __syncthreads();
    }

    float inv1 = 1.0f / l1, inv2 = 1.0f / l2;
    float* o1base = out + (size_t)(b * Ss_ + aq1) * Dd_ + h * HD_;
    float* o2base = out + (size_t)(b * Ss_ + aq1 + 8) * Dd_ + h * HD_;
    #pragma unroll
    for (int nt = 0; nt < 8; nt++) {
        float2 o1; o1.x = of[nt][0] * inv1; o1.y = of[nt][1] * inv1;
        float2 o2; o2.x = of[nt][2] * inv2; o2.y = of[nt][3] * inv2;
        *(float2*)(o1base + nt * 8 + qd * 2) = o1;
        *(float2*)(o2base + nt * 8 + qd * 2) = o2;
    }
}

// -------------------- Cross-attention (64 keys) --------------------
__global__ __launch_bounds__(64)
void cross_attn_kernel(const float* __restrict__ qc, const float* __restrict__ kc,
                       const float* __restrict__ vc, float* __restrict__ out)
{
    int qidx = blockIdx.x;
    int bh   = blockIdx.y;
    int b = bh / Hh_, h = bh % Hh_;
    int tid = threadIdx.x;

    __shared__ float sq[HD_];
    __shared__ float p[MEM_];
    __shared__ float red[2];

    const float* qrow = qc + ((size_t)(b * Ss_ + qidx)) * Dd_ + h * HD_;
    sq[tid] = qrow[tid];
    __syncthreads();

    const float* krow = kc + ((size_t)(b * MEM_ + tid)) * Dd_ + h * HD_;
    float s = 0.f;
    #pragma unroll
    for (int d = 0; d < HD_; d += 4) {
        float4 k4 = *(const float4*)(krow + d);
        s = fmaf(sq[d + 0], k4.x, s);
        s = fmaf(sq[d + 1], k4.y, s);
        s = fmaf(sq[d + 2], k4.z, s);
        s = fmaf(sq[d + 3], k4.w, s);
    }
    s *= 0.125f;

    float m = s;
    #pragma unroll
    for (int o = 16; o > 0; o >>= 1) m = fmaxf(m, __shfl_xor_sync(0xffffffffu, m, o));
    if ((tid & 31) == 0) red[tid >> 5] = m;
    __syncthreads();
    float gm = fmaxf(red[0], red[1]);
    float pv = expf(s - gm);
    p[tid] = pv;
    float su = pv;
    #pragma unroll
    for (int o = 16; o > 0; o >>= 1) su += __shfl_xor_sync(0xffffffffu, su, o);
    __syncthreads();
    if ((tid & 31) == 0) red[tid >> 5] = su;
    __syncthreads();
    float gl = red[0] + red[1];

    const float* vbase = vc + ((size_t)(b * MEM_)) * Dd_ + h * HD_ + tid;
    float a = 0.f;
    #pragma unroll 4
    for (int j = 0; j < MEM_; j++)
        a = fmaf(p[j], vbase[(size_t)j * Dd_], a);

    out[((size_t)(b * Ss_ + qidx)) * Dd_ + h * HD_ + tid] = a / gl;
}

// -------------------- launch --------------------
extern "C" void kernel_launch(void* const* d_in, const int* in_sizes, int n_in,
                              void* d_out, int out_size)
{
    const float* tgt      = (const float*)d_in[0];
    const float* memory   = (const float*)d_in[1];
    const float* rope_cos = (const float*)d_in[2];
    const float* rope_sin = (const float*)d_in[3];
    const float* W_qkv    = (const float*)d_in[4];
    const float* b_qkv    = (const float*)d_in[5];
    const float* W_o      = (const float*)d_in[6];
    const float* b_o      = (const float*)d_in[7];
    const float* Wq_c     = (const float*)d_in[8];
    const float* bq_c     = (const float*)d_in[9];
    const float* Wk_c     = (const float*)d_in[10];
    const float* bk_c     = (const float*)d_in[11];
    const float* Wv_c     = (const float*)d_in[12];
    const float* bv_c     = (const float*)d_in[13];
    const float* W_co     = (const float*)d_in[14];
    const float* b_co     = (const float*)d_in[15];
    const float* W1       = (const float*)d_in[16];
    const float* b1       = (const float*)d_in[17];
    const float* W2       = (const float*)d_in[18];
    const float* b2       = (const float*)d_in[19];
    const float* g1       = (const float*)d_in[20];
    const float* be1      = (const float*)d_in[21];
    const float* g2       = (const float*)d_in[22];
    const float* be2      = (const float*)d_in[23];
    const float* g3       = (const float*)d_in[24];
    const float* be3      = (const float*)d_in[25];
    float* out = (float*)d_out;

    float *x, *qkv, *sa, *tgtb, *kc, *vc, *ffn, *wT;
    cudaGetSymbolAddress((void**)&x,    g_x);
    cudaGetSymbolAddress((void**)&qkv,  g_qkv);
    cudaGetSymbolAddress((void**)&sa,   g_sa);
    cudaGetSymbolAddress((void**)&tgtb, g_tgt);
    cudaGetSymbolAddress((void**)&kc,   g_kc);
    cudaGetSymbolAddress((void**)&vc,   g_vc);
    cudaGetSymbolAddress((void**)&ffn,  g_ffn);
    cudaGetSymbolAddress((void**)&wT,   g_wT);

    cudaFuncSetAttribute(flash_attn_tc,
                         cudaFuncAttributeMaxDynamicSharedMemorySize, FA2_SMEM);
    cudaFuncSetAttribute(gemm_mma,
                         cudaFuncAttributeMaxDynamicSharedMemorySize, GM_SMEM);

    // 0) pre-transpose + tf32-round all weights (loop-invariant)
    {
        dim3 thr(32, 8);
        transpose_tf32<<<dim3(3 * Dd_ / 32, Dd_ / 32), thr>>>(W_qkv, wT + WT_QKV, Dd_, 3 * Dd_);
        transpose_tf32<<<dim3(Dd_ / 32, Dd_ / 32), thr>>>(W_o,  wT + WT_O,  Dd_, Dd_);
        transpose_tf32<<<dim3(Dd_ / 32, Dd_ / 32), thr>>>(Wq_c, wT + WT_QC, Dd_, Dd_);
        transpose_tf32<<<dim3(Dd_ / 32, Dd_ / 32), thr>>>(Wk_c, wT + WT_KC, Dd_, Dd_);
        transpose_tf32<<<dim3(Dd_ / 32, Dd_ / 32), thr>>>(Wv_c, wT + WT_VC, Dd_, Dd_);
        transpose_tf32<<<dim3(Dd_ / 32, Dd_ / 32), thr>>>(W_co, wT + WT_CO, Dd_, Dd_);
        transpose_tf32<<<dim3(FF_ / 32, Dd_ / 32), thr>>>(W1, wT + WT_W1, Dd_, FF_);
        transpose_tf32<<<dim3(Dd_ / 32, FF_ / 32), thr>>>(W2, wT + WT_W2, FF_, Dd_);
    }

    // 1) x = LN1(tgt)
    layernorm_kernel<<<NT_, 256>>>(tgt, g1, be1, x);
    // 2) qkv = x @ W_qkv + b
    gemm_mma<<<dim3(3 * Dd_ / 128, NT_ / 128), 256, GM_SMEM>>>(x, wT + WT_QKV, b_qkv, nullptr, qkv, 3 * Dd_, Dd_, 0);
    // 3) RoPE on q,k
    {
        int total = 2 * NT_ * Hh_ * (HD_ / 2);
        rope_kernel<<<(total + 255) / 256, 256>>>(qkv, rope_cos, rope_sin);
    }
    // 4) causal self-attention (tf32 mma flash) -> sa
    flash_attn_tc<<<dim3(Ss_ / 64, Bb_ * Hh_), 128, FA2_SMEM>>>(qkv, sa);
    // 5) tgtb = tgt + sa @ W_o + b_o
    gemm_mma<<<dim3(Dd_ / 128, NT_ / 128), 256, GM_SMEM>>>(sa, wT + WT_O, b_o, tgt, tgtb, Dd_, Dd_, 0);
    // 6) x = LN2(tgtb)
    layernorm_kernel<<<NT_, 256>>>(tgtb, g2, be2, x);
    // 7) qc = x @ Wq_c (reuse qkv buffer)
    gemm_mma<<<dim3(Dd_ / 128, NT_ / 128), 256, GM_SMEM>>>(x, wT + WT_QC, bq_c, nullptr, qkv, Dd_, Dd_, 0);
    // 8) kc/vc = memory @ Wk_c / Wv_c
    gemm_mma<<<dim3(Dd_ / 128, 1), 256, GM_SMEM>>>(memory, wT + WT_KC, bk_c, nullptr, kc, Dd_, Dd_, 0);
    gemm_mma<<<dim3(Dd_ / 128, 1), 256, GM_SMEM>>>(memory, wT + WT_VC, bv_c, nullptr, vc, Dd_, Dd_, 0);
    // 9) cross-attention -> sa (reuse)
    cross_attn_kernel<<<dim3(Ss_, Bb_ * Hh_), 64>>>(qkv, kc, vc, sa);
    // 10) tgtb += sa @ W_co + b_co
    gemm_mma<<<dim3(Dd_ / 128, NT_ / 128), 256, GM_SMEM>>>(sa, wT + WT_CO, b_co, tgtb, tgtb, Dd_, Dd_, 0);
    // 11) x = LN3(tgtb)
    layernorm_kernel<<<NT_, 256>>>(tgtb, g3, be3, x);
    // 12) ffn = gelu(x @ W1 + b1)
    gemm_mma<<<dim3(FF_ / 128, NT_ / 128), 256, GM_SMEM>>>(x, wT + WT_W1, b1, nullptr, ffn, FF_, Dd_, 1);
    // 13) out = tgtb + ffn @ W2 + b2
    gemm_mma<<<dim3(Dd_ / 128, NT_ / 128), 256, GM_SMEM>>>(ffn, wT + WT_W2, b2, tgtb, out, Dd_, FF_, 0);
}

// round 7
// speedup vs baseline: 6.8035x; 1.5511x over previous
#include <cuda_runtime.h>
#include <cuda_fp16.h>
#include <cstdint>
#include <math.h>

// Problem constants
#define Bb_  2
#define Ss_  2048
#define MEM_ 64
#define Dd_  1024
#define Hh_  16
#define FF_  4096
#define HD_  64
#define NT_  (Bb_ * Ss_)   // 4096 tokens

// -------------------- scratch (device globals; no runtime alloc) --------------------
__device__ float  g_qkv [(size_t)NT_ * 3 * Dd_];
__device__ float  g_tgt [(size_t)NT_ * Dd_];
__device__ float  g_kc  [(size_t)Bb_ * MEM_ * Dd_];
__device__ float  g_vc  [(size_t)Bb_ * MEM_ * Dd_];
__device__ __half g_wTh [(size_t)16 * 1024 * 1024];  // transposed fp16 weights
__device__ __half g_xh  [(size_t)NT_ * Dd_];
__device__ __half g_sah [(size_t)NT_ * Dd_];
__device__ __half g_ffnh[(size_t)NT_ * FF_];
__device__ __half g_memh[(size_t)Bb_ * MEM_ * Dd_];

// offsets into g_wTh (half elements)
#define WT_QKV 0u
#define WT_O   (3u * 1024u * 1024u)
#define WT_QC  (4u * 1024u * 1024u)
#define WT_KC  (5u * 1024u * 1024u)
#define WT_VC  (6u * 1024u * 1024u)
#define WT_CO  (7u * 1024u * 1024u)
#define WT_W1  (8u * 1024u * 1024u)
#define WT_W2  (12u * 1024u * 1024u)

// -------------------- helpers --------------------
__device__ __forceinline__ uint32_t smem_u32(const void* p) {
    uint32_t a;
    asm("{ .reg .u64 t; cvta.to.shared.u64 t, %1; cvt.u32.u64 %0, t; }" : "=r"(a) : "l"(p));
    return a;
}
__device__ __forceinline__ float ftf32(float x) {
    float y;
    asm("cvt.rna.tf32.f32 %0, %1;" : "=f"(y) : "f"(x));
    return y;
}
__device__ __forceinline__ float2 lds64(uint32_t addr) {
    float2 v;
    asm volatile("ld.shared.v2.f32 {%0,%1}, [%2];" : "=f"(v.x), "=f"(v.y) : "r"(addr));
    return v;
}
__device__ __forceinline__ uint2 lds64u(uint32_t addr) {
    uint2 v;
    asm volatile("ld.shared.v2.u32 {%0,%1}, [%2];" : "=r"(v.x), "=r"(v.y) : "r"(addr));
    return v;
}
__device__ __forceinline__ void cpa16(uint32_t dst, const void* src) {
    asm volatile("cp.async.cg.shared.global [%0], [%1], 16;" :: "r"(dst), "l"(src));
}
#define CPA_COMMIT() asm volatile("cp.async.commit_group;" ::: "memory")
#define CPA_WAIT1()  asm volatile("cp.async.wait_group 1;"  ::: "memory")
#define CPA_WAIT0()  asm volatile("cp.async.wait_group 0;"  ::: "memory")
#define SWZ(b) ((b) ^ (((b) >> 3) & 0x70))

__device__ __forceinline__ void mma_tf32(float* d, const uint32_t* a, uint32_t b0, uint32_t b1) {
    asm volatile(
        "mma.sync.aligned.m16n8k8.row.col.f32.tf32.tf32.f32 "
        "{%0,%1,%2,%3}, {%4,%5,%6,%7}, {%8,%9}, {%0,%1,%2,%3};"
        : "+f"(d[0]), "+f"(d[1]), "+f"(d[2]), "+f"(d[3])
        : "r"(a[0]), "r"(a[1]), "r"(a[2]), "r"(a[3]), "r"(b0), "r"(b1));
}
__device__ __forceinline__ void mma_f16(float* d, uint32_t a0, uint32_t a1, uint32_t a2,
                                        uint32_t a3, uint32_t b0, uint32_t b1) {
    asm volatile(
        "mma.sync.aligned.m16n8k16.row.col.f32.f16.f16.f32 "
        "{%0,%1,%2,%3}, {%4,%5,%6,%7}, {%8,%9}, {%0,%1,%2,%3};"
        : "+f"(d[0]), "+f"(d[1]), "+f"(d[2]), "+f"(d[3])
        : "r"(a0), "r"(a1), "r"(a2), "r"(a3), "r"(b0), "r"(b1));
}

// -------------------- weight transpose + fp16 convert (once per launch) --------------------
__global__ void transpose_h(const float* __restrict__ W, __half* __restrict__ WT,
                            int K, int N)
{
    __shared__ float t[32][33];
    const int n0 = blockIdx.x * 32, k0 = blockIdx.y * 32;
    const int tx = threadIdx.x, ty = threadIdx.y;   // 32 x 8
    #pragma unroll
    for (int r = 0; r < 32; r += 8)
        t[ty + r][tx] = W[(size_t)(k0 + ty + r) * N + n0 + tx];
    __syncthreads();
    #pragma unroll
    for (int r = 0; r < 32; r += 8)
        WT[(size_t)(n0 + ty + r) * K + k0 + tx] = __float2half_rn(t[tx][ty + r]);
}

// -------------------- fp32 -> fp16 convert (memory tensor) --------------------
__global__ void conv_h(const float* __restrict__ x, __half* __restrict__ y, int n)
{
    int i = blockIdx.x * blockDim.x + threadIdx.x;
    if (i < n) y[i] = __float2half_rn(x[i]);
}

// -------------------- LayerNorm (fp32 in, fp16 out) --------------------
__global__ void layernorm_kernel(const float* __restrict__ x,
                                 const float* __restrict__ g,
                                 const float* __restrict__ be,
                                 __half* __restrict__ y)
{
    int row = blockIdx.x;
    int tid = threadIdx.x;
    const float* xr = x + (size_t)row * Dd_;
    float4 v = *(const float4*)(xr + tid * 4);

    __shared__ float red[8];
    __shared__ float s_mu, s_inv;

    float s = v.x + v.y + v.z + v.w;
    #pragma unroll
    for (int o = 16; o > 0; o >>= 1) s += __shfl_xor_sync(0xffffffffu, s, o);
    if ((tid & 31) == 0) red[tid >> 5] = s;
    __syncthreads();
    if (tid == 0) {
        float t = 0.f;
        #pragma unroll
        for (int i = 0; i < 8; i++) t += red[i];
        s_mu = t * (1.0f / Dd_);
    }
    __syncthreads();
    float mu = s_mu;
    float dx = v.x - mu, dy = v.y - mu, dz = v.z - mu, dw = v.w - mu;
    float q = dx*dx + dy*dy + dz*dz + dw*dw;
    #pragma unroll
    for (int o = 16; o > 0; o >>= 1) q += __shfl_xor_sync(0xffffffffu, q, o);
    if ((tid & 31) == 0) red[tid >> 5] = q;
    __syncthreads();
    if (tid == 0) {
        float t = 0.f;
        #pragma unroll
        for (int i = 0; i < 8; i++) t += red[i];
        s_inv = rsqrtf(t * (1.0f / Dd_) + 1e-5f);
    }
    __syncthreads();
    float inv = s_inv;
    int c = tid * 4;
    __half* yr = y + (size_t)row * Dd_;
    float o0 = dx * inv * g[c + 0] + be[c + 0];
    float o1 = dy * inv * g[c + 1] + be[c + 1];
    float o2 = dz * inv * g[c + 2] + be[c + 2];
    float o3 = dw * inv * g[c + 3] + be[c + 3];
    ((__half2*)(yr + c))[0] = __floats2half2_rn(o0, o1);
    ((__half2*)(yr + c))[1] = __floats2half2_rn(o2, o3);
}

// -------------------- fp16 mma GEMM, cp.async 3-stage ---------------------------------
// C = A(MxK,fp16) @ WT^T + bias [+res] [gelu]; WT fp16 [N][K]. Out fp32 C or fp16 Ch.
// CTA tile 128x128, BK=64 (128B rows), 256 threads (8 warps, 4x2), warp tile 32x64.
#define GM_STAGE 32768
#define GM_SMEM  (3 * GM_STAGE + 1024)
__global__ __launch_bounds__(256)
void gemm_mma(const __half* __restrict__ A, const __half* __restrict__ WT,
              const float* __restrict__ bias, const float* __restrict__ res,
              float* __restrict__ C, __half* __restrict__ Ch,
              int Nc, int Kd, int dogelu)
{
    extern __shared__ float dyns[];
    const uint32_t sbase = (smem_u32(dyns) + 1023u) & ~1023u;

    const int tid  = threadIdx.x;
    const int lane = tid & 31, wid = tid >> 5;
    const int gid  = lane >> 2, qd = lane & 3;
    const int wm   = (wid >> 1) * 32;
    const int wn   = (wid & 1) * 64;
    const int n0   = blockIdx.x * 128;
    const int m0   = blockIdx.y * 128;

    float d[2][8][4];
    #pragma unroll
    for (int mt = 0; mt < 2; mt++)
        #pragma unroll
        for (int nt = 0; nt < 8; nt++)
            #pragma unroll
            for (int e = 0; e < 4; e++) d[mt][nt][e] = 0.f;

    const int nsteps = Kd >> 6;   // BK = 64
    const __half* Abase = A  + (size_t)m0 * Kd;
    const __half* Bbase = WT + (size_t)n0 * Kd;

    // issue cp.async for stage kstep into slot s, then commit
    auto cpa_tile = [&](int kstep, int s) {
        const int k0 = kstep * 64;
        const uint32_t aA = sbase + s * GM_STAGE;
        const uint32_t bA = aA + 16384u;
        #pragma unroll
        for (int p = 0; p < 4; p++) {
            int task = p * 256 + tid;
            int r = task >> 3, c = task & 7;
            cpa16(aA + SWZ((uint32_t)(r * 128 + c * 16)), Abase + (size_t)r * Kd + k0 + c * 8);
        }
        #pragma unroll
        for (int p = 0; p < 4; p++) {
            int task = p * 256 + tid;
            int r = task >> 3, c = task & 7;
            cpa16(bA + SWZ((uint32_t)(r * 128 + c * 16)), Bbase + (size_t)r * Kd + k0 + c * 8);
        }
        CPA_COMMIT();
    };

    cpa_tile(0, 0);
    cpa_tile(1, 1);

    for (int i = 0; i < nsteps; i++) {
        const int s = i % 3;
        if (i == nsteps - 1) { CPA_WAIT0(); } else { CPA_WAIT1(); }
        __syncthreads();
        if (i + 2 < nsteps) cpa_tile(i + 2, (i + 2) % 3);

        const uint32_t aA = sbase + s * GM_STAGE;
        const uint32_t bA = aA + 16384u;
        // 4 k16-groups per 64-wide K chunk; paired-k permutation (phys k 4qd..4qd+3)
        #pragma unroll
        for (int g = 0; g < 4; g++) {
            uint32_t afr[2][4];
            #pragma unroll
            for (int mt = 0; mt < 2; mt++) {
                int r = wm + mt * 16 + gid;
                uint2 lo = lds64u(aA + SWZ((uint32_t)(r * 128 + g * 32 + qd * 8)));
                uint2 hi = lds64u(aA + SWZ((uint32_t)((r + 8) * 128 + g * 32 + qd * 8)));
                afr[mt][0] = lo.x;  // row r,   k 4qd..4qd+1
                afr[mt][1] = hi.x;  // row r+8, k 4qd..4qd+1
                afr[mt][2] = lo.y;  // row r,   k 4qd+2..4qd+3
                afr[mt][3] = hi.y;  // row r+8, k 4qd+2..4qd+3
            }
            #pragma unroll
            for (int nt = 0; nt < 8; nt++) {
                int n = wn + nt * 8 + gid;
                uint2 bf = lds64u(bA + SWZ((uint32_t)(n * 128 + g * 32 + qd * 8)));
                mma_f16(d[0][nt], afr[0][0], afr[0][1], afr[0][2], afr[0][3], bf.x, bf.y);
                mma_f16(d[1][nt], afr[1][0], afr[1][1], afr[1][2], afr[1][3], bf.x, bf.y);
            }
        }
    }

    // ---- epilogue: bias [+res] [gelu]; fp32 or fp16 stores ----
    #pragma unroll
    for (int mt = 0; mt < 2; mt++) {
        #pragma unroll
        for (int nt = 0; nt < 8; nt++) {
            const int r0  = m0 + wm + mt * 16 + gid;
            const int col = n0 + wn + nt * 8 + qd * 2;
            float2 b2 = *(const float2*)(bias + col);
            #pragma unroll
            for (int half_ = 0; half_ < 2; half_++) {
                const int row = r0 + half_ * 8;
                float ox = d[mt][nt][half_ * 2 + 0] + b2.x;
                float oy = d[mt][nt][half_ * 2 + 1] + b2.y;
                if (res) {
                    float2 r2 = *(const float2*)(res + (size_t)row * Nc + col);
                    ox += r2.x; oy += r2.y;
                }
                if (dogelu) {
                    ox = 0.5f * ox * (1.0f + erff(ox * 0.7071067811865475f));
                    oy = 0.5f * oy * (1.0f + erff(oy * 0.7071067811865475f));
                }
                if (Ch) {
                    *(__half2*)(Ch + (size_t)row * Nc + col) = __floats2half2_rn(ox, oy);
                } else {
                    float2 o2; o2.x = ox; o2.y = oy;
                    *(float2*)(C + (size_t)row * Nc + col) = o2;
                }
            }
        }
    }
}

// -------------------- RoPE --------------------
__global__ void rope_kernel(float* __restrict__ qkv,
                            const float* __restrict__ rc,
                            const float* __restrict__ rs)
{
    int idx = blockIdx.x * blockDim.x + threadIdx.x;
    int total = 2 * NT_ * Hh_ * (HD_ / 2);
    if (idx >= total) return;
    int t = idx & 1;
    int r = idx >> 1;
    int pair = r & 31;  r >>= 5;
    int h = r & 15;     r >>= 4;
    int s = r % Ss_;
    int b = r / Ss_;
    float* base = qkv + ((size_t)(b * Ss_ + s)) * (3 * Dd_) + t * Dd_ + h * HD_ + pair * 2;
    float c  = rc[s * 32 + pair];
    float sn = rs[s * 32 + pair];
    float e = base[0], o = base[1];
    base[0] = e * c - o * sn;
    base[1] = e * sn + o * c;
}

// -------------------- tf32 mma flash attention (fp16 output) --------------------
#define FA2_PAD  68
#define FA2_SMEM (2 * 64 * FA2_PAD * 4)   // 34,816 B
__global__ __launch_bounds__(128)
void flash_attn_tc(const float* __restrict__ qkv, __half* __restrict__ out)
{
    extern __shared__ float sm2[];
    float* Ks = sm2;
    float* Vs = sm2 + 64 * FA2_PAD;

    const int qb = (int)gridDim.x - 1 - (int)blockIdx.x;
    const int q0 = qb * 64;
    const int bh = blockIdx.y;
    const int b = bh >> 4, h = bh & 15;
    const int tid = threadIdx.x, lane = tid & 31, wid = tid >> 5;
    const int gid = lane >> 2, qd = lane & 3;
    const int wr = wid * 16;
    const size_t rs3 = 3 * Dd_;

    const float* qbase = qkv + (size_t)(b * Ss_ + q0) * rs3 + h * HD_;
    const float* kbase = qkv + (size_t)(b * Ss_) * rs3 + Dd_ + h * HD_;
    const float* vbase = qkv + (size_t)(b * Ss_) * rs3 + 2 * Dd_ + h * HD_;

    #pragma unroll
    for (int p = 0; p < 8; p++) {
        int L = p * 128 + tid;
        int r = L >> 4, d4 = (L & 15) * 4;
        float4 v = *(const float4*)(qbase + (size_t)r * rs3 + d4);
        float4 w;
        w.x = ftf32(v.x) * 0.125f; w.y = ftf32(v.y) * 0.125f;
        w.z = ftf32(v.z) * 0.125f; w.w = ftf32(v.w) * 0.125f;
        *(float4*)(Ks + r * FA2_PAD + d4) = w;
    }
    __syncthreads();

    uint32_t qf[8][4];
    #pragma unroll
    for (int kt = 0; kt < 8; kt++) {
        float2 lo = *(const float2*)(Ks + (wr + gid) * FA2_PAD + kt * 8 + qd * 2);
        float2 hi = *(const float2*)(Ks + (wr + gid + 8) * FA2_PAD + kt * 8 + qd * 2);
        qf[kt][0] = __float_as_uint(lo.x);
        qf[kt][1] = __float_as_uint(hi.x);
        qf[kt][2] = __float_as_uint(lo.y);
        qf[kt][3] = __float_as_uint(hi.y);
    }
    __syncthreads();

    float of[8][4];
    #pragma unroll
    for (int nt = 0; nt < 8; nt++)
        #pragma unroll
        for (int e = 0; e < 4; e++) of[nt][e] = 0.f;
    float m1 = -1e30f, m2 = -1e30f, l1 = 0.f, l2 = 0.f;

    const int aq1 = q0 + wr + gid;

    for (int t = 0; t <= qb; t++) {
        const int k0 = t * 64;
        #pragma unroll
        for (int p = 0; p < 8; p++) {
            int L = p * 128 + tid;
            int r = L >> 4, d4 = (L & 15) * 4;
            float4 kv = *(const float4*)(kbase + (size_t)(k0 + r) * rs3 + d4);
            float4 kw;
            kw.x = ftf32(kv.x); kw.y = ftf32(kv.y); kw.z = ftf32(kv.z); kw.w = ftf32(kv.w);
            *(float4*)(Ks + r * FA2_PAD + d4) = kw;
            float4 vv = *(const float4*)(vbase + (size_t)(k0 + r) * rs3 + d4);
            float4 vw;
            vw.x = ftf32(vv.x); vw.y = ftf32(vv.y); vw.z = ftf32(vv.z); vw.w = ftf32(vv.w);
            *(float4*)(Vs + r * FA2_PAD + d4) = vw;
        }
        __syncthreads();

        float sf[8][4];
        #pragma unroll
        for (int nt = 0; nt < 8; nt++)
            #pragma unroll
            for (int e = 0; e < 4; e++) sf[nt][e] = 0.f;

        #pragma unroll
        for (int kt = 0; kt < 8; kt++) {
            #pragma unroll
            for (int nt = 0; nt < 8; nt++) {
                float2 bk = *(const float2*)(Ks + (nt * 8 + gid) * FA2_PAD + kt * 8 + qd * 2);
                mma_tf32(sf[nt], qf[kt], __float_as_uint(bk.x), __float_as_uint(bk.y));
            }
        }

        if (t == qb) {
            #pragma unroll
            for (int nt = 0; nt < 8; nt++) {
                int c = k0 + nt * 8 + qd * 2;
                if (c     > aq1)     sf[nt][0] = -1e30f;
                if (c + 1 > aq1)     sf[nt][1] = -1e30f;
                if (c     > aq1 + 8) sf[nt][2] = -1e30f;
                if (c + 1 > aq1 + 8) sf[nt][3] = -1e30f;
            }
        }

        float mx1 = -1e30f, mx2 = -1e30f;
        #pragma unroll
        for (int nt = 0; nt < 8; nt++) {
            mx1 = fmaxf(mx1, fmaxf(sf[nt][0], sf[nt][1]));
            mx2 = fmaxf(mx2, fmaxf(sf[nt][2], sf[nt][3]));
        }
        mx1 = fmaxf(mx1, __shfl_xor_sync(0xffffffffu, mx1, 1));
        mx1 = fmaxf(mx1, __shfl_xor_sync(0xffffffffu, mx1, 2));
        mx2 = fmaxf(mx2, __shfl_xor_sync(0xffffffffu, mx2, 1));
        mx2 = fmaxf(mx2, __shfl_xor_sync(0xffffffffu, mx2, 2));
        float nm1 = fmaxf(m1, mx1), nm2 = fmaxf(m2, mx2);
        float f1 = __expf(m1 - nm1), f2v = __expf(m2 - nm2);
        m1 = nm1; m2 = nm2;
        float s1 = 0.f, s2 = 0.f;
        #pragma unroll
        for (int nt = 0; nt < 8; nt++) {
            sf[nt][0] = __expf(sf[nt][0] - nm1); s1 += sf[nt][0];
            sf[nt][1] = __expf(sf[nt][1] - nm1); s1 += sf[nt][1];
            sf[nt][2] = __expf(sf[nt][2] - nm2); s2 += sf[nt][2];
            sf[nt][3] = __expf(sf[nt][3] - nm2); s2 += sf[nt][3];
        }
        s1 += __shfl_xor_sync(0xffffffffu, s1, 1);
        s1 += __shfl_xor_sync(0xffffffffu, s1, 2);
        s2 += __shfl_xor_sync(0xffffffffu, s2, 1);
        s2 += __shfl_xor_sync(0xffffffffu, s2, 2);
        l1 = l1 * f1 + s1;
        l2 = l2 * f2v + s2;
        #pragma unroll
        for (int nt = 0; nt < 8; nt++) {
            of[nt][0] *= f1;  of[nt][1] *= f1;
            of[nt][2] *= f2v; of[nt][3] *= f2v;
        }

        #pragma unroll
        for (int kt = 0; kt < 8; kt++) {
            uint32_t af[4] = { __float_as_uint(sf[kt][0]), __float_as_uint(sf[kt][2]),
                               __float_as_uint(sf[kt][1]), __float_as_uint(sf[kt][3]) };
            const float* vrow0 = Vs + (kt * 8 + qd * 2) * FA2_PAD;
            const float* vrow1 = vrow0 + FA2_PAD;
            #pragma unroll
            for (int nt = 0; nt < 8; nt++) {
                uint32_t b0 = __float_as_uint(vrow0[nt * 8 + gid]);
                uint32_t b1 = __float_as_uint(vrow1[nt * 8 + gid]);
                mma_tf32(of[nt], af, b0, b1);
            }
        }
        __syncthreads();
    }

    float inv1 = 1.0f / l1, inv2 = 1.0f / l2;
    __half* o1base = out + (size_t)(b * Ss_ + aq1) * Dd_ + h * HD_;
    __half* o2base = out + (size_t)(b * Ss_ + aq1 + 8) * Dd_ + h * HD_;
    #pragma unroll
    for (int nt = 0; nt < 8; nt++) {
        *(__half2*)(o1base + nt * 8 + qd * 2) = __floats2half2_rn(of[nt][0] * inv1, of[nt][1] * inv1);
        *(__half2*)(o2base + nt * 8 + qd * 2) = __floats2half2_rn(of[nt][2] * inv2, of[nt][3] * inv2);
    }
}

// -------------------- Cross-attention (64 keys, fp16 output) --------------------
__global__ __launch_bounds__(64)
void cross_attn_kernel(const float* __restrict__ qc, const float* __restrict__ kc,
                       const float* __restrict__ vc, __half* __restrict__ out)
{
    int qidx = blockIdx.x;
    int bh   = blockIdx.y;
    int b = bh / Hh_, h = bh % Hh_;
    int tid = threadIdx.x;

    __shared__ float sq[HD_];
    __shared__ float p[MEM_];
    __shared__ float red[2];

    const float* qrow = qc + ((size_t)(b * Ss_ + qidx)) * Dd_ + h * HD_;
    sq[tid] = qrow[tid];
    __syncthreads();

    const float* krow = kc + ((size_t)(b * MEM_ + tid)) * Dd_ + h * HD_;
    float s = 0.f;
    #pragma unroll
    for (int d = 0; d < HD_; d += 4) {
        float4 k4 = *(const float4*)(krow + d);
        s = fmaf(sq[d + 0], k4.x, s);
        s = fmaf(sq[d + 1], k4.y, s);
        s = fmaf(sq[d + 2], k4.z, s);
        s = fmaf(sq[d + 3], k4.w, s);
    }
    s *= 0.125f;

    float m = s;
    #pragma unroll
    for (int o = 16; o > 0; o >>= 1) m = fmaxf(m, __shfl_xor_sync(0xffffffffu, m, o));
    if ((tid & 31) == 0) red[tid >> 5] = m;
    __syncthreads();
    float gm = fmaxf(red[0], red[1]);
    float pv = expf(s - gm);
    p[tid] = pv;
    float su = pv;
    #pragma unroll
    for (int o = 16; o > 0; o >>= 1) su += __shfl_xor_sync(0xffffffffu, su, o);
    __syncthreads();
    if ((tid & 31) == 0) red[tid >> 5] = su;
    __syncthreads();
    float gl = red[0] + red[1];

    const float* vbase = vc + ((size_t)(b * MEM_)) * Dd_ + h * HD_ + tid;
    float a = 0.f;
    #pragma unroll 4
    for (int j = 0; j < MEM_; j++)
        a = fmaf(p[j], vbase[(size_t)j * Dd_], a);

    out[((size_t)(b * Ss_ + qidx)) * Dd_ + h * HD_ + tid] = __float2half_rn(a / gl);
}

// -------------------- launch --------------------
extern "C" void kernel_launch(void* const* d_in, const int* in_sizes, int n_in,
                              void* d_out, int out_size)
{
    const float* tgt      = (const float*)d_in[0];
    const float* memory   = (const float*)d_in[1];
    const float* rope_cos = (const float*)d_in[2];
    const float* rope_sin = (const float*)d_in[3];
    const float* W_qkv    = (const float*)d_in[4];
    const float* b_qkv    = (const float*)d_in[5];
    const float* W_o      = (const float*)d_in[6];
    const float* b_o      = (const float*)d_in[7];
    const float* Wq_c     = (const float*)d_in[8];
    const float* bq_c     = (const float*)d_in[9];
    const float* Wk_c     = (const float*)d_in[10];
    const float* bk_c     = (const float*)d_in[11];
    const float* Wv_c     = (const float*)d_in[12];
    const float* bv_c     = (const float*)d_in[13];
    const float* W_co     = (const float*)d_in[14];
    const float* b_co     = (const float*)d_in[15];
    const float* W1       = (const float*)d_in[16];
    const float* b1       = (const float*)d_in[17];
    const float* W2       = (const float*)d_in[18];
    const float* b2       = (const float*)d_in[19];
    const float* g1       = (const float*)d_in[20];
    const float* be1      = (const float*)d_in[21];
    const float* g2       = (const float*)d_in[22];
    const float* be2      = (const float*)d_in[23];
    const float* g3       = (const float*)d_in[24];
    const float* be3      = (const float*)d_in[25];
    float* out = (float*)d_out;

    float *qkv, *tgtb, *kc, *vc;
    __half *wTh, *xh, *sah, *ffnh, *memh;
    cudaGetSymbolAddress((void**)&qkv,  g_qkv);
    cudaGetSymbolAddress((void**)&tgtb, g_tgt);
    cudaGetSymbolAddress((void**)&kc,   g_kc);
    cudaGetSymbolAddress((void**)&vc,   g_vc);
    cudaGetSymbolAddress((void**)&wTh,  g_wTh);
    cudaGetSymbolAddress((void**)&xh,   g_xh);
    cudaGetSymbolAddress((void**)&sah,  g_sah);
    cudaGetSymbolAddress((void**)&ffnh, g_ffnh);
    cudaGetSymbolAddress((void**)&memh, g_memh);

    cudaFuncSetAttribute(flash_attn_tc,
                         cudaFuncAttributeMaxDynamicSharedMemorySize, FA2_SMEM);
    cudaFuncSetAttribute(gemm_mma,
                         cudaFuncAttributeMaxDynamicSharedMemorySize, GM_SMEM);

    // 0) pre-transpose + fp16-convert all weights; fp16 copy of memory
    {
        dim3 thr(32, 8);
        transpose_h<<<dim3(3 * Dd_ / 32, Dd_ / 32), thr>>>(W_qkv, wTh + WT_QKV, Dd_, 3 * Dd_);
        transpose_h<<<dim3(Dd_ / 32, Dd_ / 32), thr>>>(W_o,  wTh + WT_O,  Dd_, Dd_);
        transpose_h<<<dim3(Dd_ / 32, Dd_ / 32), thr>>>(Wq_c, wTh + WT_QC, Dd_, Dd_);
        transpose_h<<<dim3(Dd_ / 32, Dd_ / 32), thr>>>(Wk_c, wTh + WT_KC, Dd_, Dd_);
        transpose_h<<<dim3(Dd_ / 32, Dd_ / 32), thr>>>(Wv_c, wTh + WT_VC, Dd_, Dd_);
        transpose_h<<<dim3(Dd_ / 32, Dd_ / 32), thr>>>(W_co, wTh + WT_CO, Dd_, Dd_);
        transpose_h<<<dim3(FF_ / 32, Dd_ / 32), thr>>>(W1, wTh + WT_W1, Dd_, FF_);
        transpose_h<<<dim3(Dd_ / 32, FF_ / 32), thr>>>(W2, wTh + WT_W2, FF_, Dd_);
        int nmem = Bb_ * MEM_ * Dd_;
        conv_h<<<(nmem + 255) / 256, 256>>>(memory, memh, nmem);
    }

    // 1) xh = LN1(tgt)
    layernorm_kernel<<<NT_, 256>>>(tgt, g1, be1, xh);
    // 2) qkv = xh @ W_qkv + b
    gemm_mma<<<dim3(3 * Dd_ / 128, NT_ / 128), 256, GM_SMEM>>>(xh, wTh + WT_QKV, b_qkv, nullptr, qkv, nullptr, 3 * Dd_, Dd_, 0);
    // 3) RoPE on q,k
    {
        int total = 2 * NT_ * Hh_ * (HD_ / 2);
        rope_kernel<<<(total + 255) / 256, 256>>>(qkv, rope_cos, rope_sin);
    }
    // 4) causal self-attention -> sah (fp16)
    flash_attn_tc<<<dim3(Ss_ / 64, Bb_ * Hh_), 128, FA2_SMEM>>>(qkv, sah);
    // 5) tgtb = tgt + sah @ W_o + b_o
    gemm_mma<<<dim3(Dd_ / 128, NT_ / 128), 256, GM_SMEM>>>(sah, wTh + WT_O, b_o, tgt, tgtb, nullptr, Dd_, Dd_, 0);
    // 6) xh = LN2(tgtb)
    layernorm_kernel<<<NT_, 256>>>(tgtb, g2, be2, xh);
    // 7) qc = xh @ Wq_c -> qkv buffer (fp32)
    gemm_mma<<<dim3(Dd_ / 128, NT_ / 128), 256, GM_SMEM>>>(xh, wTh + WT_QC, bq_c, nullptr, qkv, nullptr, Dd_, Dd_, 0);
    // 8) kc/vc = memh @ Wk_c / Wv_c (fp32 out)
    gemm_mma<<<dim3(Dd_ / 128, 1), 256, GM_SMEM>>>(memh, wTh + WT_KC, bk_c, nullptr, kc, nullptr, Dd_, Dd_, 0);
    gemm_mma<<<dim3(Dd_ / 128, 1), 256, GM_SMEM>>>(memh, wTh + WT_VC, bv_c, nullptr, vc, nullptr, Dd_, Dd_, 0);
    // 9) cross-attention -> sah (fp16)
    cross_attn_kernel<<<dim3(Ss_, Bb_ * Hh_), 64>>>(qkv, kc, vc, sah);
    // 10) tgtb += sah @ W_co + b_co
    gemm_mma<<<dim3(Dd_ / 128, NT_ / 128), 256, GM_SMEM>>>(sah, wTh + WT_CO, b_co, tgtb, tgtb, nullptr, Dd_, Dd_, 0);
    // 11) xh = LN3(tgtb)
    layernorm_kernel<<<NT_, 256>>>(tgtb, g3, be3, xh);
    // 12) ffnh = gelu(xh @ W1 + b1) (fp16 out)
    gemm_mma<<<dim3(FF_ / 128, NT_ / 128), 256, GM_SMEM>>>(xh, wTh + WT_W1, b1, nullptr, nullptr, ffnh, FF_, Dd_, 1);
    // 13) out = tgtb + ffnh @ W2 + b2
    gemm_mma<<<dim3(Dd_ / 128, NT_ / 128), 256, GM_SMEM>>>(ffnh, wTh + WT_W2, b2, tgtb, out, nullptr, Dd_, FF_, 0);
}

// round 8
// speedup vs baseline: 8.5813x; 1.2613x over previous
#include <cuda_runtime.h>
#include <cuda_fp16.h>
#include <cstdint>
#include <math.h>

// Problem constants
#define Bb_  2
#define Ss_  2048
#define MEM_ 64
#define Dd_  1024
#define Hh_  16
#define FF_  4096
#define HD_  64
#define NT_  (Bb_ * Ss_)   // 4096 tokens

// -------------------- scratch (device globals; no runtime alloc) --------------------
__device__ float  g_qkv [(size_t)NT_ * 3 * Dd_];
__device__ float  g_tgt [(size_t)NT_ * Dd_];
__device__ float  g_kvc [(size_t)Bb_ * MEM_ * 2 * Dd_];   // kc|vc interleaved rows of 2048
__device__ float  g_b2  [2 * Dd_];
__device__ __half g_wTh [(size_t)16 * 1024 * 1024];  // transposed fp16 weights
__device__ __half g_xh  [(size_t)NT_ * Dd_];
__device__ __half g_sah [(size_t)NT_ * Dd_];
__device__ __half g_ffnh[(size_t)NT_ * FF_];
__device__ __half g_memh[(size_t)Bb_ * MEM_ * Dd_];

// offsets into g_wTh (half elements)
#define WT_QKV 0u
#define WT_O   (3u * 1024u * 1024u)
#define WT_QC  (4u * 1024u * 1024u)
#define WT_KC  (5u * 1024u * 1024u)   // [2048][1024] together with VC
#define WT_VC  (6u * 1024u * 1024u)
#define WT_CO  (7u * 1024u * 1024u)
#define WT_W1  (8u * 1024u * 1024u)
#define WT_W2  (12u * 1024u * 1024u)

// -------------------- helpers --------------------
__device__ __forceinline__ uint32_t smem_u32(const void* p) {
    uint32_t a;
    asm("{ .reg .u64 t; cvta.to.shared.u64 t, %1; cvt.u32.u64 %0, t; }" : "=r"(a) : "l"(p));
    return a;
}
__device__ __forceinline__ float ftf32(float x) {
    float y;
    asm("cvt.rna.tf32.f32 %0, %1;" : "=f"(y) : "f"(x));
    return y;
}
__device__ __forceinline__ void cpa16(uint32_t dst, const void* src) {
    asm volatile("cp.async.cg.shared.global [%0], [%1], 16;" :: "r"(dst), "l"(src));
}
__device__ __forceinline__ void ldsm_x4(uint32_t& r0, uint32_t& r1, uint32_t& r2,
                                        uint32_t& r3, uint32_t addr) {
    asm volatile("ldmatrix.sync.aligned.m8n8.x4.shared.b16 {%0,%1,%2,%3}, [%4];"
                 : "=r"(r0), "=r"(r1), "=r"(r2), "=r"(r3) : "r"(addr));
}
#define CPA_COMMIT() asm volatile("cp.async.commit_group;" ::: "memory")
#define CPA_WAIT1()  asm volatile("cp.async.wait_group 1;"  ::: "memory")
#define CPA_WAIT0()  asm volatile("cp.async.wait_group 0;"  ::: "memory")
#define SWZ(b) ((b) ^ (((b) >> 3) & 0x70))

__device__ __forceinline__ void mma_tf32(float* d, const uint32_t* a, uint32_t b0, uint32_t b1) {
    asm volatile(
        "mma.sync.aligned.m16n8k8.row.col.f32.tf32.tf32.f32 "
        "{%0,%1,%2,%3}, {%4,%5,%6,%7}, {%8,%9}, {%0,%1,%2,%3};"
        : "+f"(d[0]), "+f"(d[1]), "+f"(d[2]), "+f"(d[3])
        : "r"(a[0]), "r"(a[1]), "r"(a[2]), "r"(a[3]), "r"(b0), "r"(b1));
}
__device__ __forceinline__ void mma_f16(float* d, uint32_t a0, uint32_t a1, uint32_t a2,
                                        uint32_t a3, uint32_t b0, uint32_t b1) {
    asm volatile(
        "mma.sync.aligned.m16n8k16.row.col.f32.f16.f16.f32 "
        "{%0,%1,%2,%3}, {%4,%5,%6,%7}, {%8,%9}, {%0,%1,%2,%3};"
        : "+f"(d[0]), "+f"(d[1]), "+f"(d[2]), "+f"(d[3])
        : "r"(a0), "r"(a1), "r"(a2), "r"(a3), "r"(b0), "r"(b1));
}

// -------------------- weight transpose + fp16 convert --------------------
__global__ void transpose_h(const float* __restrict__ W, __half* __restrict__ WT,
                            int K, int N)
{
    __shared__ float t[32][33];
    const int n0 = blockIdx.x * 32, k0 = blockIdx.y * 32;
    const int tx = threadIdx.x, ty = threadIdx.y;   // 32 x 8
    #pragma unroll
    for (int r = 0; r < 32; r += 8)
        t[ty + r][tx] = W[(size_t)(k0 + ty + r) * N + n0 + tx];
    __syncthreads();
    #pragma unroll
    for (int r = 0; r < 32; r += 8)
        WT[(size_t)(n0 + ty + r) * K + k0 + tx] = __float2half_rn(t[tx][ty + r]);
}

// -------------------- misc small kernels --------------------
__global__ void conv_h(const float* __restrict__ x, __half* __restrict__ y, int n)
{
    int i = blockIdx.x * blockDim.x + threadIdx.x;
    if (i < n) y[i] = __float2half_rn(x[i]);
}
__global__ void concat2(const float* __restrict__ a, const float* __restrict__ b,
                        float* __restrict__ o)
{
    int i = blockIdx.x * blockDim.x + threadIdx.x;
    if (i < Dd_) o[i] = a[i];
    else if (i < 2 * Dd_) o[i] = b[i - Dd_];
}

// -------------------- LayerNorm (fp32 in, fp16 out) --------------------
__global__ void layernorm_kernel(const float* __restrict__ x,
                                 const float* __restrict__ g,
                                 const float* __restrict__ be,
                                 __half* __restrict__ y)
{
    int row = blockIdx.x;
    int tid = threadIdx.x;
    const float* xr = x + (size_t)row * Dd_;
    float4 v = *(const float4*)(xr + tid * 4);

    __shared__ float red[8];
    __shared__ float s_mu, s_inv;

    float s = v.x + v.y + v.z + v.w;
    #pragma unroll
    for (int o = 16; o > 0; o >>= 1) s += __shfl_xor_sync(0xffffffffu, s, o);
    if ((tid & 31) == 0) red[tid >> 5] = s;
    __syncthreads();
    if (tid == 0) {
        float t = 0.f;
        #pragma unroll
        for (int i = 0; i < 8; i++) t += red[i];
        s_mu = t * (1.0f / Dd_);
    }
    __syncthreads();
    float mu = s_mu;
    float dx = v.x - mu, dy = v.y - mu, dz = v.z - mu, dw = v.w - mu;
    float q = dx*dx + dy*dy + dz*dz + dw*dw;
    #pragma unroll
    for (int o = 16; o > 0; o >>= 1) q += __shfl_xor_sync(0xffffffffu, q, o);
    if ((tid & 31) == 0) red[tid >> 5] = q;
    __syncthreads();
    if (tid == 0) {
        float t = 0.f;
        #pragma unroll
        for (int i = 0; i < 8; i++) t += red[i];
        s_inv = rsqrtf(t * (1.0f / Dd_) + 1e-5f);
    }
    __syncthreads();
    float inv = s_inv;
    int c = tid * 4;
    __half* yr = y + (size_t)row * Dd_;
    float o0 = dx * inv * g[c + 0] + be[c + 0];
    float o1 = dy * inv * g[c + 1] + be[c + 1];
    float o2 = dz * inv * g[c + 2] + be[c + 2];
    float o3 = dw * inv * g[c + 3] + be[c + 3];
    ((__half2*)(yr + c))[0] = __floats2half2_rn(o0, o1);
    ((__half2*)(yr + c))[1] = __floats2half2_rn(o2, o3);
}

// -------------------- fp16 mma GEMM, cp.async 3-stage, ldmatrix fragments ------------
// C = A(MxK,fp16) @ WT^T + bias [+res] [gelu]; WT fp16 [N][K]. Out fp32 C or fp16 Ch.
// CTA tile 128x128, BK=64 (128B rows), 256 threads (8 warps, 4x2), warp tile 32x64.
#define GM_STAGE 32768
#define GM_SMEM  (3 * GM_STAGE + 1024)
__global__ __launch_bounds__(256)
void gemm_mma(const __half* __restrict__ A, const __half* __restrict__ WT,
              const float* __restrict__ bias, const float* __restrict__ res,
              float* __restrict__ C, __half* __restrict__ Ch,
              int Nc, int Kd, int dogelu)
{
    extern __shared__ float dyns[];
    const uint32_t sbase = (smem_u32(dyns) + 1023u) & ~1023u;

    const int tid  = threadIdx.x;
    const int lane = tid & 31, wid = tid >> 5;
    const int gid  = lane >> 2, qd = lane & 3;
    const int wm   = (wid >> 1) * 32;
    const int wn   = (wid & 1) * 64;
    const int n0   = blockIdx.x * 128;
    const int m0   = blockIdx.y * 128;

    // ldmatrix per-lane address components (constant across loop)
    const int arow  = wm + (lane & 7) + ((lane >> 3) & 1) * 8;   // A rows (mt=0); +16 for mt=1
    const uint32_t acolb = (uint32_t)((lane >> 4) * 16);          // A k-half select
    const int bn_base = wn + ((lane >> 4) & 1) * 8 + (lane & 7);  // B n row within jp pair
    const uint32_t bcolb = (uint32_t)(((lane >> 3) & 1) * 16);    // B k-half select

    float d[2][8][4];
    #pragma unroll
    for (int mt = 0; mt < 2; mt++)
        #pragma unroll
        for (int nt = 0; nt < 8; nt++)
            #pragma unroll
            for (int e = 0; e < 4; e++) d[mt][nt][e] = 0.f;

    const int nsteps = Kd >> 6;   // BK = 64
    const __half* Abase = A  + (size_t)m0 * Kd;
    const __half* Bbase = WT + (size_t)n0 * Kd;

    auto cpa_tile = [&](int kstep, int s) {
        const int k0 = kstep * 64;
        const uint32_t aA = sbase + s * GM_STAGE;
        const uint32_t bA = aA + 16384u;
        #pragma unroll
        for (int p = 0; p < 4; p++) {
            int task = p * 256 + tid;
            int r = task >> 3, c = task & 7;
            cpa16(aA + SWZ((uint32_t)(r * 128 + c * 16)), Abase + (size_t)r * Kd + k0 + c * 8);
        }
        #pragma unroll
        for (int p = 0; p < 4; p++) {
            int task = p * 256 + tid;
            int r = task >> 3, c = task & 7;
            cpa16(bA + SWZ((uint32_t)(r * 128 + c * 16)), Bbase + (size_t)r * Kd + k0 + c * 8);
        }
        CPA_COMMIT();
    };

    cpa_tile(0, 0);
    cpa_tile(1, 1);

    for (int i = 0; i < nsteps; i++) {
        const int s = i % 3;
        if (i == nsteps - 1) { CPA_WAIT0(); } else { CPA_WAIT1(); }
        __syncthreads();
        if (i + 2 < nsteps) cpa_tile(i + 2, (i + 2) % 3);

        const uint32_t aA = sbase + s * GM_STAGE;
        const uint32_t bA = aA + 16384u;
        #pragma unroll
        for (int g = 0; g < 4; g++) {
            const uint32_t gb = (uint32_t)(g * 32);
            uint32_t a0[4], a1[4];
            ldsm_x4(a0[0], a0[1], a0[2], a0[3],
                    aA + SWZ((uint32_t)(arow * 128) + gb + acolb));
            ldsm_x4(a1[0], a1[1], a1[2], a1[3],
                    aA + SWZ((uint32_t)((arow + 16) * 128) + gb + acolb));
            uint32_t bf[8][2];
            #pragma unroll
            for (int jp = 0; jp < 4; jp++) {
                int n = bn_base + jp * 16;
                ldsm_x4(bf[jp * 2][0], bf[jp * 2][1], bf[jp * 2 + 1][0], bf[jp * 2 + 1][1],
                        bA + SWZ((uint32_t)(n * 128) + gb + bcolb));
            }
            #pragma unroll
            for (int nt = 0; nt < 8; nt++) {
                mma_f16(d[0][nt], a0[0], a0[1], a0[2], a0[3], bf[nt][0], bf[nt][1]);
                mma_f16(d[1][nt], a1[0], a1[1], a1[2], a1[3], bf[nt][0], bf[nt][1]);
            }
        }
    }

    // ---- epilogue: bias [+res] [gelu]; fp32 or fp16 stores ----
    #pragma unroll
    for (int mt = 0; mt < 2; mt++) {
        #pragma unroll
        for (int nt = 0; nt < 8; nt++) {
            const int r0  = m0 + wm + mt * 16 + gid;
            const int col = n0 + wn + nt * 8 + qd * 2;
            float2 b2 = *(const float2*)(bias + col);
            #pragma unroll
            for (int half_ = 0; half_ < 2; half_++) {
                const int row = r0 + half_ * 8;
                float ox = d[mt][nt][half_ * 2 + 0] + b2.x;
                float oy = d[mt][nt][half_ * 2 + 1] + b2.y;
                if (res) {
                    float2 r2 = *(const float2*)(res + (size_t)row * Nc + col);
                    ox += r2.x; oy += r2.y;
                }
                if (dogelu) {
                    ox = 0.5f * ox * (1.0f + erff(ox * 0.7071067811865475f));
                    oy = 0.5f * oy * (1.0f + erff(oy * 0.7071067811865475f));
                }
                if (Ch) {
                    *(__half2*)(Ch + (size_t)row * Nc + col) = __floats2half2_rn(ox, oy);
                } else {
                    float2 o2; o2.x = ox; o2.y = oy;
                    *(float2*)(C + (size_t)row * Nc + col) = o2;
                }
            }
        }
    }
}

// -------------------- RoPE --------------------
__global__ void rope_kernel(float* __restrict__ qkv,
                            const float* __restrict__ rc,
                            const float* __restrict__ rs)
{
    int idx = blockIdx.x * blockDim.x + threadIdx.x;
    int total = 2 * NT_ * Hh_ * (HD_ / 2);
    if (idx >= total) return;
    int t = idx & 1;
    int r = idx >> 1;
    int pair = r & 31;  r >>= 5;
    int h = r & 15;     r >>= 4;
    int s = r % Ss_;
    int b = r / Ss_;
    float* base = qkv + ((size_t)(b * Ss_ + s)) * (3 * Dd_) + t * Dd_ + h * HD_ + pair * 2;
    float c  = rc[s * 32 + pair];
    float sn = rs[s * 32 + pair];
    float e = base[0], o = base[1];
    base[0] = e * c - o * sn;
    base[1] = e * sn + o * c;
}

// -------------------- tf32 mma flash attention (fp16 output) --------------------
#define FA2_PAD  68
#define FA2_SMEM (2 * 64 * FA2_PAD * 4)   // 34,816 B
__global__ __launch_bounds__(128)
void flash_attn_tc(const float* __restrict__ qkv, __half* __restrict__ out)
{
    extern __shared__ float sm2[];
    float* Ks = sm2;
    float* Vs = sm2 + 64 * FA2_PAD;

    const int qb = (int)gridDim.x - 1 - (int)blockIdx.x;
    const int q0 = qb * 64;
    const int bh = blockIdx.y;
    const int b = bh >> 4, h = bh & 15;
    const int tid = threadIdx.x, lane = tid & 31, wid = tid >> 5;
    const int gid = lane >> 2, qd = lane & 3;
    const int wr = wid * 16;
    const size_t rs3 = 3 * Dd_;

    const float* qbase = qkv + (size_t)(b * Ss_ + q0) * rs3 + h * HD_;
    const float* kbase = qkv + (size_t)(b * Ss_) * rs3 + Dd_ + h * HD_;
    const float* vbase = qkv + (size_t)(b * Ss_) * rs3 + 2 * Dd_ + h * HD_;

    #pragma unroll
    for (int p = 0; p < 8; p++) {
        int L = p * 128 + tid;
        int r = L >> 4, d4 = (L & 15) * 4;
        float4 v = *(const float4*)(qbase + (size_t)r * rs3 + d4);
        float4 w;
        w.x = ftf32(v.x) * 0.125f; w.y = ftf32(v.y) * 0.125f;
        w.z = ftf32(v.z) * 0.125f; w.w = ftf32(v.w) * 0.125f;
        *(float4*)(Ks + r * FA2_PAD + d4) = w;
    }
    __syncthreads();

    uint32_t qf[8][4];
    #pragma unroll
    for (int kt = 0; kt < 8; kt++) {
        float2 lo = *(const float2*)(Ks + (wr + gid) * FA2_PAD + kt * 8 + qd * 2);
        float2 hi = *(const float2*)(Ks + (wr + gid + 8) * FA2_PAD + kt * 8 + qd * 2);
        qf[kt][0] = __float_as_uint(lo.x);
        qf[kt][1] = __float_as_uint(hi.x);
        qf[kt][2] = __float_as_uint(lo.y);
        qf[kt][3] = __float_as_uint(hi.y);
    }
    __syncthreads();

    float of[8][4];
    #pragma unroll
    for (int nt = 0; nt < 8; nt++)
        #pragma unroll
        for (int e = 0; e < 4; e++) of[nt][e] = 0.f;
    float m1 = -1e30f, m2 = -1e30f, l1 = 0.f, l2 = 0.f;

    const int aq1 = q0 + wr + gid;

    for (int t = 0; t <= qb; t++) {
        const int k0 = t * 64;
        #pragma unroll
        for (int p = 0; p < 8; p++) {
            int L = p * 128 + tid;
            int r = L >> 4, d4 = (L & 15) * 4;
            float4 kv = *(const float4*)(kbase + (size_t)(k0 + r) * rs3 + d4);
            float4 kw;
            kw.x = ftf32(kv.x); kw.y = ftf32(kv.y); kw.z = ftf32(kv.z); kw.w = ftf32(kv.w);
            *(float4*)(Ks + r * FA2_PAD + d4) = kw;
            float4 vv = *(const float4*)(vbase + (size_t)(k0 + r) * rs3 + d4);
            float4 vw;
            vw.x = ftf32(vv.x); vw.y = ftf32(vv.y); vw.z = ftf32(vv.z); vw.w = ftf32(vv.w);
            *(float4*)(Vs + r * FA2_PAD + d4) = vw;
        }
        __syncthreads();

        float sf[8][4];
        #pragma unroll
        for (int nt = 0; nt < 8; nt++)
            #pragma unroll
            for (int e = 0; e < 4; e++) sf[nt][e] = 0.f;

        #pragma unroll
        for (int kt = 0; kt < 8; kt++) {
            #pragma unroll
            for (int nt = 0; nt < 8; nt++) {
                float2 bk = *(const float2*)(Ks + (nt * 8 + gid) * FA2_PAD + kt * 8 + qd * 2);
                mma_tf32(sf[nt], qf[kt], __float_as_uint(bk.x), __float_as_uint(bk.y));
            }
        }

        if (t == qb) {
            #pragma unroll
            for (int nt = 0; nt < 8; nt++) {
                int c = k0 + nt * 8 + qd * 2;
                if (c     > aq1)     sf[nt][0] = -1e30f;
                if (c + 1 > aq1)     sf[nt][1] = -1e30f;
                if (c     > aq1 + 8) sf[nt][2] = -1e30f;
                if (c + 1 > aq1 + 8) sf[nt][3] = -1e30f;
            }
        }

        float mx1 = -1e30f, mx2 = -1e30f;
        #pragma unroll
        for (int nt = 0; nt < 8; nt++) {
            mx1 = fmaxf(mx1, fmaxf(sf[nt][0], sf[nt][1]));
            mx2 = fmaxf(mx2, fmaxf(sf[nt][2], sf[nt][3]));
        }
        mx1 = fmaxf(mx1, __shfl_xor_sync(0xffffffffu, mx1, 1));
        mx1 = fmaxf(mx1, __shfl_xor_sync(0xffffffffu, mx1, 2));
        mx2 = fmaxf(mx2, __shfl_xor_sync(0xffffffffu, mx2, 1));
        mx2 = fmaxf(mx2, __shfl_xor_sync(0xffffffffu, mx2, 2));
        float nm1 = fmaxf(m1, mx1), nm2 = fmaxf(m2, mx2);
        float f1 = __expf(m1 - nm1), f2v = __expf(m2 - nm2);
        m1 = nm1; m2 = nm2;
        float s1 = 0.f, s2 = 0.f;
        #pragma unroll
        for (int nt = 0; nt < 8; nt++) {
            sf[nt][0] = __expf(sf[nt][0] - nm1); s1 += sf[nt][0];
            sf[nt][1] = __expf(sf[nt][1] - nm1); s1 += sf[nt][1];
            sf[nt][2] = __expf(sf[nt][2] - nm2); s2 += sf[nt][2];
            sf[nt][3] = __expf(sf[nt][3] - nm2); s2 += sf[nt][3];
        }
        s1 += __shfl_xor_sync(0xffffffffu, s1, 1);
        s1 += __shfl_xor_sync(0xffffffffu, s1, 2);
        s2 += __shfl_xor_sync(0xffffffffu, s2, 1);
        s2 += __shfl_xor_sync(0xffffffffu, s2, 2);
        l1 = l1 * f1 + s1;
        l2 = l2 * f2v + s2;
        #pragma unroll
        for (int nt = 0; nt < 8; nt++) {
            of[nt][0] *= f1;  of[nt][1] *= f1;
            of[nt][2] *= f2v; of[nt][3] *= f2v;
        }

        #pragma unroll
        for (int kt = 0; kt < 8; kt++) {
            uint32_t af[4] = { __float_as_uint(sf[kt][0]), __float_as_uint(sf[kt][2]),
                               __float_as_uint(sf[kt][1]), __float_as_uint(sf[kt][3]) };
            const float* vrow0 = Vs + (kt * 8 + qd * 2) * FA2_PAD;
            const float* vrow1 = vrow0 + FA2_PAD;
            #pragma unroll
            for (int nt = 0; nt < 8; nt++) {
                uint32_t b0 = __float_as_uint(vrow0[nt * 8 + gid]);
                uint32_t b1 = __float_as_uint(vrow1[nt * 8 + gid]);
                mma_tf32(of[nt], af, b0, b1);
            }
        }
        __syncthreads();
    }

    float inv1 = 1.0f / l1, inv2 = 1.0f / l2;
    __half* o1base = out + (size_t)(b * Ss_ + aq1) * Dd_ + h * HD_;
    __half* o2base = out + (size_t)(b * Ss_ + aq1 + 8) * Dd_ + h * HD_;
    #pragma unroll
    for (int nt = 0; nt < 8; nt++) {
        *(__half2*)(o1base + nt * 8 + qd * 2) = __floats2half2_rn(of[nt][0] * inv1, of[nt][1] * inv1);
        *(__half2*)(o2base + nt * 8 + qd * 2) = __floats2half2_rn(of[nt][2] * inv2, of[nt][3] * inv2);
    }
}

// -------------------- Cross-attention (64 keys, kvc stride 2048, fp16 out) ------------
__global__ __launch_bounds__(64)
void cross_attn_kernel(const float* __restrict__ qc, const float* __restrict__ kvc,
                       __half* __restrict__ out)
{
    int qidx = blockIdx.x;
    int bh   = blockIdx.y;
    int b = bh / Hh_, h = bh % Hh_;
    int tid = threadIdx.x;

    __shared__ float sq[HD_];
    __shared__ float p[MEM_];
    __shared__ float red[2];

    const float* qrow = qc + ((size_t)(b * Ss_ + qidx)) * Dd_ + h * HD_;
    sq[tid] = qrow[tid];
    __syncthreads();

    const float* krow = kvc + ((size_t)(b * MEM_ + tid)) * (2 * Dd_) + h * HD_;
    float s = 0.f;
    #pragma unroll
    for (int d = 0; d < HD_; d += 4) {
        float4 k4 = *(const float4*)(krow + d);
        s = fmaf(sq[d + 0], k4.x, s);
        s = fmaf(sq[d + 1], k4.y, s);
        s = fmaf(sq[d + 2], k4.z, s);
        s = fmaf(sq[d + 3], k4.w, s);
    }
    s *= 0.125f;

    float m = s;
    #pragma unroll
    for (int o = 16; o > 0; o >>= 1) m = fmaxf(m, __shfl_xor_sync(0xffffffffu, m, o));
    if ((tid & 31) == 0) red[tid >> 5] = m;
    __syncthreads();
    float gm = fmaxf(red[0], red[1]);
    float pv = expf(s - gm);
    p[tid] = pv;
    float su = pv;
    #pragma unroll
    for (int o = 16; o > 0; o >>= 1) su += __shfl_xor_sync(0xffffffffu, su, o);
    __syncthreads();
    if ((tid & 31) == 0) red[tid >> 5] = su;
    __syncthreads();
    float gl = red[0] + red[1];

    const float* vbase = kvc + ((size_t)(b * MEM_)) * (2 * Dd_) + Dd_ + h * HD_ + tid;
    float a = 0.f;
    #pragma unroll 4
    for (int j = 0; j < MEM_; j++)
        a = fmaf(p[j], vbase[(size_t)j * (2 * Dd_)], a);

    out[((size_t)(b * Ss_ + qidx)) * Dd_ + h * HD_ + tid] = __float2half_rn(a / gl);
}

// -------------------- launch --------------------
extern "C" void kernel_launch(void* const* d_in, const int* in_sizes, int n_in,
                              void* d_out, int out_size)
{
    const float* tgt      = (const float*)d_in[0];
    const float* memory   = (const float*)d_in[1];
    const float* rope_cos = (const float*)d_in[2];
    const float* rope_sin = (const float*)d_in[3];
    const float* W_qkv    = (const float*)d_in[4];
    const float* b_qkv    = (const float*)d_in[5];
    const float* W_o      = (const float*)d_in[6];
    const float* b_o      = (const float*)d_in[7];
    const float* Wq_c     = (const float*)d_in[8];
    const float* bq_c     = (const float*)d_in[9];
    const float* Wk_c     = (const float*)d_in[10];
    const float* bk_c     = (const float*)d_in[11];
    const float* Wv_c     = (const float*)d_in[12];
    const float* bv_c     = (const float*)d_in[13];
    const float* W_co     = (const float*)d_in[14];
    const float* b_co     = (const float*)d_in[15];
    const float* W1       = (const float*)d_in[16];
    const float* b1       = (const float*)d_in[17];
    const float* W2       = (const float*)d_in[18];
    const float* b2       = (const float*)d_in[19];
    const float* g1       = (const float*)d_in[20];
    const float* be1      = (const float*)d_in[21];
    const float* g2       = (const float*)d_in[22];
    const float* be2      = (const float*)d_in[23];
    const float* g3       = (const float*)d_in[24];
    const float* be3      = (const float*)d_in[25];
    float* out = (float*)d_out;

    float *qkv, *tgtb, *kvc, *b2c;
    __half *wTh, *xh, *sah, *ffnh, *memh;
    cudaGetSymbolAddress((void**)&qkv,  g_qkv);
    cudaGetSymbolAddress((void**)&tgtb, g_tgt);
    cudaGetSymbolAddress((void**)&kvc,  g_kvc);
    cudaGetSymbolAddress((void**)&b2c,  g_b2);
    cudaGetSymbolAddress((void**)&wTh,  g_wTh);
    cudaGetSymbolAddress((void**)&xh,   g_xh);
    cudaGetSymbolAddress((void**)&sah,  g_sah);
    cudaGetSymbolAddress((void**)&ffnh, g_ffnh);
    cudaGetSymbolAddress((void**)&memh, g_memh);

    cudaFuncSetAttribute(flash_attn_tc,
                         cudaFuncAttributeMaxDynamicSharedMemorySize, FA2_SMEM);
    cudaFuncSetAttribute(gemm_mma,
                         cudaFuncAttributeMaxDynamicSharedMemorySize, GM_SMEM);

    // 0) pre-transpose + fp16-convert all weights; fp16 copy of memory; concat bias
    {
        dim3 thr(32, 8);
        transpose_h<<<dim3(3 * Dd_ / 32, Dd_ / 32), thr>>>(W_qkv, wTh + WT_QKV, Dd_, 3 * Dd_);
        transpose_h<<<dim3(Dd_ / 32, Dd_ / 32), thr>>>(W_o,  wTh + WT_O,  Dd_, Dd_);
        transpose_h<<<dim3(Dd_ / 32, Dd_ / 32), thr>>>(Wq_c, wTh + WT_QC, Dd_, Dd_);
        transpose_h<<<dim3(Dd_ / 32, Dd_ / 32), thr>>>(Wk_c, wTh + WT_KC, Dd_, Dd_);
        transpose_h<<<dim3(Dd_ / 32, Dd_ / 32), thr>>>(Wv_c, wTh + WT_VC, Dd_, Dd_);
        transpose_h<<<dim3(Dd_ / 32, Dd_ / 32), thr>>>(W_co, wTh + WT_CO, Dd_, Dd_);
        transpose_h<<<dim3(FF_ / 32, Dd_ / 32), thr>>>(W1, wTh + WT_W1, Dd_, FF_);
        transpose_h<<<dim3(Dd_ / 32, FF_ / 32), thr>>>(W2, wTh + WT_W2, FF_, Dd_);
        int nmem = Bb_ * MEM_ * Dd_;
        conv_h<<<(nmem + 255) / 256, 256>>>(memory, memh, nmem);
        concat2<<<(2 * Dd_ + 255) / 256, 256>>>(bk_c, bv_c, b2c);
    }

    // 1) xh = LN1(tgt)
    layernorm_kernel<<<NT_, 256>>>(tgt, g1, be1, xh);
    // 2) qkv = xh @ W_qkv + b
    gemm_mma<<<dim3(3 * Dd_ / 128, NT_ / 128), 256, GM_SMEM>>>(xh, wTh + WT_QKV, b_qkv, nullptr, qkv, nullptr, 3 * Dd_, Dd_, 0);
    // 3) RoPE on q,k
    {
        int total = 2 * NT_ * Hh_ * (HD_ / 2);
        rope_kernel<<<(total + 255) / 256, 256>>>(qkv, rope_cos, rope_sin);
    }
    // 4) causal self-attention -> sah (fp16)
    flash_attn_tc<<<dim3(Ss_ / 64, Bb_ * Hh_), 128, FA2_SMEM>>>(qkv, sah);
    // 5) tgtb = tgt + sah @ W_o + b_o
    gemm_mma<<<dim3(Dd_ / 128, NT_ / 128), 256, GM_SMEM>>>(sah, wTh + WT_O, b_o, tgt, tgtb, nullptr, Dd_, Dd_, 0);
    // 6) xh = LN2(tgtb)
    layernorm_kernel<<<NT_, 256>>>(tgtb, g2, be2, xh);
    // 7) qc = xh @ Wq_c -> qkv buffer (fp32)
    gemm_mma<<<dim3(Dd_ / 128, NT_ / 128), 256, GM_SMEM>>>(xh, wTh + WT_QC, bq_c, nullptr, qkv, nullptr, Dd_, Dd_, 0);
    // 8) kvc = memh @ [Wk_c|Wv_c] (one launch, N=2048)
    gemm_mma<<<dim3(2 * Dd_ / 128, 1), 256, GM_SMEM>>>(memh, wTh + WT_KC, b2c, nullptr, kvc, nullptr, 2 * Dd_, Dd_, 0);
    // 9) cross-attention -> sah (fp16)
    cross_attn_kernel<<<dim3(Ss_, Bb_ * Hh_), 64>>>(qkv, kvc, sah);
    // 10) tgtb += sah @ W_co + b_co
    gemm_mma<<<dim3(Dd_ / 128, NT_ / 128), 256, GM_SMEM>>>(sah, wTh + WT_CO, b_co, tgtb, tgtb, nullptr, Dd_, Dd_, 0);
    // 11) xh = LN3(tgtb)
    layernorm_kernel<<<NT_, 256>>>(tgtb, g3, be3, xh);
    // 12) ffnh = gelu(xh @ W1 + b1) (fp16 out)
    gemm_mma<<<dim3(FF_ / 128, NT_ / 128), 256, GM_SMEM>>>(xh, wTh + WT_W1, b1, nullptr, nullptr, ffnh, FF_, Dd_, 1);
    // 13) out = tgtb + ffnh @ W2 + b2
    gemm_mma<<<dim3(Dd_ / 128, NT_ / 128), 256, GM_SMEM>>>(ffnh, wTh + WT_W2, b2, tgtb, out, nullptr, Dd_, FF_, 0);
}

// round 10
// speedup vs baseline: 9.3899x; 1.0942x over previous
#include <cuda_runtime.h>
#include <cuda_fp16.h>
#include <cstdint>
#include <math.h>

// Problem constants
#define Bb_  2
#define Ss_  2048
#define MEM_ 64
#define Dd_  1024
#define Hh_  16
#define FF_  4096
#define HD_  64
#define NT_  (Bb_ * Ss_)   // 4096 tokens

// -------------------- scratch (device globals; no runtime alloc) --------------------
__device__ float  g_qkv [(size_t)NT_ * 3 * Dd_];
__device__ float  g_tgt [(size_t)NT_ * Dd_];
__device__ float  g_kvc [(size_t)Bb_ * MEM_ * 2 * Dd_];   // kc|vc rows of 2048
__device__ float  g_b2  [2 * Dd_];
__device__ __half g_wTh [(size_t)16 * 1024 * 1024];  // transposed fp16 weights
__device__ __half g_xh  [(size_t)NT_ * Dd_];
__device__ __half g_sah [(size_t)NT_ * Dd_];
__device__ __half g_ffnh[(size_t)NT_ * FF_];
__device__ __half g_memh[(size_t)Bb_ * MEM_ * Dd_];

// offsets into g_wTh (half elements)
#define WT_QKV 0u
#define WT_O   (3u * 1024u * 1024u)
#define WT_QC  (4u * 1024u * 1024u)
#define WT_KC  (5u * 1024u * 1024u)   // [2048][1024] together with VC
#define WT_VC  (6u * 1024u * 1024u)
#define WT_CO  (7u * 1024u * 1024u)
#define WT_W1  (8u * 1024u * 1024u)
#define WT_W2  (12u * 1024u * 1024u)

// -------------------- helpers --------------------
__device__ __forceinline__ uint32_t smem_u32(const void* p) {
    uint32_t a;
    asm("{ .reg .u64 t; cvta.to.shared.u64 t, %1; cvt.u32.u64 %0, t; }" : "=r"(a) : "l"(p));
    return a;
}
__device__ __forceinline__ void cpa16(uint32_t dst, const void* src) {
    asm volatile("cp.async.cg.shared.global [%0], [%1], 16;" :: "r"(dst), "l"(src));
}
__device__ __forceinline__ void ldsm_x4(uint32_t& r0, uint32_t& r1, uint32_t& r2,
                                        uint32_t& r3, uint32_t addr) {
    asm volatile("ldmatrix.sync.aligned.m8n8.x4.shared.b16 {%0,%1,%2,%3}, [%4];"
                 : "=r"(r0), "=r"(r1), "=r"(r2), "=r"(r3) : "r"(addr));
}
__device__ __forceinline__ void ldsm_x4t(uint32_t& r0, uint32_t& r1, uint32_t& r2,
                                         uint32_t& r3, uint32_t addr) {
    asm volatile("ldmatrix.sync.aligned.m8n8.x4.trans.shared.b16 {%0,%1,%2,%3}, [%4];"
                 : "=r"(r0), "=r"(r1), "=r"(r2), "=r"(r3) : "r"(addr));
}
__device__ __forceinline__ void sts64u(uint32_t addr, uint32_t x, uint32_t y) {
    asm volatile("st.shared.v2.u32 [%0], {%1,%2};" :: "r"(addr), "r"(x), "r"(y) : "memory");
}
#define CPA_COMMIT() asm volatile("cp.async.commit_group;" ::: "memory")
#define CPA_WAIT1()  asm volatile("cp.async.wait_group 1;"  ::: "memory")
#define CPA_WAIT0()  asm volatile("cp.async.wait_group 0;"  ::: "memory")
#define SWZ(b) ((b) ^ (((b) >> 3) & 0x70))

__device__ __forceinline__ void mma_f16(float* d, uint32_t a0, uint32_t a1, uint32_t a2,
                                        uint32_t a3, uint32_t b0, uint32_t b1) {
    asm volatile(
        "mma.sync.aligned.m16n8k16.row.col.f32.f16.f16.f32 "
        "{%0,%1,%2,%3}, {%4,%5,%6,%7}, {%8,%9}, {%0,%1,%2,%3};"
        : "+f"(d[0]), "+f"(d[1]), "+f"(d[2]), "+f"(d[3])
        : "r"(a0), "r"(a1), "r"(a2), "r"(a3), "r"(b0), "r"(b1));
}
__device__ __forceinline__ uint32_t packh2(float a, float b) {
    __half2 h = __floats2half2_rn(a, b);
    return *reinterpret_cast<uint32_t*>(&h);
}

// -------------------- weight transpose + fp16 convert --------------------
__global__ void transpose_h(const float* __restrict__ W, __half* __restrict__ WT,
                            int K, int N)
{
    __shared__ float t[32][33];
    const int n0 = blockIdx.x * 32, k0 = blockIdx.y * 32;
    const int tx = threadIdx.x, ty = threadIdx.y;   // 32 x 8
    #pragma unroll
    for (int r = 0; r < 32; r += 8)
        t[ty + r][tx] = W[(size_t)(k0 + ty + r) * N + n0 + tx];
    __syncthreads();
    #pragma unroll
    for (int r = 0; r < 32; r += 8)
        WT[(size_t)(n0 + ty + r) * K + k0 + tx] = __float2half_rn(t[tx][ty + r]);
}

// -------------------- misc small kernels --------------------
__global__ void conv_h(const float* __restrict__ x, __half* __restrict__ y, int n)
{
    int i = blockIdx.x * blockDim.x + threadIdx.x;
    if (i < n) y[i] = __float2half_rn(x[i]);
}
__global__ void concat2(const float* __restrict__ a, const float* __restrict__ b,
                        float* __restrict__ o)
{
    int i = blockIdx.x * blockDim.x + threadIdx.x;
    if (i < Dd_) o[i] = a[i];
    else if (i < 2 * Dd_) o[i] = b[i - Dd_];
}

// -------------------- LayerNorm (fp32 in, fp16 out) --------------------
__global__ void layernorm_kernel(const float* __restrict__ x,
                                 const float* __restrict__ g,
                                 const float* __restrict__ be,
                                 __half* __restrict__ y)
{
    int row = blockIdx.x;
    int tid = threadIdx.x;
    const float* xr = x + (size_t)row * Dd_;
    float4 v = *(const float4*)(xr + tid * 4);

    __shared__ float red[8];
    __shared__ float s_mu, s_inv;

    float s = v.x + v.y + v.z + v.w;
    #pragma unroll
    for (int o = 16; o > 0; o >>= 1) s += __shfl_xor_sync(0xffffffffu, s, o);
    if ((tid & 31) == 0) red[tid >> 5] = s;
    __syncthreads();
    if (tid == 0) {
        float t = 0.f;
        #pragma unroll
        for (int i = 0; i < 8; i++) t += red[i];
        s_mu = t * (1.0f / Dd_);
    }
    __syncthreads();
    float mu = s_mu;
    float dx = v.x - mu, dy = v.y - mu, dz = v.z - mu, dw = v.w - mu;
    float q = dx*dx + dy*dy + dz*dz + dw*dw;
    #pragma unroll
    for (int o = 16; o > 0; o >>= 1) q += __shfl_xor_sync(0xffffffffu, q, o);
    if ((tid & 31) == 0) red[tid >> 5] = q;
    __syncthreads();
    if (tid == 0) {
        float t = 0.f;
        #pragma unroll
        for (int i = 0; i < 8; i++) t += red[i];
        s_inv = rsqrtf(t * (1.0f / Dd_) + 1e-5f);
    }
    __syncthreads();
    float inv = s_inv;
    int c = tid * 4;
    __half* yr = y + (size_t)row * Dd_;
    float o0 = dx * inv * g[c + 0] + be[c + 0];
    float o1 = dy * inv * g[c + 1] + be[c + 1];
    float o2 = dz * inv * g[c + 2] + be[c + 2];
    float o3 = dw * inv * g[c + 3] + be[c + 3];
    ((__half2*)(yr + c))[0] = __floats2half2_rn(o0, o1);
    ((__half2*)(yr + c))[1] = __floats2half2_rn(o2, o3);
}

// -------------------- fp16 mma GEMM, cp.async 3-stage, ldmatrix fragments ------------
#define GM_STAGE 32768
#define GM_SMEM  (3 * GM_STAGE + 1024)
__global__ __launch_bounds__(256)
void gemm_mma(const __half* __restrict__ A, const __half* __restrict__ WT,
              const float* __restrict__ bias, const float* __restrict__ res,
              float* __restrict__ C, __half* __restrict__ Ch,
              int Nc, int Kd, int dogelu)
{
    extern __shared__ float dyns[];
    const uint32_t sbase = (smem_u32(dyns) + 1023u) & ~1023u;

    const int tid  = threadIdx.x;
    const int lane = tid & 31, wid = tid >> 5;
    const int gid  = lane >> 2, qd = lane & 3;
    const int wm   = (wid >> 1) * 32;
    const int wn   = (wid & 1) * 64;
    const int n0   = blockIdx.x * 128;
    const int m0   = blockIdx.y * 128;

    const int arow  = wm + (lane & 7) + ((lane >> 3) & 1) * 8;
    const uint32_t acolb = (uint32_t)((lane >> 4) * 16);
    const int bn_base = wn + ((lane >> 4) & 1) * 8 + (lane & 7);
    const uint32_t bcolb = (uint32_t)(((lane >> 3) & 1) * 16);

    float d[2][8][4];
    #pragma unroll
    for (int mt = 0; mt < 2; mt++)
        #pragma unroll
        for (int nt = 0; nt < 8; nt++)
            #pragma unroll
            for (int e = 0; e < 4; e++) d[mt][nt][e] = 0.f;

    const int nsteps = Kd >> 6;   // BK = 64
    const __half* Abase = A  + (size_t)m0 * Kd;
    const __half* Bbase = WT + (size_t)n0 * Kd;

    auto cpa_tile = [&](int kstep, int s) {
        const int k0 = kstep * 64;
        const uint32_t aA = sbase + s * GM_STAGE;
        const uint32_t bA = aA + 16384u;
        #pragma unroll
        for (int p = 0; p < 4; p++) {
            int task = p * 256 + tid;
            int r = task >> 3, c = task & 7;
            cpa16(aA + SWZ((uint32_t)(r * 128 + c * 16)), Abase + (size_t)r * Kd + k0 + c * 8);
        }
        #pragma unroll
        for (int p = 0; p < 4; p++) {
            int task = p * 256 + tid;
            int r = task >> 3, c = task & 7;
            cpa16(bA + SWZ((uint32_t)(r * 128 + c * 16)), Bbase + (size_t)r * Kd + k0 + c * 8);
        }
        CPA_COMMIT();
    };

    cpa_tile(0, 0);
    cpa_tile(1, 1);

    for (int i = 0; i < nsteps; i++) {
        const int s = i % 3;
        if (i == nsteps - 1) { CPA_WAIT0(); } else { CPA_WAIT1(); }
        __syncthreads();
        if (i + 2 < nsteps) cpa_tile(i + 2, (i + 2) % 3);

        const uint32_t aA = sbase + s * GM_STAGE;
        const uint32_t bA = aA + 16384u;
        #pragma unroll
        for (int g = 0; g < 4; g++) {
            const uint32_t gb = (uint32_t)(g * 32);
            uint32_t a0[4], a1[4];
            ldsm_x4(a0[0], a0[1], a0[2], a0[3],
                    aA + SWZ((uint32_t)(arow * 128) + gb + acolb));
            ldsm_x4(a1[0], a1[1], a1[2], a1[3],
                    aA + SWZ((uint32_t)((arow + 16) * 128) + gb + acolb));
            uint32_t bf[8][2];
            #pragma unroll
            for (int jp = 0; jp < 4; jp++) {
                int n = bn_base + jp * 16;
                ldsm_x4(bf[jp * 2][0], bf[jp * 2][1], bf[jp * 2 + 1][0], bf[jp * 2 + 1][1],
                        bA + SWZ((uint32_t)(n * 128) + gb + bcolb));
            }
            #pragma unroll
            for (int nt = 0; nt < 8; nt++) {
                mma_f16(d[0][nt], a0[0], a0[1], a0[2], a0[3], bf[nt][0], bf[nt][1]);
                mma_f16(d[1][nt], a1[0], a1[1], a1[2], a1[3], bf[nt][0], bf[nt][1]);
            }
        }
    }

    #pragma unroll
    for (int mt = 0; mt < 2; mt++) {
        #pragma unroll
        for (int nt = 0; nt < 8; nt++) {
            const int r0  = m0 + wm + mt * 16 + gid;
            const int col = n0 + wn + nt * 8 + qd * 2;
            float2 b2 = *(const float2*)(bias + col);
            #pragma unroll
            for (int half_ = 0; half_ < 2; half_++) {
                const int row = r0 + half_ * 8;
                float ox = d[mt][nt][half_ * 2 + 0] + b2.x;
                float oy = d[mt][nt][half_ * 2 + 1] + b2.y;
                if (res) {
                    float2 r2 = *(const float2*)(res + (size_t)row * Nc + col);
                    ox += r2.x; oy += r2.y;
                }
                if (dogelu) {
                    ox = 0.5f * ox * (1.0f + erff(ox * 0.7071067811865475f));
                    oy = 0.5f * oy * (1.0f + erff(oy * 0.7071067811865475f));
                }
                if (Ch) {
                    *(__half2*)(Ch + (size_t)row * Nc + col) = __floats2half2_rn(ox, oy);
                } else {
                    float2 o2; o2.x = ox; o2.y = oy;
                    *(float2*)(C + (size_t)row * Nc + col) = o2;
                }
            }
        }
    }
}

// -------------------- fp16 mma flash attention, RoPE fused, ldmatrix -----------------
// 1 block = 64 queries x (b,h). 128 thr / 4 warps; warp owns 16 query rows.
// Tiles: Ks/Vs 64 rows x 64 fp16 (128B rows, SWZ). RoPE applied during staging.
// Softmax fp32 in C-frags; P packed to fp16 A-frags in regs; V via ldmatrix.trans.
#define FAH_SMEM (2 * 64 * 64 * 2)   // 16,384 B
__global__ __launch_bounds__(128)
void flash_attn_h(const float* __restrict__ qkv,
                  const float* __restrict__ rc, const float* __restrict__ rs,
                  __half* __restrict__ out)
{
    extern __shared__ __half smh[];
    const uint32_t kA = smem_u32(smh);           // K tile (also stages Q)
    const uint32_t vA = kA + 8192u;              // V tile

    const int qb = (int)gridDim.x - 1 - (int)blockIdx.x;  // heavy blocks first
    const int q0 = qb * 64;
    const int bh = blockIdx.y;
    const int b = bh >> 4, h = bh & 15;
    const int tid = threadIdx.x, lane = tid & 31, wid = tid >> 5;
    const int gid = lane >> 2, qd = lane & 3;
    const int wr = wid * 16;
    const size_t rs3 = 3 * Dd_;

    const float* qbase = qkv + (size_t)(b * Ss_ + q0) * rs3 + h * HD_;
    const float* kbase = qkv + (size_t)(b * Ss_) * rs3 + Dd_ + h * HD_;
    const float* vbase = qkv + (size_t)(b * Ss_) * rs3 + 2 * Dd_ + h * HD_;

    // staging coords: each pass covers 8 rows x 64 cols (16 col-groups of 4)
    const int srow = tid >> 4;            // 0..7
    const int sd4  = (tid & 15) * 4;      // 0..60

    // ---- stage Q with RoPE + scale (full 64 rows: p = 0..7) ----
    #pragma unroll
    for (int p = 0; p < 8; p++) {
        int r = p * 8 + srow;
        float4 v = *(const float4*)(qbase + (size_t)r * rs3 + sd4);
        int pos = q0 + r;
        float2 cs0 = *(const float2*)(rc + pos * 32 + (sd4 >> 1));
        float2 sn0 = *(const float2*)(rs + pos * 32 + (sd4 >> 1));
        float re0 = v.x * cs0.x - v.y * sn0.x, im0 = v.x * sn0.x + v.y * cs0.x;
        float re1 = v.z * cs0.y - v.w * sn0.y, im1 = v.z * sn0.y + v.w * cs0.y;
        sts64u(kA + SWZ((uint32_t)(r * 128 + sd4 * 2)),
               packh2(re0 * 0.125f, im0 * 0.125f), packh2(re1 * 0.125f, im1 * 0.125f));
    }
    __syncthreads();

    uint32_t qf[4][4];
    {
        const int arow = wr + (lane & 7) + ((lane >> 3) & 1) * 8;
        const uint32_t acolb = (uint32_t)((lane >> 4) * 16);
        #pragma unroll
        for (int g = 0; g < 4; g++)
            ldsm_x4(qf[g][0], qf[g][1], qf[g][2], qf[g][3],
                    kA + SWZ((uint32_t)(arow * 128) + (uint32_t)(g * 32) + acolb));
    }
    __syncthreads();

    float of[8][4];
    #pragma unroll
    for (int nt = 0; nt < 8; nt++)
        #pragma unroll
        for (int e = 0; e < 4; e++) of[nt][e] = 0.f;
    float m1 = -1e30f, m2 = -1e30f, l1 = 0.f, l2 = 0.f;

    const int aq1 = q0 + wr + gid;
    const int bn_base = ((lane >> 4) & 1) * 8 + (lane & 7);
    const uint32_t bcolb = (uint32_t)(((lane >> 3) & 1) * 16);
    const int vrow_l = (lane & 7) + ((lane >> 3) & 1) * 8;
    const uint32_t vcol_l = (uint32_t)(((lane >> 4) & 1) * 16);

    for (int t = 0; t <= qb; t++) {
        const int k0 = t * 64;
        // stage K (RoPE) and V (plain) as fp16 — full 64 rows
        #pragma unroll
        for (int p = 0; p < 8; p++) {
            int r = p * 8 + srow;
            float4 kv = *(const float4*)(kbase + (size_t)(k0 + r) * rs3 + sd4);
            int pos = k0 + r;
            float2 cs0 = *(const float2*)(rc + pos * 32 + (sd4 >> 1));
            float2 sn0 = *(const float2*)(rs + pos * 32 + (sd4 >> 1));
            float re0 = kv.x * cs0.x - kv.y * sn0.x, im0 = kv.x * sn0.x + kv.y * cs0.x;
            float re1 = kv.z * cs0.y - kv.w * sn0.y, im1 = kv.z * sn0.y + kv.w * cs0.y;
            sts64u(kA + SWZ((uint32_t)(r * 128 + sd4 * 2)), packh2(re0, im0), packh2(re1, im1));
            float4 vv = *(const float4*)(vbase + (size_t)(k0 + r) * rs3 + sd4);
            sts64u(vA + SWZ((uint32_t)(r * 128 + sd4 * 2)), packh2(vv.x, vv.y), packh2(vv.z, vv.w));
        }
        __syncthreads();

        // S = Q @ K^T
        float sf[8][4];
        #pragma unroll
        for (int nt = 0; nt < 8; nt++)
            #pragma unroll
            for (int e = 0; e < 4; e++) sf[nt][e] = 0.f;

        #pragma unroll
        for (int g = 0; g < 4; g++) {
            const uint32_t gb = (uint32_t)(g * 32);
            uint32_t kb[8][2];
            #pragma unroll
            for (int jp = 0; jp < 4; jp++) {
                int n = bn_base + jp * 16;
                ldsm_x4(kb[jp * 2][0], kb[jp * 2][1], kb[jp * 2 + 1][0], kb[jp * 2 + 1][1],
                        kA + SWZ((uint32_t)(n * 128) + gb + bcolb));
            }
            #pragma unroll
            for (int nt = 0; nt < 8; nt++)
                mma_f16(sf[nt], qf[g][0], qf[g][1], qf[g][2], qf[g][3], kb[nt][0], kb[nt][1]);
        }

        // causal mask (diagonal tile only)
        if (t == qb) {
            #pragma unroll
            for (int nt = 0; nt < 8; nt++) {
                int c = k0 + nt * 8 + qd * 2;
                if (c     > aq1)     sf[nt][0] = -1e30f;
                if (c + 1 > aq1)     sf[nt][1] = -1e30f;
                if (c     > aq1 + 8) sf[nt][2] = -1e30f;
                if (c + 1 > aq1 + 8) sf[nt][3] = -1e30f;
            }
        }

        // online softmax over quad lanes (fp32)
        float mx1 = -1e30f, mx2 = -1e30f;
        #pragma unroll
        for (int nt = 0; nt < 8; nt++) {
            mx1 = fmaxf(mx1, fmaxf(sf[nt][0], sf[nt][1]));
            mx2 = fmaxf(mx2, fmaxf(sf[nt][2], sf[nt][3]));
        }
        mx1 = fmaxf(mx1, __shfl_xor_sync(0xffffffffu, mx1, 1));
        mx1 = fmaxf(mx1, __shfl_xor_sync(0xffffffffu, mx1, 2));
        mx2 = fmaxf(mx2, __shfl_xor_sync(0xffffffffu, mx2, 1));
        mx2 = fmaxf(mx2, __shfl_xor_sync(0xffffffffu, mx2, 2));
        float nm1 = fmaxf(m1, mx1), nm2 = fmaxf(m2, mx2);
        float f1 = __expf(m1 - nm1), f2v = __expf(m2 - nm2);
        m1 = nm1; m2 = nm2;
        float s1 = 0.f, s2 = 0.f;
        #pragma unroll
        for (int nt = 0; nt < 8; nt++) {
            sf[nt][0] = __expf(sf[nt][0] - nm1); s1 += sf[nt][0];
            sf[nt][1] = __expf(sf[nt][1] - nm1); s1 += sf[nt][1];
            sf[nt][2] = __expf(sf[nt][2] - nm2); s2 += sf[nt][2];
            sf[nt][3] = __expf(sf[nt][3] - nm2); s2 += sf[nt][3];
        }
        s1 += __shfl_xor_sync(0xffffffffu, s1, 1);
        s1 += __shfl_xor_sync(0xffffffffu, s1, 2);
        s2 += __shfl_xor_sync(0xffffffffu, s2, 1);
        s2 += __shfl_xor_sync(0xffffffffu, s2, 2);
        l1 = l1 * f1 + s1;
        l2 = l2 * f2v + s2;
        #pragma unroll
        for (int nt = 0; nt < 8; nt++) {
            of[nt][0] *= f1;  of[nt][1] *= f1;
            of[nt][2] *= f2v; of[nt][3] *= f2v;
        }

        // O += P @ V : P packed from S C-frags; V via ldmatrix.trans
        #pragma unroll
        for (int g2 = 0; g2 < 4; g2++) {
            uint32_t pa0 = packh2(sf[2 * g2][0], sf[2 * g2][1]);
            uint32_t pa1 = packh2(sf[2 * g2][2], sf[2 * g2][3]);
            uint32_t pa2 = packh2(sf[2 * g2 + 1][0], sf[2 * g2 + 1][1]);
            uint32_t pa3 = packh2(sf[2 * g2 + 1][2], sf[2 * g2 + 1][3]);
            const int vrow = g2 * 16 + vrow_l;
            #pragma unroll
            for (int dp = 0; dp < 4; dp++) {
                uint32_t r0, r1, r2, r3;
                ldsm_x4t(r0, r1, r2, r3,
                         vA + SWZ((uint32_t)(vrow * 128) + (uint32_t)(dp * 32) + vcol_l));
                mma_f16(of[2 * dp],     pa0, pa1, pa2, pa3, r0, r1);
                mma_f16(of[2 * dp + 1], pa0, pa1, pa2, pa3, r2, r3);
            }
        }
        __syncthreads();
    }

    // epilogue: normalize, store fp16 (b,s,D layout)
    float inv1 = 1.0f / l1, inv2 = 1.0f / l2;
    __half* o1base = out + (size_t)(b * Ss_ + aq1) * Dd_ + h * HD_;
    __half* o2base = out + (size_t)(b * Ss_ + aq1 + 8) * Dd_ + h * HD_;
    #pragma unroll
    for (int nt = 0; nt < 8; nt++) {
        *(__half2*)(o1base + nt * 8 + qd * 2) = __floats2half2_rn(of[nt][0] * inv1, of[nt][1] * inv1);
        *(__half2*)(o2base + nt * 8 + qd * 2) = __floats2half2_rn(of[nt][2] * inv2, of[nt][3] * inv2);
    }
}

// -------------------- Cross-attention (64 keys, kvc stride 2048, fp16 out) ------------
__global__ __launch_bounds__(64)
void cross_attn_kernel(const float* __restrict__ qc, const float* __restrict__ kvc,
                       __half* __restrict__ out)
{
    int qidx = blockIdx.x;
    int bh   = blockIdx.y;
    int b = bh / Hh_, h = bh % Hh_;
    int tid = threadIdx.x;

    __shared__ float sq[HD_];
    __shared__ float p[MEM_];
    __shared__ float red[2];

    const float* qrow = qc + ((size_t)(b * Ss_ + qidx)) * Dd_ + h * HD_;
    sq[tid] = qrow[tid];
    __syncthreads();

    const float* krow = kvc + ((size_t)(b * MEM_ + tid)) * (2 * Dd_) + h * HD_;
    float s = 0.f;
    #pragma unroll
    for (int d = 0; d < HD_; d += 4) {
        float4 k4 = *(const float4*)(krow + d);
        s = fmaf(sq[d + 0], k4.x, s);
        s = fmaf(sq[d + 1], k4.y, s);
        s = fmaf(sq[d + 2], k4.z, s);
        s = fmaf(sq[d + 3], k4.w, s);
    }
    s *= 0.125f;

    float m = s;
    #pragma unroll
    for (int o = 16; o > 0; o >>= 1) m = fmaxf(m, __shfl_xor_sync(0xffffffffu, m, o));
    if ((tid & 31) == 0) red[tid >> 5] = m;
    __syncthreads();
    float gm = fmaxf(red[0], red[1]);
    float pv = expf(s - gm);
    p[tid] = pv;
    float su = pv;
    #pragma unroll
    for (int o = 16; o > 0; o >>= 1) su += __shfl_xor_sync(0xffffffffu, su, o);
    __syncthreads();
    if ((tid & 31) == 0) red[tid >> 5] = su;
    __syncthreads();
    float gl = red[0] + red[1];

    const float* vbase = kvc + ((size_t)(b * MEM_)) * (2 * Dd_) + Dd_ + h * HD_ + tid;
    float a = 0.f;
    #pragma unroll 4
    for (int j = 0; j < MEM_; j++)
        a = fmaf(p[j], vbase[(size_t)j * (2 * Dd_)], a);

    out[((size_t)(b * Ss_ + qidx)) * Dd_ + h * HD_ + tid] = __float2half_rn(a / gl);
}

// -------------------- launch --------------------
extern "C" void kernel_launch(void* const* d_in, const int* in_sizes, int n_in,
                              void* d_out, int out_size)
{
    const float* tgt      = (const float*)d_in[0];
    const float* memory   = (const float*)d_in[1];
    const float* rope_cos = (const float*)d_in[2];
    const float* rope_sin = (const float*)d_in[3];
    const float* W_qkv    = (const float*)d_in[4];
    const float* b_qkv    = (const float*)d_in[5];
    const float* W_o      = (const float*)d_in[6];
    const float* b_o      = (const float*)d_in[7];
    const float* Wq_c     = (const float*)d_in[8];
    const float* bq_c     = (const float*)d_in[9];
    const float* Wk_c     = (const float*)d_in[10];
    const float* bk_c     = (const float*)d_in[11];
    const float* Wv_c     = (const float*)d_in[12];
    const float* bv_c     = (const float*)d_in[13];
    const float* W_co     = (const float*)d_in[14];
    const float* b_co     = (const float*)d_in[15];
    const float* W1       = (const float*)d_in[16];
    const float* b1       = (const float*)d_in[17];
    const float* W2       = (const float*)d_in[18];
    const float* b2       = (const float*)d_in[19];
    const float* g1       = (const float*)d_in[20];
    const float* be1      = (const float*)d_in[21];
    const float* g2       = (const float*)d_in[22];
    const float* be2      = (const float*)d_in[23];
    const float* g3       = (const float*)d_in[24];
    const float* be3      = (const float*)d_in[25];
    float* out = (float*)d_out;

    float *qkv, *tgtb, *kvc, *b2c;
    __half *wTh, *xh, *sah, *ffnh, *memh;
    cudaGetSymbolAddress((void**)&qkv,  g_qkv);
    cudaGetSymbolAddress((void**)&tgtb, g_tgt);
    cudaGetSymbolAddress((void**)&kvc,  g_kvc);
    cudaGetSymbolAddress((void**)&b2c,  g_b2);
    cudaGetSymbolAddress((void**)&wTh,  g_wTh);
    cudaGetSymbolAddress((void**)&xh,   g_xh);
    cudaGetSymbolAddress((void**)&sah,  g_sah);
    cudaGetSymbolAddress((void**)&ffnh, g_ffnh);
    cudaGetSymbolAddress((void**)&memh, g_memh);

    cudaFuncSetAttribute(flash_attn_h,
                         cudaFuncAttributeMaxDynamicSharedMemorySize, FAH_SMEM);
    cudaFuncSetAttribute(gemm_mma,
                         cudaFuncAttributeMaxDynamicSharedMemorySize, GM_SMEM);

    // 0) pre-transpose + fp16-convert all weights; fp16 copy of memory; concat bias
    {
        dim3 thr(32, 8);
        transpose_h<<<dim3(3 * Dd_ / 32, Dd_ / 32), thr>>>(W_qkv, wTh + WT_QKV, Dd_, 3 * Dd_);
        transpose_h<<<dim3(Dd_ / 32, Dd_ / 32), thr>>>(W_o,  wTh + WT_O,  Dd_, Dd_);
        transpose_h<<<dim3(Dd_ / 32, Dd_ / 32), thr>>>(Wq_c, wTh + WT_QC, Dd_, Dd_);
        transpose_h<<<dim3(Dd_ / 32, Dd_ / 32), thr>>>(Wk_c, wTh + WT_KC, Dd_, Dd_);
        transpose_h<<<dim3(Dd_ / 32, Dd_ / 32), thr>>>(Wv_c, wTh + WT_VC, Dd_, Dd_);
        transpose_h<<<dim3(Dd_ / 32, Dd_ / 32), thr>>>(W_co, wTh + WT_CO, Dd_, Dd_);
        transpose_h<<<dim3(FF_ / 32, Dd_ / 32), thr>>>(W1, wTh + WT_W1, Dd_, FF_);
        transpose_h<<<dim3(Dd_ / 32, FF_ / 32), thr>>>(W2, wTh + WT_W2, FF_, Dd_);
        int nmem = Bb_ * MEM_ * Dd_;
        conv_h<<<(nmem + 255) / 256, 256>>>(memory, memh, nmem);
        concat2<<<(2 * Dd_ + 255) / 256, 256>>>(bk_c, bv_c, b2c);
    }

    // 1) xh = LN1(tgt)
    layernorm_kernel<<<NT_, 256>>>(tgt, g1, be1, xh);
    // 2) qkv = xh @ W_qkv + b  (un-roped; RoPE fused into attention)
    gemm_mma<<<dim3(3 * Dd_ / 128, NT_ / 128), 256, GM_SMEM>>>(xh, wTh + WT_QKV, b_qkv, nullptr, qkv, nullptr, 3 * Dd_, Dd_, 0);
    // 3) causal self-attention (fp16 mma, RoPE fused) -> sah
    flash_attn_h<<<dim3(Ss_ / 64, Bb_ * Hh_), 128, FAH_SMEM>>>(qkv, rope_cos, rope_sin, sah);
    // 4) tgtb = tgt + sah @ W_o + b_o
    gemm_mma<<<dim3(Dd_ / 128, NT_ / 128), 256, GM_SMEM>>>(sah, wTh + WT_O, b_o, tgt, tgtb, nullptr, Dd_, Dd_, 0);
    // 5) xh = LN2(tgtb)
    layernorm_kernel<<<NT_, 256>>>(tgtb, g2, be2, xh);
    // 6) qc = xh @ Wq_c -> qkv buffer (fp32)
    gemm_mma<<<dim3(Dd_ / 128, NT_ / 128), 256, GM_SMEM>>>(xh, wTh + WT_QC, bq_c, nullptr, qkv, nullptr, Dd_, Dd_, 0);
    // 7) kvc = memh @ [Wk_c|Wv_c]
    gemm_mma<<<dim3(2 * Dd_ / 128, 1), 256, GM_SMEM>>>(memh, wTh + WT_KC, b2c, nullptr, kvc, nullptr, 2 * Dd_, Dd_, 0);
    // 8) cross-attention -> sah (fp16)
    cross_attn_kernel<<<dim3(Ss_, Bb_ * Hh_), 64>>>(qkv, kvc, sah);
    // 9) tgtb += sah @ W_co + b_co
    gemm_mma<<<dim3(Dd_ / 128, NT_ / 128), 256, GM_SMEM>>>(sah, wTh + WT_CO, b_co, tgtb, tgtb, nullptr, Dd_, Dd_, 0);
    // 10) xh = LN3(tgtb)
    layernorm_kernel<<<NT_, 256>>>(tgtb, g3, be3, xh);
    // 11) ffnh = gelu(xh @ W1 + b1) (fp16 out)
    gemm_mma<<<dim3(FF_ / 128, NT_ / 128), 256, GM_SMEM>>>(xh, wTh + WT_W1, b1, nullptr, nullptr, ffnh, FF_, Dd_, 1);
    // 12) out = tgtb + ffnh @ W2 + b2
    gemm_mma<<<dim3(Dd_ / 128, NT_ / 128), 256, GM_SMEM>>>(ffnh, wTh + WT_W2, b2, tgtb, out, nullptr, Dd_, FF_, 0);
}